// round 2
// baseline (speedup 1.0000x reference)
#include <cuda_runtime.h>
#include <cuda_bf16.h>

#define B_SZ 4096
#define G_NUM 16384
#define D0 4096
#define D1 2048
#define D2 512
#define KEMB 8192

// -------- scratch (static device memory; no allocations) --------
__device__ float g_h1[(size_t)B_SZ * D0];   // 64MB, reused by decoder
__device__ float g_h2[(size_t)B_SZ * D1];   // 32MB, reused by decoder
__device__ float g_z [(size_t)B_SZ * D2];   // 8MB
__device__ float g_q [(size_t)B_SZ * D2];   // 8MB
__device__ float g_ee[KEMB];
__device__ float g_zz[B_SZ];
__device__ unsigned long long g_best[B_SZ];
__device__ float g_rowsum[B_SZ];

// ---------------- XLA/Eigen tanh f32 rational approximation ----------------
// Replicates XLA's EmitTanh (same coefficients as Eigen's generic_fast_tanh):
//   |x| < 0.0004 -> x ; else clamp to +-7.90531110763549805 and evaluate
//   odd rational P(x)/Q(x) with fp32 FMA Horner + IEEE divide.
__device__ __forceinline__ float xla_tanh(float x)
{
    if (fabsf(x) < 0.0004f) return x;
    float xc = fminf(fmaxf(x, -7.90531110763549805f), 7.90531110763549805f);
    float x2 = __fmul_rn(xc, xc);
    float p = fmaf(x2, -2.76076847742355e-16f, 2.00018790482477e-13f);
    p = fmaf(x2, p, -8.60467152213735e-11f);
    p = fmaf(x2, p,  5.12229709037114e-08f);
    p = fmaf(x2, p,  1.48572235717979e-05f);
    p = fmaf(x2, p,  6.37261928875436e-04f);
    p = fmaf(x2, p,  4.89352455891786e-03f);
    p = __fmul_rn(xc, p);
    float q = fmaf(x2, 1.19825839466702e-06f, 1.18534705686654e-04f);
    q = fmaf(x2, q, 2.26843463243900e-03f);
    q = fmaf(x2, q, 4.89352518554385e-03f);
    return __fdiv_rn(p, q);
}

// ----------------------------------------------------------------
// Classic 128x128x8 SGEMM, A[M,K] row-major, W[N,K] row-major (NT),
// C = act(A @ W^T + bias). Accumulation is a single ascending-k pure
// FMA chain per output element (replicating Eigen/XLA:CPU order).
// ----------------------------------------------------------------
template<bool TANH>
__global__ __launch_bounds__(256, 2)
void gemm_bias_act(const float* __restrict__ A, const float* __restrict__ W,
                   const float* __restrict__ bias, float* __restrict__ C,
                   int M, int N, int K)
{
    __shared__ float As[8][128];
    __shared__ float Bs[8][128];
    const int t  = threadIdx.x;
    const int tx = t & 15, ty = t >> 4;
    const int m0 = blockIdx.y * 128, n0 = blockIdx.x * 128;
    const int lr = t >> 1;            // 0..127
    const int lc = (t & 1) * 4;       // 0 or 4
    const float* Aptr = A + (size_t)(m0 + lr) * K + lc;
    const float* Wptr = W + (size_t)(n0 + lr) * K + lc;

    float acc[8][8];
#pragma unroll
    for (int i = 0; i < 8; i++)
#pragma unroll
        for (int j = 0; j < 8; j++) acc[i][j] = 0.f;

    for (int k0 = 0; k0 < K; k0 += 8) {
        float4 av = *(const float4*)(Aptr + k0);
        float4 wv = *(const float4*)(Wptr + k0);
        As[lc + 0][lr] = av.x; As[lc + 1][lr] = av.y;
        As[lc + 2][lr] = av.z; As[lc + 3][lr] = av.w;
        Bs[lc + 0][lr] = wv.x; Bs[lc + 1][lr] = wv.y;
        Bs[lc + 2][lr] = wv.z; Bs[lc + 3][lr] = wv.w;
        __syncthreads();
#pragma unroll
        for (int kk = 0; kk < 8; kk++) {
            float4 a0 = *(const float4*)&As[kk][ty * 8];
            float4 a1 = *(const float4*)&As[kk][ty * 8 + 4];
            float4 b0 = *(const float4*)&Bs[kk][tx * 8];
            float4 b1 = *(const float4*)&Bs[kk][tx * 8 + 4];
            float a[8] = {a0.x, a0.y, a0.z, a0.w, a1.x, a1.y, a1.z, a1.w};
            float b[8] = {b0.x, b0.y, b0.z, b0.w, b1.x, b1.y, b1.z, b1.w};
#pragma unroll
            for (int i = 0; i < 8; i++)
#pragma unroll
                for (int j = 0; j < 8; j++)
                    acc[i][j] = fmaf(a[i], b[j], acc[i][j]);
        }
        __syncthreads();
    }

#pragma unroll
    for (int i = 0; i < 8; i++) {
        const int m = m0 + ty * 8 + i;
#pragma unroll
        for (int j = 0; j < 8; j++) {
            const int n = n0 + tx * 8 + j;
            float v = __fadd_rn(acc[i][j], bias[n]);
            if (TANH) v = xla_tanh(v);
            C[(size_t)m * N + n] = v;
        }
    }
}

// ---------------- codebook row norms (order-insensitive here) ----------------
__global__ void ee_kernel(const float* __restrict__ E)
{
    const int row  = blockIdx.x * 8 + (threadIdx.x >> 5);
    const int lane = threadIdx.x & 31;
    const float* e = E + (size_t)row * D2;
    float s = 0.f;
    for (int j = lane; j < D2; j += 32)
        s = __fadd_rn(s, __fmul_rn(e[j], e[j]));
#pragma unroll
    for (int o = 16; o; o >>= 1) s = __fadd_rn(s, __shfl_xor_sync(0xffffffffu, s, o));
    if (lane == 0) g_ee[row] = s;
}

// zz = sum(z*z, axis=1): sequential scalar mul+add chain per row
// (replicating XLA:CPU's unvectorized f32 reduce order).
__global__ void zz_kernel()
{
    const int m = blockIdx.x * 256 + threadIdx.x;
    if (m >= B_SZ) return;
    const float* z = g_z + (size_t)m * D2;
    float s = 0.f;
    for (int k = 0; k < D2; k++)
        s = __fadd_rn(s, __fmul_rn(z[k], z[k]));
    g_zz[m] = s;
}

__global__ void init_best()
{
    int i = blockIdx.x * 256 + threadIdx.x;
    if (i < B_SZ) g_best[i] = ~0ull;
}

__device__ __forceinline__ unsigned int orderable_f32(float f)
{
    unsigned int u = __float_as_uint(f);
    return (u & 0x80000000u) ? ~u : (u | 0x80000000u);
}

// ------------- VQ scoring, replicating the reference formula -------------
// dist_c = fl( fl(zz_m + ee_c) - fl(2*s_c) ), s_c = ascending-k FMA chain,
// argmin with ties -> lowest index (first occurrence, like jnp.argmin).
__global__ __launch_bounds__(256, 2)
void vq_score(const float* __restrict__ Z, const float* __restrict__ E)
{
    __shared__ float As[8][128];
    __shared__ float Bs[8][128];
    __shared__ unsigned long long skey[128][17];   // padded
    const int t  = threadIdx.x;
    const int tx = t & 15, ty = t >> 4;
    const int m0 = blockIdx.y * 128, n0 = blockIdx.x * 128;
    const int lr = t >> 1;
    const int lc = (t & 1) * 4;
    const float* Aptr = Z + (size_t)(m0 + lr) * D2 + lc;
    const float* Wptr = E + (size_t)(n0 + lr) * D2 + lc;

    float acc[8][8];
#pragma unroll
    for (int i = 0; i < 8; i++)
#pragma unroll
        for (int j = 0; j < 8; j++) acc[i][j] = 0.f;

    for (int k0 = 0; k0 < D2; k0 += 8) {
        float4 av = *(const float4*)(Aptr + k0);
        float4 wv = *(const float4*)(Wptr + k0);
        As[lc + 0][lr] = av.x; As[lc + 1][lr] = av.y;
        As[lc + 2][lr] = av.z; As[lc + 3][lr] = av.w;
        Bs[lc + 0][lr] = wv.x; Bs[lc + 1][lr] = wv.y;
        Bs[lc + 2][lr] = wv.z; Bs[lc + 3][lr] = wv.w;
        __syncthreads();
#pragma unroll
        for (int kk = 0; kk < 8; kk++) {
            float4 a0 = *(const float4*)&As[kk][ty * 8];
            float4 a1 = *(const float4*)&As[kk][ty * 8 + 4];
            float4 b0 = *(const float4*)&Bs[kk][tx * 8];
            float4 b1 = *(const float4*)&Bs[kk][tx * 8 + 4];
            float a[8] = {a0.x, a0.y, a0.z, a0.w, a1.x, a1.y, a1.z, a1.w};
            float b[8] = {b0.x, b0.y, b0.z, b0.w, b1.x, b1.y, b1.z, b1.w};
#pragma unroll
            for (int i = 0; i < 8; i++)
#pragma unroll
                for (int j = 0; j < 8; j++)
                    acc[i][j] = fmaf(a[i], b[j], acc[i][j]);
        }
        __syncthreads();
    }

#pragma unroll
    for (int i = 0; i < 8; i++) {
        const int m = m0 + ty * 8 + i;
        const float zzm = g_zz[m];
        unsigned long long best = ~0ull;
#pragma unroll
        for (int j = 0; j < 8; j++) {
            const int n = n0 + tx * 8 + j;
            const float zze  = __fadd_rn(zzm, g_ee[n]);                 // fl(zz+ee)
            const float twos = __fmul_rn(2.f, acc[i][j]);               // exact
            const float d    = __fadd_rn(zze, -twos);                   // fl(. - 2s)
            unsigned long long key =
                ((unsigned long long)orderable_f32(d) << 32) | (unsigned int)n;
            best = (key < best) ? key : best;
        }
        skey[ty * 8 + i][tx] = best;
    }
    __syncthreads();
    if (t < 128) {
        unsigned long long b = ~0ull;
#pragma unroll
        for (int x = 0; x < 16; x++) {
            unsigned long long k = skey[t][x];
            b = (k < b) ? k : b;
        }
        atomicMin(&g_best[m0 + t], b);
    }
}

// --------- gather q = E[idx], emit q_st, per-row (q-z)^2 partials ---------
__global__ void gather_loss(const float* __restrict__ E, float* __restrict__ out_q)
{
    const int m   = blockIdx.x;
    const int idx = (int)(unsigned int)(g_best[m] & 0xFFFFFFFFull);
    const float* e = E + (size_t)idx * D2;
    const float* z = g_z + (size_t)m * D2;
    float s = 0.f;
    for (int j = threadIdx.x; j < D2; j += 256) {
        float qv = e[j];
        float d  = qv - z[j];
        s = fmaf(d, d, s);
        g_q[(size_t)m * D2 + j] = qv;
        if (out_q) out_q[(size_t)m * D2 + j] = qv;
    }
    __shared__ float red[256];
    red[threadIdx.x] = s;
    __syncthreads();
    for (int o = 128; o; o >>= 1) {
        if (threadIdx.x < o) red[threadIdx.x] += red[threadIdx.x + o];
        __syncthreads();
    }
    if (threadIdx.x == 0) g_rowsum[m] = red[0];
}

__global__ void reduce_loss(float* __restrict__ out_loss)
{
    __shared__ float red[1024];
    float s = 0.f;
    for (int i = threadIdx.x; i < B_SZ; i += 1024) s += g_rowsum[i];
    red[threadIdx.x] = s;
    __syncthreads();
    for (int o = 512; o; o >>= 1) {
        if (threadIdx.x < o) red[threadIdx.x] += red[threadIdx.x + o];
        __syncthreads();
    }
    if (threadIdx.x == 0)
        out_loss[0] = red[0] * (1.25f / (float)((size_t)B_SZ * D2));
}

// ----------------------------------------------------------------
extern "C" void kernel_launch(void* const* d_in, const int* in_sizes, int n_in,
                              void* d_out, int out_size)
{
    const float* X  = (const float*)d_in[0];
    const float* W1 = (const float*)d_in[1];
    const float* b1 = (const float*)d_in[2];
    const float* W2 = (const float*)d_in[3];
    const float* b2 = (const float*)d_in[4];
    const float* W3 = (const float*)d_in[5];
    const float* b3 = (const float*)d_in[6];
    const float* E  = (const float*)d_in[7];
    const float* W4 = (const float*)d_in[8];
    const float* b4 = (const float*)d_in[9];
    const float* W5 = (const float*)d_in[10];
    const float* b5 = (const float*)d_in[11];
    const float* W6 = (const float*)d_in[12];
    const float* b6 = (const float*)d_in[13];

    float *h1, *h2, *z, *q;
    cudaGetSymbolAddress((void**)&h1, g_h1);
    cudaGetSymbolAddress((void**)&h2, g_h2);
    cudaGetSymbolAddress((void**)&z,  g_z);
    cudaGetSymbolAddress((void**)&q,  g_q);

    float* out = (float*)d_out;
    const long long full = 1LL + (long long)B_SZ * G_NUM + (long long)B_SZ * D2;
    float* out_loss = nullptr;
    float* out_x    = out;
    float* out_q    = nullptr;
    if ((long long)out_size == full) {
        out_loss = out;
        out_x    = out + 1;
        out_q    = out + 1 + (long long)B_SZ * G_NUM;
    }

    const dim3 blk(256);

    // codebook norms (independent of encoder)
    ee_kernel<<<KEMB / 8, 256>>>(E);

    // encoder
    gemm_bias_act<true><<<dim3(D0 / 128, B_SZ / 128), blk>>>(X,  W1, b1, h1, B_SZ, D0, G_NUM);
    gemm_bias_act<true><<<dim3(D1 / 128, B_SZ / 128), blk>>>(h1, W2, b2, h2, B_SZ, D1, D0);
    gemm_bias_act<true><<<dim3(D2 / 128, B_SZ / 128), blk>>>(h2, W3, b3, z,  B_SZ, D2, D1);

    // VQ
    zz_kernel<<<B_SZ / 256, 256>>>();
    init_best<<<B_SZ / 256, 256>>>();
    vq_score<<<dim3(KEMB / 128, B_SZ / 128), blk>>>(z, E);
    gather_loss<<<B_SZ, 256>>>(E, out_q);
    if (out_loss) reduce_loss<<<1, 1024>>>(out_loss);

    // decoder (q_st == q in forward values)
    gemm_bias_act<true ><<<dim3(D1 / 128,   B_SZ / 128), blk>>>(q,  W4, b4, h2,   B_SZ, D1,   D2);
    gemm_bias_act<true ><<<dim3(D0 / 128,   B_SZ / 128), blk>>>(h2, W5, b5, h1,   B_SZ, D0,   D1);
    gemm_bias_act<false><<<dim3(G_NUM / 128, B_SZ / 128), blk>>>(h1, W6, b6, out_x, B_SZ, G_NUM, D0);
}

// round 4
// speedup vs baseline: 1.3761x; 1.3761x over previous
#include <cuda_runtime.h>
#include <cuda_bf16.h>

#define B_SZ 4096
#define G_NUM 16384
#define D0 4096
#define D1 2048
#define D2 512
#define KEMB 8192

// -------- scratch (static device memory; no allocations) --------
__device__ float g_h1[(size_t)B_SZ * D0];   // 64MB, reused by decoder
__device__ float g_h2[(size_t)B_SZ * D1];   // 32MB, reused by decoder
__device__ float g_z [(size_t)B_SZ * D2];   // 8MB
__device__ float g_q [(size_t)B_SZ * D2];   // 8MB
__device__ float g_ee[KEMB];
__device__ float g_zz[B_SZ];
__device__ unsigned long long g_best[B_SZ];
__device__ float g_rowsum[B_SZ];

// ---------------- XLA/Eigen tanh f32 rational approximation ----------------
__device__ __forceinline__ float xla_tanh(float x)
{
    if (fabsf(x) < 0.0004f) return x;
    float xc = fminf(fmaxf(x, -7.90531110763549805f), 7.90531110763549805f);
    float x2 = __fmul_rn(xc, xc);
    float p = fmaf(x2, -2.76076847742355e-16f, 2.00018790482477e-13f);
    p = fmaf(x2, p, -8.60467152213735e-11f);
    p = fmaf(x2, p,  5.12229709037114e-08f);
    p = fmaf(x2, p,  1.48572235717979e-05f);
    p = fmaf(x2, p,  6.37261928875436e-04f);
    p = fmaf(x2, p,  4.89352455891786e-03f);
    p = __fmul_rn(xc, p);
    float q = fmaf(x2, 1.19825839466702e-06f, 1.18534705686654e-04f);
    q = fmaf(x2, q, 2.26843463243900e-03f);
    q = fmaf(x2, q, 4.89352518554385e-03f);
    return __fdiv_rn(p, q);
}

// ---------------- shared-tile helpers (Kt = 16) ----------------
// Thread t: lr = t>>1 (row 0..127), lc = (t&1)*4 (k offset 0/4).
// Each thread stores 2 float4 of A and 2 of B per tile.
__device__ __forceinline__ void sts_tile(float (&As)[16][128], float (&Bs)[16][128],
                                         int lr, int lc,
                                         float4 a0, float4 a1, float4 w0, float4 w1)
{
    As[lc + 0][lr] = a0.x; As[lc + 1][lr] = a0.y;
    As[lc + 2][lr] = a0.z; As[lc + 3][lr] = a0.w;
    As[lc + 8][lr] = a1.x; As[lc + 9][lr] = a1.y;
    As[lc +10][lr] = a1.z; As[lc +11][lr] = a1.w;
    Bs[lc + 0][lr] = w0.x; Bs[lc + 1][lr] = w0.y;
    Bs[lc + 2][lr] = w0.z; Bs[lc + 3][lr] = w0.w;
    Bs[lc + 8][lr] = w1.x; Bs[lc + 9][lr] = w1.y;
    Bs[lc +10][lr] = w1.z; Bs[lc +11][lr] = w1.w;
}

// Per-element accumulation stays a single ascending-k FMA chain (numerics-frozen).
// B reads are stride-16B contiguous: thread's n-columns are
// {tx*4..tx*4+3} and {64+tx*4..64+tx*4+3}  -> conflict-free LDS.128.
__device__ __forceinline__ void tile_fma16(const float (&As)[16][128],
                                           const float (&Bs)[16][128],
                                           float (&acc)[8][8], int tx, int ty)
{
#pragma unroll
    for (int kk = 0; kk < 16; kk++) {
        float4 a0 = *(const float4*)&As[kk][ty * 8];
        float4 a1 = *(const float4*)&As[kk][ty * 8 + 4];
        float4 b0 = *(const float4*)&Bs[kk][tx * 4];
        float4 b1 = *(const float4*)&Bs[kk][64 + tx * 4];
        float a[8] = {a0.x, a0.y, a0.z, a0.w, a1.x, a1.y, a1.z, a1.w};
        float b[8] = {b0.x, b0.y, b0.z, b0.w, b1.x, b1.y, b1.z, b1.w};
#pragma unroll
        for (int i = 0; i < 8; i++)
#pragma unroll
            for (int j = 0; j < 8; j++)
                acc[i][j] = fmaf(a[i], b[j], acc[i][j]);
    }
}

__device__ __forceinline__ int col_of(int tx, int j)
{
    return (j < 4) ? (tx * 4 + j) : (64 + tx * 4 + (j - 4));
}

// ----------------------------------------------------------------
// 128x128x16 SGEMM, double-buffered smem + register prefetch.
// A[M,K] row-major, W[N,K] row-major, C = act(A @ W^T + bias).
// ----------------------------------------------------------------
template<bool TANH>
__global__ __launch_bounds__(256, 2)
void gemm_bias_act(const float* __restrict__ A, const float* __restrict__ W,
                   const float* __restrict__ bias, float* __restrict__ C,
                   int M, int N, int K)
{
    __shared__ float As[2][16][128];
    __shared__ float Bs[2][16][128];
    const int t  = threadIdx.x;
    const int tx = t & 15, ty = t >> 4;
    const int m0 = blockIdx.y * 128, n0 = blockIdx.x * 128;
    const int lr = t >> 1;
    const int lc = (t & 1) * 4;
    const float* Aptr = A + (size_t)(m0 + lr) * K + lc;
    const float* Wptr = W + (size_t)(n0 + lr) * K + lc;

    float acc[8][8];
#pragma unroll
    for (int i = 0; i < 8; i++)
#pragma unroll
        for (int j = 0; j < 8; j++) acc[i][j] = 0.f;

    // prologue: tile 0
    {
        float4 a0 = *(const float4*)(Aptr);
        float4 a1 = *(const float4*)(Aptr + 8);
        float4 w0 = *(const float4*)(Wptr);
        float4 w1 = *(const float4*)(Wptr + 8);
        sts_tile(As[0], Bs[0], lr, lc, a0, a1, w0, w1);
    }
    __syncthreads();

    int cur = 0;
    for (int k0 = 16; k0 < K; k0 += 16) {
        float4 a0 = *(const float4*)(Aptr + k0);
        float4 a1 = *(const float4*)(Aptr + k0 + 8);
        float4 w0 = *(const float4*)(Wptr + k0);
        float4 w1 = *(const float4*)(Wptr + k0 + 8);
        tile_fma16(As[cur], Bs[cur], acc, tx, ty);
        sts_tile(As[cur ^ 1], Bs[cur ^ 1], lr, lc, a0, a1, w0, w1);
        __syncthreads();
        cur ^= 1;
    }
    tile_fma16(As[cur], Bs[cur], acc, tx, ty);

#pragma unroll
    for (int i = 0; i < 8; i++) {
        const int m = m0 + ty * 8 + i;
#pragma unroll
        for (int j = 0; j < 8; j++) {
            const int n = n0 + col_of(tx, j);
            float v = __fadd_rn(acc[i][j], bias[n]);
            if (TANH) v = xla_tanh(v);
            C[(size_t)m * N + n] = v;
        }
    }
}

// ---------------- codebook row norms ----------------
__global__ void ee_kernel(const float* __restrict__ E)
{
    const int row  = blockIdx.x * 8 + (threadIdx.x >> 5);
    const int lane = threadIdx.x & 31;
    const float* e = E + (size_t)row * D2;
    float s = 0.f;
    for (int j = lane; j < D2; j += 32)
        s = __fadd_rn(s, __fmul_rn(e[j], e[j]));
#pragma unroll
    for (int o = 16; o; o >>= 1) s = __fadd_rn(s, __shfl_xor_sync(0xffffffffu, s, o));
    if (lane == 0) g_ee[row] = s;
}

// zz = sum(z*z, axis=1): sequential scalar chain (matches reference order)
__global__ void zz_kernel()
{
    const int m = blockIdx.x * 256 + threadIdx.x;
    if (m >= B_SZ) return;
    const float* z = g_z + (size_t)m * D2;
    float s = 0.f;
    for (int k = 0; k < D2; k++)
        s = __fadd_rn(s, __fmul_rn(z[k], z[k]));
    g_zz[m] = s;
}

__global__ void init_best()
{
    int i = blockIdx.x * 256 + threadIdx.x;
    if (i < B_SZ) g_best[i] = ~0ull;
}

__device__ __forceinline__ unsigned int orderable_f32(float f)
{
    unsigned int u = __float_as_uint(f);
    return (u & 0x80000000u) ? ~u : (u | 0x80000000u);
}

// ------------- VQ scoring, replicating the reference formula -------------
// dist = fl( fl(zz+ee) - fl(2*s) ), s = ascending-k FMA chain; ties -> lowest idx.
__global__ __launch_bounds__(256, 2)
void vq_score(const float* __restrict__ Z, const float* __restrict__ E)
{
    __shared__ float As[2][16][128];
    __shared__ float Bs[2][16][128];
    const int t  = threadIdx.x;
    const int tx = t & 15, ty = t >> 4;
    const int m0 = blockIdx.y * 128, n0 = blockIdx.x * 128;
    const int lr = t >> 1;
    const int lc = (t & 1) * 4;
    const float* Aptr = Z + (size_t)(m0 + lr) * D2 + lc;
    const float* Wptr = E + (size_t)(n0 + lr) * D2 + lc;

    float acc[8][8];
#pragma unroll
    for (int i = 0; i < 8; i++)
#pragma unroll
        for (int j = 0; j < 8; j++) acc[i][j] = 0.f;

    {
        float4 a0 = *(const float4*)(Aptr);
        float4 a1 = *(const float4*)(Aptr + 8);
        float4 w0 = *(const float4*)(Wptr);
        float4 w1 = *(const float4*)(Wptr + 8);
        sts_tile(As[0], Bs[0], lr, lc, a0, a1, w0, w1);
    }
    __syncthreads();

    int cur = 0;
    for (int k0 = 16; k0 < D2; k0 += 16) {
        float4 a0 = *(const float4*)(Aptr + k0);
        float4 a1 = *(const float4*)(Aptr + k0 + 8);
        float4 w0 = *(const float4*)(Wptr + k0);
        float4 w1 = *(const float4*)(Wptr + k0 + 8);
        tile_fma16(As[cur], Bs[cur], acc, tx, ty);
        sts_tile(As[cur ^ 1], Bs[cur ^ 1], lr, lc, a0, a1, w0, w1);
        __syncthreads();
        cur ^= 1;
    }
    tile_fma16(As[cur], Bs[cur], acc, tx, ty);

    // rows m0+ty*8+i live on the 16 lanes sharing ty (half-warp): shfl-min reduce
#pragma unroll
    for (int i = 0; i < 8; i++) {
        const int m = m0 + ty * 8 + i;
        const float zzm = g_zz[m];
        unsigned long long best = ~0ull;
#pragma unroll
        for (int j = 0; j < 8; j++) {
            const int n = n0 + col_of(tx, j);
            const float zze  = __fadd_rn(zzm, g_ee[n]);     // fl(zz+ee)
            const float twos = __fmul_rn(2.f, acc[i][j]);   // exact
            const float d    = __fadd_rn(zze, -twos);       // fl(. - 2s)
            unsigned long long key =
                ((unsigned long long)orderable_f32(d) << 32) | (unsigned int)n;
            best = (key < best) ? key : best;
        }
#pragma unroll
        for (int o = 8; o; o >>= 1) {
            unsigned long long other = __shfl_xor_sync(0xffffffffu, best, o);
            best = (other < best) ? other : best;
        }
        if (tx == 0) atomicMin(&g_best[m], best);
    }
}

// --------- gather q = E[idx], emit q_st, per-row (q-z)^2 partials ---------
__global__ void gather_loss(const float* __restrict__ E, float* __restrict__ out_q)
{
    const int m   = blockIdx.x;
    const int idx = (int)(unsigned int)(g_best[m] & 0xFFFFFFFFull);
    const float* e = E + (size_t)idx * D2;
    const float* z = g_z + (size_t)m * D2;
    float s = 0.f;
    for (int j = threadIdx.x; j < D2; j += 256) {
        float qv = e[j];
        float d  = qv - z[j];
        s = fmaf(d, d, s);
        g_q[(size_t)m * D2 + j] = qv;
        if (out_q) out_q[(size_t)m * D2 + j] = qv;
    }
    __shared__ float red[256];
    red[threadIdx.x] = s;
    __syncthreads();
    for (int o = 128; o; o >>= 1) {
        if (threadIdx.x < o) red[threadIdx.x] += red[threadIdx.x + o];
        __syncthreads();
    }
    if (threadIdx.x == 0) g_rowsum[m] = red[0];
}

__global__ void reduce_loss(float* __restrict__ out_loss)
{
    __shared__ float red[1024];
    float s = 0.f;
    for (int i = threadIdx.x; i < B_SZ; i += 1024) s += g_rowsum[i];
    red[threadIdx.x] = s;
    __syncthreads();
    for (int o = 512; o; o >>= 1) {
        if (threadIdx.x < o) red[threadIdx.x] += red[threadIdx.x + o];
        __syncthreads();
    }
    if (threadIdx.x == 0)
        out_loss[0] = red[0] * (1.25f / (float)((size_t)B_SZ * D2));
}

// ----------------------------------------------------------------
extern "C" void kernel_launch(void* const* d_in, const int* in_sizes, int n_in,
                              void* d_out, int out_size)
{
    const float* X  = (const float*)d_in[0];
    const float* W1 = (const float*)d_in[1];
    const float* b1 = (const float*)d_in[2];
    const float* W2 = (const float*)d_in[3];
    const float* b2 = (const float*)d_in[4];
    const float* W3 = (const float*)d_in[5];
    const float* b3 = (const float*)d_in[6];
    const float* E  = (const float*)d_in[7];
    const float* W4 = (const float*)d_in[8];
    const float* b4 = (const float*)d_in[9];
    const float* W5 = (const float*)d_in[10];
    const float* b5 = (const float*)d_in[11];
    const float* W6 = (const float*)d_in[12];
    const float* b6 = (const float*)d_in[13];

    float *h1, *h2, *z, *q;
    cudaGetSymbolAddress((void**)&h1, g_h1);
    cudaGetSymbolAddress((void**)&h2, g_h2);
    cudaGetSymbolAddress((void**)&z,  g_z);
    cudaGetSymbolAddress((void**)&q,  g_q);

    float* out = (float*)d_out;
    const long long full = 1LL + (long long)B_SZ * G_NUM + (long long)B_SZ * D2;
    float* out_loss = nullptr;
    float* out_x    = out;
    float* out_q    = nullptr;
    if ((long long)out_size == full) {
        out_loss = out;
        out_x    = out + 1;
        out_q    = out + 1 + (long long)B_SZ * G_NUM;
    }

    const dim3 blk(256);

    ee_kernel<<<KEMB / 8, 256>>>(E);
    init_best<<<B_SZ / 256, 256>>>();

    // encoder
    gemm_bias_act<true><<<dim3(D0 / 128, B_SZ / 128), blk>>>(X,  W1, b1, h1, B_SZ, D0, G_NUM);
    gemm_bias_act<true><<<dim3(D1 / 128, B_SZ / 128), blk>>>(h1, W2, b2, h2, B_SZ, D1, D0);
    gemm_bias_act<true><<<dim3(D2 / 128, B_SZ / 128), blk>>>(h2, W3, b3, z,  B_SZ, D2, D1);

    // VQ
    zz_kernel<<<B_SZ / 256, 256>>>();
    vq_score<<<dim3(KEMB / 128, B_SZ / 128), blk>>>(z, E);
    gather_loss<<<B_SZ, 256>>>(E, out_q);
    if (out_loss) reduce_loss<<<1, 1024>>>(out_loss);

    // decoder (q_st == q in forward values)
    gemm_bias_act<true ><<<dim3(D1 / 128,   B_SZ / 128), blk>>>(q,  W4, b4, h2,   B_SZ, D1,   D2);
    gemm_bias_act<true ><<<dim3(D0 / 128,   B_SZ / 128), blk>>>(h2, W5, b5, h1,   B_SZ, D0,   D1);
    gemm_bias_act<false><<<dim3(G_NUM / 128, B_SZ / 128), blk>>>(h1, W6, b6, out_x, B_SZ, G_NUM, D0);
}

// round 8
// speedup vs baseline: 1.5171x; 1.1025x over previous
#include <cuda_runtime.h>
#include <cuda_bf16.h>
#include <cstdint>

#define B_SZ 4096
#define G_NUM 16384
#define D0 4096
#define D1 2048
#define D2 512
#define KEMB 8192

// -------- scratch (static device memory; no allocations) --------
__device__ float g_h1[(size_t)B_SZ * D0];
__device__ float g_h2[(size_t)B_SZ * D1];
__device__ float g_z [(size_t)B_SZ * D2];
__device__ float g_q [(size_t)B_SZ * D2];
__device__ float g_ee[KEMB];
__device__ float g_zz[B_SZ];
__device__ unsigned long long g_best[B_SZ];
__device__ float g_rowsum[B_SZ];

// ---------------- XLA/Eigen tanh f32 rational approximation ----------------
__device__ __forceinline__ float xla_tanh(float x)
{
    if (fabsf(x) < 0.0004f) return x;
    float xc = fminf(fmaxf(x, -7.90531110763549805f), 7.90531110763549805f);
    float x2 = __fmul_rn(xc, xc);
    float p = fmaf(x2, -2.76076847742355e-16f, 2.00018790482477e-13f);
    p = fmaf(x2, p, -8.60467152213735e-11f);
    p = fmaf(x2, p,  5.12229709037114e-08f);
    p = fmaf(x2, p,  1.48572235717979e-05f);
    p = fmaf(x2, p,  6.37261928875436e-04f);
    p = fmaf(x2, p,  4.89352455891786e-03f);
    p = __fmul_rn(xc, p);
    float q = fmaf(x2, 1.19825839466702e-06f, 1.18534705686654e-04f);
    q = fmaf(x2, q, 2.26843463243900e-03f);
    q = fmaf(x2, q, 4.89352518554385e-03f);
    return __fdiv_rn(p, q);
}

// ======================= SIMT exact-chain GEMM (encoder) =======================
__device__ __forceinline__ void sts_tile(float (&As)[16][128], float (&Bs)[16][128],
                                         int lr, int lc,
                                         float4 a0, float4 a1, float4 w0, float4 w1)
{
    As[lc + 0][lr] = a0.x; As[lc + 1][lr] = a0.y;
    As[lc + 2][lr] = a0.z; As[lc + 3][lr] = a0.w;
    As[lc + 8][lr] = a1.x; As[lc + 9][lr] = a1.y;
    As[lc +10][lr] = a1.z; As[lc +11][lr] = a1.w;
    Bs[lc + 0][lr] = w0.x; Bs[lc + 1][lr] = w0.y;
    Bs[lc + 2][lr] = w0.z; Bs[lc + 3][lr] = w0.w;
    Bs[lc + 8][lr] = w1.x; Bs[lc + 9][lr] = w1.y;
    Bs[lc +10][lr] = w1.z; Bs[lc +11][lr] = w1.w;
}

__device__ __forceinline__ void tile_fma16(const float (&As)[16][128],
                                           const float (&Bs)[16][128],
                                           float (&acc)[8][8], int tx, int ty)
{
#pragma unroll
    for (int kk = 0; kk < 16; kk++) {
        float4 a0 = *(const float4*)&As[kk][ty * 8];
        float4 a1 = *(const float4*)&As[kk][ty * 8 + 4];
        float4 b0 = *(const float4*)&Bs[kk][tx * 4];
        float4 b1 = *(const float4*)&Bs[kk][64 + tx * 4];
        float a[8] = {a0.x, a0.y, a0.z, a0.w, a1.x, a1.y, a1.z, a1.w};
        float b[8] = {b0.x, b0.y, b0.z, b0.w, b1.x, b1.y, b1.z, b1.w};
#pragma unroll
        for (int i = 0; i < 8; i++)
#pragma unroll
            for (int j = 0; j < 8; j++)
                acc[i][j] = fmaf(a[i], b[j], acc[i][j]);
    }
}

__device__ __forceinline__ int col_of(int tx, int j)
{
    return (j < 4) ? (tx * 4 + j) : (64 + tx * 4 + (j - 4));
}

template<bool TANH>
__global__ __launch_bounds__(256, 2)
void gemm_bias_act(const float* __restrict__ A, const float* __restrict__ W,
                   const float* __restrict__ bias, float* __restrict__ C,
                   int M, int N, int K)
{
    __shared__ float As[2][16][128];
    __shared__ float Bs[2][16][128];
    const int t  = threadIdx.x;
    const int tx = t & 15, ty = t >> 4;
    const int m0 = blockIdx.y * 128, n0 = blockIdx.x * 128;
    const int lr = t >> 1;
    const int lc = (t & 1) * 4;
    const float* Aptr = A + (size_t)(m0 + lr) * K + lc;
    const float* Wptr = W + (size_t)(n0 + lr) * K + lc;

    float acc[8][8];
#pragma unroll
    for (int i = 0; i < 8; i++)
#pragma unroll
        for (int j = 0; j < 8; j++) acc[i][j] = 0.f;

    {
        float4 a0 = *(const float4*)(Aptr);
        float4 a1 = *(const float4*)(Aptr + 8);
        float4 w0 = *(const float4*)(Wptr);
        float4 w1 = *(const float4*)(Wptr + 8);
        sts_tile(As[0], Bs[0], lr, lc, a0, a1, w0, w1);
    }
    __syncthreads();

    int cur = 0;
    for (int k0 = 16; k0 < K; k0 += 16) {
        float4 a0 = *(const float4*)(Aptr + k0);
        float4 a1 = *(const float4*)(Aptr + k0 + 8);
        float4 w0 = *(const float4*)(Wptr + k0);
        float4 w1 = *(const float4*)(Wptr + k0 + 8);
        tile_fma16(As[cur], Bs[cur], acc, tx, ty);
        sts_tile(As[cur ^ 1], Bs[cur ^ 1], lr, lc, a0, a1, w0, w1);
        __syncthreads();
        cur ^= 1;
    }
    tile_fma16(As[cur], Bs[cur], acc, tx, ty);

#pragma unroll
    for (int i = 0; i < 8; i++) {
        const int m = m0 + ty * 8 + i;
#pragma unroll
        for (int j = 0; j < 8; j++) {
            const int n = n0 + col_of(tx, j);
            float v = __fadd_rn(acc[i][j], bias[n]);
            if (TANH) v = xla_tanh(v);
            C[(size_t)m * N + n] = v;
        }
    }
}

// ======================= HMMA (mma.sync) decoder GEMM =======================
__device__ __forceinline__ uint32_t smem_u32(const void* p)
{
    uint32_t a;
    asm("{ .reg .u64 t; cvta.to.shared.u64 t, %1; cvt.u32.u64 %0, t; }"
        : "=r"(a) : "l"(p));
    return a;
}

// split fp32 pair -> bf16x2 hi + bf16x2 residual
__device__ __forceinline__ void split2(float f0, float f1, uint32_t& hi, uint32_t& lo)
{
    asm("cvt.rn.bf16x2.f32 %0, %1, %2;" : "=r"(hi) : "f"(f1), "f"(f0));
    float h0 = __uint_as_float(hi << 16);
    float h1 = __uint_as_float(hi & 0xFFFF0000u);
    float r0 = __fadd_rn(f0, -h0);
    float r1 = __fadd_rn(f1, -h1);
    asm("cvt.rn.bf16x2.f32 %0, %1, %2;" : "=r"(lo) : "f"(r1), "f"(r0));
}

__device__ __forceinline__ void mma16816(float* c, uint32_t a0, uint32_t a1,
                                         uint32_t a2, uint32_t a3,
                                         uint32_t b0, uint32_t b1)
{
    asm volatile(
        "mma.sync.aligned.m16n8k16.row.col.f32.bf16.bf16.f32 "
        "{%0,%1,%2,%3}, {%4,%5,%6,%7}, {%8,%9}, {%0,%1,%2,%3};"
        : "+f"(c[0]), "+f"(c[1]), "+f"(c[2]), "+f"(c[3])
        : "r"(a0), "r"(a1), "r"(a2), "r"(a3), "r"(b0), "r"(b1));
}

__device__ __forceinline__ uint2 lds64(uint32_t a)
{
    uint2 v;
    asm volatile("ld.shared.v2.u32 {%0,%1}, [%2];" : "=r"(v.x), "=r"(v.y) : "r"(a));
    return v;
}

__device__ __forceinline__ void sts128(uint32_t a, uint32_t x, uint32_t y,
                                       uint32_t z, uint32_t w)
{
    asm volatile("st.shared.v4.u32 [%0], {%1,%2,%3,%4};"
                 :: "r"(a), "r"(x), "r"(y), "r"(z), "r"(w));
}

// Tile layout in smem: per slab (K=32), A and B tiles of 128 rows.
// Row r, k-pair p (=k/2), split s: byte = r*160 + p*8 + s*4 (hi/lo interleaved).
#define TSTRIDE 160
#define TILE_BYTES (128 * TSTRIDE)          // 20480
#define BUF_BYTES  (2 * TILE_BYTES)         // A + B = 40960
#define MMA_SMEM   (2 * BUF_BYTES)          // double buffered = 81920

// C = act(A @ W^T + bias); A [4096,K] fp32, W [N,K] fp32, bf16 3-term split.
// NOTE: C may be only 4-byte aligned (x_recon lives at d_out+1) -> scalar stores.
template<bool TANH>
__global__ __launch_bounds__(256, 1)
void gemm_mma(const float* __restrict__ A, const float* __restrict__ W,
              const float* __restrict__ bias, float* __restrict__ C,
              int N, int K)
{
    extern __shared__ char sm[];
    const uint32_t sb = smem_u32(sm);
    const int t    = threadIdx.x;
    const int lane = t & 31;
    const int wid  = t >> 5;
    const int wm   = (wid >> 2) * 64;       // warp m-offset in CTA tile
    const int wn   = (wid & 3) * 32;        // warp n-offset
    const int m0   = blockIdx.x * 128;
    const int n0   = blockIdx.y * 128;

    // gmem loader mapping: 2 threads per row, 16 k each
    const int grow  = t >> 1;
    const int khalf = (t & 1) * 16;
    const float* Ap = A + (size_t)(m0 + grow) * K + khalf;
    const float* Wp = W + (size_t)(n0 + grow) * K + khalf;
    const uint32_t srow = (uint32_t)(grow * TSTRIDE + khalf * 4); // kpair*8 = khalf*4

    float acc[4][4][4];
#pragma unroll
    for (int i = 0; i < 4; i++)
#pragma unroll
        for (int j = 0; j < 4; j++)
#pragma unroll
            for (int r = 0; r < 4; r++) acc[i][j][r] = 0.f;

    const int nslab = K >> 5;
    float4 pa[4], pb[4];
#pragma unroll
    for (int j = 0; j < 4; j++) {
        pa[j] = *(const float4*)(Ap + j * 4);
        pb[j] = *(const float4*)(Wp + j * 4);
    }

    for (int s = 0; s < nslab; s++) {
        const uint32_t buf = sb + (uint32_t)(s & 1) * BUF_BYTES;
        // store prefetched slab (split to bf16 hi/lo, interleaved)
#pragma unroll
        for (int j = 0; j < 4; j++) {
            uint32_t h01, l01, h23, l23;
            split2(pa[j].x, pa[j].y, h01, l01);
            split2(pa[j].z, pa[j].w, h23, l23);
            sts128(buf + srow + j * 16, h01, l01, h23, l23);
            split2(pb[j].x, pb[j].y, h01, l01);
            split2(pb[j].z, pb[j].w, h23, l23);
            sts128(buf + TILE_BYTES + srow + j * 16, h01, l01, h23, l23);
        }
        __syncthreads();
        if (s + 1 < nslab) {
            const float* ap = Ap + (s + 1) * 32;
            const float* wp = Wp + (s + 1) * 32;
#pragma unroll
            for (int j = 0; j < 4; j++) {
                pa[j] = *(const float4*)(ap + j * 4);
                pb[j] = *(const float4*)(wp + j * 4);
            }
        }
        // compute: 2 k16 steps
        const uint32_t abase = buf + (uint32_t)((wm + (lane >> 2)) * TSTRIDE + (lane & 3) * 8);
        const uint32_t bbase = buf + TILE_BYTES +
                               (uint32_t)((wn + (lane >> 2)) * TSTRIDE + (lane & 3) * 8);
#pragma unroll
        for (int ks = 0; ks < 2; ks++) {
            const uint32_t ko = (uint32_t)(ks * 64);     // 8 kpairs * 8B
            uint2 bf[4][2];                              // [nt][b0/b1] = {hi, lo}
#pragma unroll
            for (int nt = 0; nt < 4; nt++) {
                bf[nt][0] = lds64(bbase + nt * (8 * TSTRIDE) + ko);
                bf[nt][1] = lds64(bbase + nt * (8 * TSTRIDE) + ko + 32);
            }
#pragma unroll
            for (int mt = 0; mt < 4; mt++) {
                const uint32_t ab = abase + mt * (16 * TSTRIDE) + ko;
                uint2 r0 = lds64(ab);
                uint2 r1 = lds64(ab + 8 * TSTRIDE);
                uint2 r2 = lds64(ab + 32);
                uint2 r3 = lds64(ab + 8 * TSTRIDE + 32);
#pragma unroll
                for (int nt = 0; nt < 4; nt++) {
                    float* c = acc[mt][nt];
                    mma16816(c, r0.x, r1.x, r2.x, r3.x, bf[nt][0].x, bf[nt][1].x); // A1*B1
                    mma16816(c, r0.x, r1.x, r2.x, r3.x, bf[nt][0].y, bf[nt][1].y); // A1*B2
                    mma16816(c, r0.y, r1.y, r2.y, r3.y, bf[nt][0].x, bf[nt][1].x); // A2*B1
                }
            }
        }
        __syncthreads();
    }

    // epilogue: c-frag rows l/4, l/4+8; cols (l%4)*2, +1.  SCALAR stores:
    // C may be 4-byte aligned only (x_recon at d_out+1).
#pragma unroll
    for (int mt = 0; mt < 4; mt++) {
        const int mr = m0 + wm + mt * 16 + (lane >> 2);
#pragma unroll
        for (int nt = 0; nt < 4; nt++) {
            const int nc = n0 + wn + nt * 8 + (lane & 3) * 2;
            const float b0 = bias[nc], b1 = bias[nc + 1];
            float v0 = __fadd_rn(acc[mt][nt][0], b0);
            float v1 = __fadd_rn(acc[mt][nt][1], b1);
            float v2 = __fadd_rn(acc[mt][nt][2], b0);
            float v3 = __fadd_rn(acc[mt][nt][3], b1);
            if (TANH) { v0 = xla_tanh(v0); v1 = xla_tanh(v1); v2 = xla_tanh(v2); v3 = xla_tanh(v3); }
            float* r0 = &C[(size_t)mr * N + nc];
            float* r1 = &C[(size_t)(mr + 8) * N + nc];
            r0[0] = v0; r0[1] = v1;
            r1[0] = v2; r1[1] = v3;
        }
    }
}

// ======================= VQ / misc kernels (unchanged, passing) =======================
__global__ void ee_kernel(const float* __restrict__ E)
{
    const int row  = blockIdx.x * 8 + (threadIdx.x >> 5);
    const int lane = threadIdx.x & 31;
    const float* e = E + (size_t)row * D2;
    float s = 0.f;
    for (int j = lane; j < D2; j += 32)
        s = __fadd_rn(s, __fmul_rn(e[j], e[j]));
#pragma unroll
    for (int o = 16; o; o >>= 1) s = __fadd_rn(s, __shfl_xor_sync(0xffffffffu, s, o));
    if (lane == 0) g_ee[row] = s;
}

__global__ void zz_kernel()
{
    const int m = blockIdx.x * 256 + threadIdx.x;
    if (m >= B_SZ) return;
    const float* z = g_z + (size_t)m * D2;
    float s = 0.f;
    for (int k = 0; k < D2; k++)
        s = __fadd_rn(s, __fmul_rn(z[k], z[k]));
    g_zz[m] = s;
}

__global__ void init_best()
{
    int i = blockIdx.x * 256 + threadIdx.x;
    if (i < B_SZ) g_best[i] = ~0ull;
}

__device__ __forceinline__ unsigned int orderable_f32(float f)
{
    unsigned int u = __float_as_uint(f);
    return (u & 0x80000000u) ? ~u : (u | 0x80000000u);
}

__global__ __launch_bounds__(256, 2)
void vq_score(const float* __restrict__ Z, const float* __restrict__ E)
{
    __shared__ float As[2][16][128];
    __shared__ float Bs[2][16][128];
    const int t  = threadIdx.x;
    const int tx = t & 15, ty = t >> 4;
    const int m0 = blockIdx.y * 128, n0 = blockIdx.x * 128;
    const int lr = t >> 1;
    const int lc = (t & 1) * 4;
    const float* Aptr = Z + (size_t)(m0 + lr) * D2 + lc;
    const float* Wptr = E + (size_t)(n0 + lr) * D2 + lc;

    float acc[8][8];
#pragma unroll
    for (int i = 0; i < 8; i++)
#pragma unroll
        for (int j = 0; j < 8; j++) acc[i][j] = 0.f;

    {
        float4 a0 = *(const float4*)(Aptr);
        float4 a1 = *(const float4*)(Aptr + 8);
        float4 w0 = *(const float4*)(Wptr);
        float4 w1 = *(const float4*)(Wptr + 8);
        sts_tile(As[0], Bs[0], lr, lc, a0, a1, w0, w1);
    }
    __syncthreads();

    int cur = 0;
    for (int k0 = 16; k0 < D2; k0 += 16) {
        float4 a0 = *(const float4*)(Aptr + k0);
        float4 a1 = *(const float4*)(Aptr + k0 + 8);
        float4 w0 = *(const float4*)(Wptr + k0);
        float4 w1 = *(const float4*)(Wptr + k0 + 8);
        tile_fma16(As[cur], Bs[cur], acc, tx, ty);
        sts_tile(As[cur ^ 1], Bs[cur ^ 1], lr, lc, a0, a1, w0, w1);
        __syncthreads();
        cur ^= 1;
    }
    tile_fma16(As[cur], Bs[cur], acc, tx, ty);

#pragma unroll
    for (int i = 0; i < 8; i++) {
        const int m = m0 + ty * 8 + i;
        const float zzm = g_zz[m];
        unsigned long long best = ~0ull;
#pragma unroll
        for (int j = 0; j < 8; j++) {
            const int n = n0 + col_of(tx, j);
            const float zze  = __fadd_rn(zzm, g_ee[n]);
            const float twos = __fmul_rn(2.f, acc[i][j]);
            const float d    = __fadd_rn(zze, -twos);
            unsigned long long key =
                ((unsigned long long)orderable_f32(d) << 32) | (unsigned int)n;
            best = (key < best) ? key : best;
        }
#pragma unroll
        for (int o = 8; o; o >>= 1) {
            unsigned long long other = __shfl_xor_sync(0xffffffffu, best, o);
            best = (other < best) ? other : best;
        }
        if (tx == 0) atomicMin(&g_best[m], best);
    }
}

__global__ void gather_loss(const float* __restrict__ E, float* __restrict__ out_q)
{
    const int m   = blockIdx.x;
    const int idx = (int)(unsigned int)(g_best[m] & 0xFFFFFFFFull);
    const float* e = E + (size_t)idx * D2;
    const float* z = g_z + (size_t)m * D2;
    float s = 0.f;
    for (int j = threadIdx.x; j < D2; j += 256) {
        float qv = e[j];
        float d  = qv - z[j];
        s = fmaf(d, d, s);
        g_q[(size_t)m * D2 + j] = qv;
        if (out_q) out_q[(size_t)m * D2 + j] = qv;
    }
    __shared__ float red[256];
    red[threadIdx.x] = s;
    __syncthreads();
    for (int o = 128; o; o >>= 1) {
        if (threadIdx.x < o) red[threadIdx.x] += red[threadIdx.x + o];
        __syncthreads();
    }
    if (threadIdx.x == 0) g_rowsum[m] = red[0];
}

__global__ void reduce_loss(float* __restrict__ out_loss)
{
    __shared__ float red[1024];
    float s = 0.f;
    for (int i = threadIdx.x; i < B_SZ; i += 1024) s += g_rowsum[i];
    red[threadIdx.x] = s;
    __syncthreads();
    for (int o = 512; o; o >>= 1) {
        if (threadIdx.x < o) red[threadIdx.x] += red[threadIdx.x + o];
        __syncthreads();
    }
    if (threadIdx.x == 0)
        out_loss[0] = red[0] * (1.25f / (float)((size_t)B_SZ * D2));
}

// ----------------------------------------------------------------
extern "C" void kernel_launch(void* const* d_in, const int* in_sizes, int n_in,
                              void* d_out, int out_size)
{
    const float* X  = (const float*)d_in[0];
    const float* W1 = (const float*)d_in[1];
    const float* b1 = (const float*)d_in[2];
    const float* W2 = (const float*)d_in[3];
    const float* b2 = (const float*)d_in[4];
    const float* W3 = (const float*)d_in[5];
    const float* b3 = (const float*)d_in[6];
    const float* E  = (const float*)d_in[7];
    const float* W4 = (const float*)d_in[8];
    const float* b4 = (const float*)d_in[9];
    const float* W5 = (const float*)d_in[10];
    const float* b5 = (const float*)d_in[11];
    const float* W6 = (const float*)d_in[12];
    const float* b6 = (const float*)d_in[13];

    float *h1, *h2, *z, *q;
    cudaGetSymbolAddress((void**)&h1, g_h1);
    cudaGetSymbolAddress((void**)&h2, g_h2);
    cudaGetSymbolAddress((void**)&z,  g_z);
    cudaGetSymbolAddress((void**)&q,  g_q);

    float* out = (float*)d_out;
    const long long full = 1LL + (long long)B_SZ * G_NUM + (long long)B_SZ * D2;
    float* out_loss = nullptr;
    float* out_x    = out;
    float* out_q    = nullptr;
    if ((long long)out_size == full) {
        out_loss = out;
        out_x    = out + 1;
        out_q    = out + 1 + (long long)B_SZ * G_NUM;
    }

    cudaFuncSetAttribute(gemm_mma<true>,
                         cudaFuncAttributeMaxDynamicSharedMemorySize, MMA_SMEM);
    cudaFuncSetAttribute(gemm_mma<false>,
                         cudaFuncAttributeMaxDynamicSharedMemorySize, MMA_SMEM);

    const dim3 blk(256);

    ee_kernel<<<KEMB / 8, 256>>>(E);
    init_best<<<B_SZ / 256, 256>>>();

    // encoder (bit-exact fp32 chain: feeds argmin)
    gemm_bias_act<true><<<dim3(D0 / 128, B_SZ / 128), blk>>>(X,  W1, b1, h1, B_SZ, D0, G_NUM);
    gemm_bias_act<true><<<dim3(D1 / 128, B_SZ / 128), blk>>>(h1, W2, b2, h2, B_SZ, D1, D0);
    gemm_bias_act<true><<<dim3(D2 / 128, B_SZ / 128), blk>>>(h2, W3, b3, z,  B_SZ, D2, D1);

    // VQ (bit-exact replication of reference dist formula)
    zz_kernel<<<B_SZ / 256, 256>>>();
    vq_score<<<dim3(KEMB / 128, B_SZ / 128), blk>>>(z, E);
    gather_loss<<<B_SZ, 256>>>(E, out_q);
    if (out_loss) reduce_loss<<<1, 1024>>>(out_loss);

    // decoder: mma.sync bf16 3-term split (tolerance-bound path)
    gemm_mma<true ><<<dim3(B_SZ / 128, D1 / 128),    blk, MMA_SMEM>>>(q,  W4, b4, h2,    D1,    D2);
    gemm_mma<true ><<<dim3(B_SZ / 128, D0 / 128),    blk, MMA_SMEM>>>(h2, W5, b5, h1,    D0,    D1);
    gemm_mma<false><<<dim3(B_SZ / 128, G_NUM / 128), blk, MMA_SMEM>>>(h1, W6, b6, out_x, G_NUM, D0);
}

// round 9
// speedup vs baseline: 1.5455x; 1.0187x over previous
#include <cuda_runtime.h>
#include <cuda_bf16.h>
#include <cstdint>

#define B_SZ 4096
#define G_NUM 16384
#define D0 4096
#define D1 2048
#define D2 512
#define KEMB 8192

// -------- scratch (static device memory; no allocations) --------
__device__ float g_h1[(size_t)B_SZ * D0];        // encoder h1 (fp32)
__device__ float g_h2[(size_t)B_SZ * D1];        // encoder h2 (fp32)
__device__ float g_z [(size_t)B_SZ * D2];
__device__ float g_ee[KEMB];
__device__ float g_zz[B_SZ];
__device__ unsigned long long g_best[B_SZ];
__device__ float g_rowsum[B_SZ];

// packed bf16 hi/lo pairs (u32 = 2 consecutive bf16 elements)
__device__ uint32_t g_w4h[(size_t)D1 * D2 / 2],    g_w4l[(size_t)D1 * D2 / 2];
__device__ uint32_t g_w5h[(size_t)D0 * D1 / 2],    g_w5l[(size_t)D0 * D1 / 2];
__device__ uint32_t g_w6h[(size_t)G_NUM * D0 / 2], g_w6l[(size_t)G_NUM * D0 / 2];
__device__ uint32_t g_qh [(size_t)B_SZ * D2 / 2],  g_ql [(size_t)B_SZ * D2 / 2];
__device__ uint32_t g_h2h[(size_t)B_SZ * D1 / 2],  g_h2l[(size_t)B_SZ * D1 / 2];
__device__ uint32_t g_h1h[(size_t)B_SZ * D0 / 2],  g_h1l[(size_t)B_SZ * D0 / 2];

// ---------------- XLA/Eigen tanh f32 rational approximation ----------------
__device__ __forceinline__ float xla_tanh(float x)
{
    if (fabsf(x) < 0.0004f) return x;
    float xc = fminf(fmaxf(x, -7.90531110763549805f), 7.90531110763549805f);
    float x2 = __fmul_rn(xc, xc);
    float p = fmaf(x2, -2.76076847742355e-16f, 2.00018790482477e-13f);
    p = fmaf(x2, p, -8.60467152213735e-11f);
    p = fmaf(x2, p,  5.12229709037114e-08f);
    p = fmaf(x2, p,  1.48572235717979e-05f);
    p = fmaf(x2, p,  6.37261928875436e-04f);
    p = fmaf(x2, p,  4.89352455891786e-03f);
    p = __fmul_rn(xc, p);
    float q = fmaf(x2, 1.19825839466702e-06f, 1.18534705686654e-04f);
    q = fmaf(x2, q, 2.26843463243900e-03f);
    q = fmaf(x2, q, 4.89352518554385e-03f);
    return __fdiv_rn(p, q);
}

// ---------------- packed fp32x2 helpers ----------------
__device__ __forceinline__ void ffma2(unsigned long long& d,
                                      unsigned long long a, unsigned long long b)
{
    asm("fma.rn.f32x2 %0, %1, %2, %0;" : "+l"(d) : "l"(a), "l"(b));
}
__device__ __forceinline__ unsigned long long dup2(float a)
{
    unsigned long long r;
    asm("mov.b64 %0, {%1, %1};" : "=l"(r) : "f"(a));
    return r;
}
__device__ __forceinline__ float2 unpack2(unsigned long long v)
{
    float lo, hi;
    asm("mov.b64 {%0, %1}, %2;" : "=f"(lo), "=f"(hi) : "l"(v));
    return make_float2(lo, hi);
}

// ======================= SIMT exact-chain GEMM (encoder) =======================
__device__ __forceinline__ void sts_tile(float (&As)[16][128], float (&Bs)[16][128],
                                         int lr, int lc,
                                         float4 a0, float4 a1, float4 w0, float4 w1)
{
    As[lc + 0][lr] = a0.x; As[lc + 1][lr] = a0.y;
    As[lc + 2][lr] = a0.z; As[lc + 3][lr] = a0.w;
    As[lc + 8][lr] = a1.x; As[lc + 9][lr] = a1.y;
    As[lc +10][lr] = a1.z; As[lc +11][lr] = a1.w;
    Bs[lc + 0][lr] = w0.x; Bs[lc + 1][lr] = w0.y;
    Bs[lc + 2][lr] = w0.z; Bs[lc + 3][lr] = w0.w;
    Bs[lc + 8][lr] = w1.x; Bs[lc + 9][lr] = w1.y;
    Bs[lc +10][lr] = w1.z; Bs[lc +11][lr] = w1.w;
}

// packed-f32x2 inner product tile; each acc element keeps its own ascending-k
// IEEE-RN FMA chain (bit-identical to scalar fmaf version).
__device__ __forceinline__ void tile_fma16p(const float (&As)[16][128],
                                            const float (&Bs)[16][128],
                                            unsigned long long (&acc)[8][4],
                                            int tx, int ty)
{
#pragma unroll
    for (int kk = 0; kk < 16; kk++) {
        float4 a0 = *(const float4*)&As[kk][ty * 8];
        float4 a1 = *(const float4*)&As[kk][ty * 8 + 4];
        ulonglong2 b01 = *(const ulonglong2*)&Bs[kk][tx * 4];
        ulonglong2 b23 = *(const ulonglong2*)&Bs[kk][64 + tx * 4];
        unsigned long long bb[4] = {b01.x, b01.y, b23.x, b23.y};
        float a[8] = {a0.x, a0.y, a0.z, a0.w, a1.x, a1.y, a1.z, a1.w};
#pragma unroll
        for (int i = 0; i < 8; i++) {
            unsigned long long ai = dup2(a[i]);
#pragma unroll
            for (int p = 0; p < 4; p++) ffma2(acc[i][p], ai, bb[p]);
        }
    }
}

__device__ __forceinline__ int col_of(int tx, int j)
{
    return (j < 4) ? (tx * 4 + j) : (64 + tx * 4 + (j - 4));
}

template<bool TANH>
__global__ __launch_bounds__(256, 2)
void gemm_bias_act(const float* __restrict__ A, const float* __restrict__ W,
                   const float* __restrict__ bias, float* __restrict__ C,
                   int M, int N, int K)
{
    __shared__ float As[2][16][128];
    __shared__ float Bs[2][16][128];
    const int t  = threadIdx.x;
    const int tx = t & 15, ty = t >> 4;
    const int m0 = blockIdx.y * 128, n0 = blockIdx.x * 128;
    const int lr = t >> 1;
    const int lc = (t & 1) * 4;
    const float* Aptr = A + (size_t)(m0 + lr) * K + lc;
    const float* Wptr = W + (size_t)(n0 + lr) * K + lc;

    unsigned long long acc[8][4];
#pragma unroll
    for (int i = 0; i < 8; i++)
#pragma unroll
        for (int p = 0; p < 4; p++) acc[i][p] = 0ull;

    {
        float4 a0 = *(const float4*)(Aptr);
        float4 a1 = *(const float4*)(Aptr + 8);
        float4 w0 = *(const float4*)(Wptr);
        float4 w1 = *(const float4*)(Wptr + 8);
        sts_tile(As[0], Bs[0], lr, lc, a0, a1, w0, w1);
    }
    __syncthreads();

    int cur = 0;
    for (int k0 = 16; k0 < K; k0 += 16) {
        float4 a0 = *(const float4*)(Aptr + k0);
        float4 a1 = *(const float4*)(Aptr + k0 + 8);
        float4 w0 = *(const float4*)(Wptr + k0);
        float4 w1 = *(const float4*)(Wptr + k0 + 8);
        tile_fma16p(As[cur], Bs[cur], acc, tx, ty);
        sts_tile(As[cur ^ 1], Bs[cur ^ 1], lr, lc, a0, a1, w0, w1);
        __syncthreads();
        cur ^= 1;
    }
    tile_fma16p(As[cur], Bs[cur], acc, tx, ty);

#pragma unroll
    for (int i = 0; i < 8; i++) {
        const int m = m0 + ty * 8 + i;
#pragma unroll
        for (int p = 0; p < 4; p++) {
            float2 pr = unpack2(acc[i][p]);
#pragma unroll
            for (int h = 0; h < 2; h++) {
                const int j = 2 * p + h;
                const int n = n0 + col_of(tx, j);
                float v = __fadd_rn(h ? pr.y : pr.x, bias[n]);
                if (TANH) v = xla_tanh(v);
                C[(size_t)m * N + n] = v;
            }
        }
    }
}

// ======================= bf16 split helpers =======================
// split fp32 pair -> bf16x2 hi + bf16x2 residual (packed u32 each)
__device__ __forceinline__ void split2(float f0, float f1, uint32_t& hi, uint32_t& lo)
{
    asm("cvt.rn.bf16x2.f32 %0, %1, %2;" : "=r"(hi) : "f"(f1), "f"(f0));
    float h0 = __uint_as_float(hi << 16);
    float h1 = __uint_as_float(hi & 0xFFFF0000u);
    float r0 = __fadd_rn(f0, -h0);
    float r1 = __fadd_rn(f1, -h1);
    asm("cvt.rn.bf16x2.f32 %0, %1, %2;" : "=r"(lo) : "f"(r1), "f"(r0));
}

// elementwise weight split: W fp32 -> packed hi/lo bf16 pair arrays
__global__ void split_pairs(const float* __restrict__ W, uint32_t* __restrict__ Wh,
                            uint32_t* __restrict__ Wl, int n4)
{
    int i = blockIdx.x * 256 + threadIdx.x;
    if (i >= n4) return;
    float4 v = ((const float4*)W)[i];
    uint32_t h0, l0, h1, l1;
    split2(v.x, v.y, h0, l0);
    split2(v.z, v.w, h1, l1);
    ((uint2*)Wh)[i] = make_uint2(h0, h1);
    ((uint2*)Wl)[i] = make_uint2(l0, l1);
}

// ======================= HMMA decoder GEMM (bf16 3-term split) =======================
__device__ __forceinline__ uint32_t smem_u32(const void* p)
{
    uint32_t a;
    asm("{ .reg .u64 t; cvta.to.shared.u64 t, %1; cvt.u32.u64 %0, t; }"
        : "=r"(a) : "l"(p));
    return a;
}

__device__ __forceinline__ void mma16816(float* c, const uint32_t* a, const uint32_t* b)
{
    asm volatile(
        "mma.sync.aligned.m16n8k16.row.col.f32.bf16.bf16.f32 "
        "{%0,%1,%2,%3}, {%4,%5,%6,%7}, {%8,%9}, {%0,%1,%2,%3};"
        : "+f"(c[0]), "+f"(c[1]), "+f"(c[2]), "+f"(c[3])
        : "r"(a[0]), "r"(a[1]), "r"(a[2]), "r"(a[3]), "r"(b[0]), "r"(b[1]));
}

__device__ __forceinline__ void ldmx4(uint32_t* r, uint32_t a)
{
    asm volatile("ldmatrix.sync.aligned.m8n8.x4.shared.b16 {%0,%1,%2,%3}, [%4];"
                 : "=r"(r[0]), "=r"(r[1]), "=r"(r[2]), "=r"(r[3]) : "r"(a));
}
__device__ __forceinline__ void ldmx2(uint32_t* r, uint32_t a)
{
    asm volatile("ldmatrix.sync.aligned.m8n8.x2.shared.b16 {%0,%1}, [%2];"
                 : "=r"(r[0]), "=r"(r[1]) : "r"(a));
}
__device__ __forceinline__ void sts128(uint32_t a, uint4 v)
{
    asm volatile("st.shared.v4.u32 [%0], {%1,%2,%3,%4};"
                 :: "r"(a), "r"(v.x), "r"(v.y), "r"(v.z), "r"(v.w));
}

// smem: 4 tiles (Ah, Al, Bh, Bl), 128 rows x 32 bf16 (64B) padded to 80B stride
#define DSTRIDE 80
#define DTILE  (128 * DSTRIDE)   // 10240
#define DBUF   (4 * DTILE)       // 40960
#define DSMEM  (2 * DBUF)        // 81920

// C = act(A @ W^T + bias). Inputs are packed bf16 hi/lo pair arrays.
// OUTMODE 0: fp32 C (scalar stores; C may be 4B-aligned). OUTMODE 1: bf16 split out.
template<int OUTMODE, bool TANH>
__global__ __launch_bounds__(256, 1)
void gemm_mma2(const uint32_t* __restrict__ Ahp, const uint32_t* __restrict__ Alp,
               const uint32_t* __restrict__ Bhp, const uint32_t* __restrict__ Blp,
               const float* __restrict__ bias, float* __restrict__ C,
               uint32_t* __restrict__ Chp, uint32_t* __restrict__ Clp,
               int N, int K)
{
    extern __shared__ char sm[];
    const uint32_t sb = smem_u32(sm);
    const int t    = threadIdx.x;
    const int lane = t & 31;
    const int wid  = t >> 5;
    const int wm   = (wid >> 2) * 64;
    const int wn   = (wid & 3) * 32;
    const int m0   = blockIdx.x * 128;
    const int n0   = blockIdx.y * 128;
    const int Kp   = K >> 1;                 // u32 per row

    // loader: tile = t>>6 (0:Ah 1:Al 2:Bh 3:Bl), u = t&63 -> rows 2u, 2u+1
    const int tile = t >> 6, u = t & 63;
    const uint32_t* src = (tile == 0) ? Ahp : (tile == 1) ? Alp : (tile == 2) ? Bhp : Blp;
    const int grow = ((tile < 2) ? m0 : n0) + 2 * u;
    const uint32_t* g0 = src + (size_t)grow * Kp;
    const uint32_t* g1 = g0 + Kp;
    const uint32_t dstr = (uint32_t)(tile * DTILE + (2 * u) * DSTRIDE);

    float acc[4][4][4];
#pragma unroll
    for (int i = 0; i < 4; i++)
#pragma unroll
        for (int j = 0; j < 4; j++)
#pragma unroll
            for (int r = 0; r < 4; r++) acc[i][j][r] = 0.f;

    const int nslab = K >> 5;
    uint4 pf[8];
#pragma unroll
    for (int c = 0; c < 4; c++) {
        pf[c]     = ((const uint4*)g0)[c];
        pf[4 + c] = ((const uint4*)g1)[c];
    }

    const uint32_t a_lane = (uint32_t)((wm + (lane & 7) + ((lane >> 3) & 1) * 8) * DSTRIDE
                                       + (lane >> 4) * 16);
    const uint32_t b_lane = (uint32_t)((wn + (lane & 7)) * DSTRIDE
                                       + ((lane >> 3) & 1) * 16);

    for (int s = 0; s < nslab; s++) {
        const uint32_t buf = sb + (uint32_t)(s & 1) * DBUF;
        const uint32_t da  = buf + dstr;
#pragma unroll
        for (int c = 0; c < 4; c++) {
            sts128(da + c * 16,           pf[c]);
            sts128(da + DSTRIDE + c * 16, pf[4 + c]);
        }
        if (s + 1 < nslab) {
            const uint4* n0p = (const uint4*)(g0 + (s + 1) * 16);
            const uint4* n1p = (const uint4*)(g1 + (s + 1) * 16);
#pragma unroll
            for (int c = 0; c < 4; c++) { pf[c] = n0p[c]; pf[4 + c] = n1p[c]; }
        }
        __syncthreads();

        const uint32_t Ath = buf;
        const uint32_t Atl = buf + DTILE;
        const uint32_t Bth = buf + 2 * DTILE;
        const uint32_t Btl = buf + 3 * DTILE;
#pragma unroll
        for (int ks = 0; ks < 2; ks++) {
            uint32_t ah[4][4], al[4][4], bh[4][2], bl[4][2];
#pragma unroll
            for (int mt = 0; mt < 4; mt++) {
                const uint32_t off = a_lane + (uint32_t)(mt * 16 * DSTRIDE + ks * 32);
                ldmx4(ah[mt], Ath + off);
                ldmx4(al[mt], Atl + off);
            }
#pragma unroll
            for (int nt = 0; nt < 4; nt++) {
                const uint32_t off = b_lane + (uint32_t)(nt * 8 * DSTRIDE + ks * 32);
                ldmx2(bh[nt], Bth + off);
                ldmx2(bl[nt], Btl + off);
            }
            // 3 split terms as separate passes -> 16 independent acc chains each
#pragma unroll
            for (int mt = 0; mt < 4; mt++)
#pragma unroll
                for (int nt = 0; nt < 4; nt++)
                    mma16816(acc[mt][nt], ah[mt], bh[nt]);     // A1*B1
#pragma unroll
            for (int mt = 0; mt < 4; mt++)
#pragma unroll
                for (int nt = 0; nt < 4; nt++)
                    mma16816(acc[mt][nt], ah[mt], bl[nt]);     // A1*B2
#pragma unroll
            for (int mt = 0; mt < 4; mt++)
#pragma unroll
                for (int nt = 0; nt < 4; nt++)
                    mma16816(acc[mt][nt], al[mt], bh[nt]);     // A2*B1
        }
        // no trailing barrier needed: next iteration's STS targets the other
        // buffer, and its barrier orders buffer reuse two slabs out.
    }

#pragma unroll
    for (int mt = 0; mt < 4; mt++) {
        const int mr = m0 + wm + mt * 16 + (lane >> 2);
#pragma unroll
        for (int nt = 0; nt < 4; nt++) {
            const int nc = n0 + wn + nt * 8 + (lane & 3) * 2;
            const float b0 = bias[nc], b1 = bias[nc + 1];
            float v0 = __fadd_rn(acc[mt][nt][0], b0);
            float v1 = __fadd_rn(acc[mt][nt][1], b1);
            float v2 = __fadd_rn(acc[mt][nt][2], b0);
            float v3 = __fadd_rn(acc[mt][nt][3], b1);
            if (TANH) { v0 = xla_tanh(v0); v1 = xla_tanh(v1); v2 = xla_tanh(v2); v3 = xla_tanh(v3); }
            if (OUTMODE == 0) {
                float* r0 = &C[(size_t)mr * N + nc];
                float* r1 = &C[(size_t)(mr + 8) * N + nc];
                r0[0] = v0; r0[1] = v1;
                r1[0] = v2; r1[1] = v3;
            } else {
                uint32_t hi, lo;
                const size_t i0 = (size_t)mr * (N >> 1) + (nc >> 1);
                const size_t i1 = (size_t)(mr + 8) * (N >> 1) + (nc >> 1);
                split2(v0, v1, hi, lo); Chp[i0] = hi; Clp[i0] = lo;
                split2(v2, v3, hi, lo); Chp[i1] = hi; Clp[i1] = lo;
            }
        }
    }
}

// ======================= VQ / misc kernels =======================
__global__ void ee_kernel(const float* __restrict__ E)
{
    const int row  = blockIdx.x * 8 + (threadIdx.x >> 5);
    const int lane = threadIdx.x & 31;
    const float* e = E + (size_t)row * D2;
    float s = 0.f;
    for (int j = lane; j < D2; j += 32)
        s = __fadd_rn(s, __fmul_rn(e[j], e[j]));
#pragma unroll
    for (int o = 16; o; o >>= 1) s = __fadd_rn(s, __shfl_xor_sync(0xffffffffu, s, o));
    if (lane == 0) g_ee[row] = s;
}

__global__ void zz_kernel()
{
    const int m = blockIdx.x * 256 + threadIdx.x;
    if (m >= B_SZ) return;
    const float* z = g_z + (size_t)m * D2;
    float s = 0.f;
    for (int k = 0; k < D2; k++)
        s = __fadd_rn(s, __fmul_rn(z[k], z[k]));
    g_zz[m] = s;
}

__global__ void init_best()
{
    int i = blockIdx.x * 256 + threadIdx.x;
    if (i < B_SZ) g_best[i] = ~0ull;
}

__device__ __forceinline__ unsigned int orderable_f32(float f)
{
    unsigned int u = __float_as_uint(f);
    return (u & 0x80000000u) ? ~u : (u | 0x80000000u);
}

__global__ __launch_bounds__(256, 2)
void vq_score(const float* __restrict__ Z, const float* __restrict__ E)
{
    __shared__ float As[2][16][128];
    __shared__ float Bs[2][16][128];
    const int t  = threadIdx.x;
    const int tx = t & 15, ty = t >> 4;
    const int m0 = blockIdx.y * 128, n0 = blockIdx.x * 128;
    const int lr = t >> 1;
    const int lc = (t & 1) * 4;
    const float* Aptr = Z + (size_t)(m0 + lr) * D2 + lc;
    const float* Wptr = E + (size_t)(n0 + lr) * D2 + lc;

    unsigned long long acc[8][4];
#pragma unroll
    for (int i = 0; i < 8; i++)
#pragma unroll
        for (int p = 0; p < 4; p++) acc[i][p] = 0ull;

    {
        float4 a0 = *(const float4*)(Aptr);
        float4 a1 = *(const float4*)(Aptr + 8);
        float4 w0 = *(const float4*)(Wptr);
        float4 w1 = *(const float4*)(Wptr + 8);
        sts_tile(As[0], Bs[0], lr, lc, a0, a1, w0, w1);
    }
    __syncthreads();

    int cur = 0;
    for (int k0 = 16; k0 < D2; k0 += 16) {
        float4 a0 = *(const float4*)(Aptr + k0);
        float4 a1 = *(const float4*)(Aptr + k0 + 8);
        float4 w0 = *(const float4*)(Wptr + k0);
        float4 w1 = *(const float4*)(Wptr + k0 + 8);
        tile_fma16p(As[cur], Bs[cur], acc, tx, ty);
        sts_tile(As[cur ^ 1], Bs[cur ^ 1], lr, lc, a0, a1, w0, w1);
        __syncthreads();
        cur ^= 1;
    }
    tile_fma16p(As[cur], Bs[cur], acc, tx, ty);

#pragma unroll
    for (int i = 0; i < 8; i++) {
        const int m = m0 + ty * 8 + i;
        const float zzm = g_zz[m];
        unsigned long long best = ~0ull;
#pragma unroll
        for (int p = 0; p < 4; p++) {
            float2 pr = unpack2(acc[i][p]);
#pragma unroll
            for (int h = 0; h < 2; h++) {
                const int j = 2 * p + h;
                const int n = n0 + col_of(tx, j);
                const float s    = h ? pr.y : pr.x;
                const float zze  = __fadd_rn(zzm, g_ee[n]);
                const float twos = __fmul_rn(2.f, s);
                const float d    = __fadd_rn(zze, -twos);
                unsigned long long key =
                    ((unsigned long long)orderable_f32(d) << 32) | (unsigned int)n;
                best = (key < best) ? key : best;
            }
        }
#pragma unroll
        for (int o = 8; o; o >>= 1) {
            unsigned long long other = __shfl_xor_sync(0xffffffffu, best, o);
            best = (other < best) ? other : best;
        }
        if (tx == 0) atomicMin(&g_best[m], best);
    }
}

// gather q = E[idx]: emit q_st fp32 output + packed bf16 splits + loss partials
__global__ void gather_loss(const float* __restrict__ E, float* __restrict__ out_q)
{
    const int m   = blockIdx.x;
    const int idx = (int)(unsigned int)(g_best[m] & 0xFFFFFFFFull);
    const float* e = E + (size_t)idx * D2;
    const float* z = g_z + (size_t)m * D2;
    const int j = threadIdx.x * 2;                 // 256 threads x 2 = 512
    float q0 = e[j], q1 = e[j + 1];
    float d0 = q0 - z[j], d1 = q1 - z[j + 1];
    float s = fmaf(d1, d1, d0 * d0);
    uint32_t hi, lo;
    split2(q0, q1, hi, lo);
    const size_t pi = ((size_t)m * D2 + j) >> 1;
    g_qh[pi] = hi; g_ql[pi] = lo;
    if (out_q) { out_q[(size_t)m * D2 + j] = q0; out_q[(size_t)m * D2 + j + 1] = q1; }

    __shared__ float red[256];
    red[threadIdx.x] = s;
    __syncthreads();
    for (int o = 128; o; o >>= 1) {
        if (threadIdx.x < o) red[threadIdx.x] += red[threadIdx.x + o];
        __syncthreads();
    }
    if (threadIdx.x == 0) g_rowsum[m] = red[0];
}

__global__ void reduce_loss(float* __restrict__ out_loss)
{
    __shared__ float red[1024];
    float s = 0.f;
    for (int i = threadIdx.x; i < B_SZ; i += 1024) s += g_rowsum[i];
    red[threadIdx.x] = s;
    __syncthreads();
    for (int o = 512; o; o >>= 1) {
        if (threadIdx.x < o) red[threadIdx.x] += red[threadIdx.x + o];
        __syncthreads();
    }
    if (threadIdx.x == 0)
        out_loss[0] = red[0] * (1.25f / (float)((size_t)B_SZ * D2));
}

// ----------------------------------------------------------------
extern "C" void kernel_launch(void* const* d_in, const int* in_sizes, int n_in,
                              void* d_out, int out_size)
{
    const float* X  = (const float*)d_in[0];
    const float* W1 = (const float*)d_in[1];
    const float* b1 = (const float*)d_in[2];
    const float* W2 = (const float*)d_in[3];
    const float* b2 = (const float*)d_in[4];
    const float* W3 = (const float*)d_in[5];
    const float* b3 = (const float*)d_in[6];
    const float* E  = (const float*)d_in[7];
    const float* W4 = (const float*)d_in[8];
    const float* b4 = (const float*)d_in[9];
    const float* W5 = (const float*)d_in[10];
    const float* b5 = (const float*)d_in[11];
    const float* W6 = (const float*)d_in[12];
    const float* b6 = (const float*)d_in[13];

    float *h1, *h2, *z;
    cudaGetSymbolAddress((void**)&h1, g_h1);
    cudaGetSymbolAddress((void**)&h2, g_h2);
    cudaGetSymbolAddress((void**)&z,  g_z);
    uint32_t *w4h, *w4l, *w5h, *w5l, *w6h, *w6l, *qh, *ql, *h2h, *h2l, *h1h, *h1l;
    cudaGetSymbolAddress((void**)&w4h, g_w4h); cudaGetSymbolAddress((void**)&w4l, g_w4l);
    cudaGetSymbolAddress((void**)&w5h, g_w5h); cudaGetSymbolAddress((void**)&w5l, g_w5l);
    cudaGetSymbolAddress((void**)&w6h, g_w6h); cudaGetSymbolAddress((void**)&w6l, g_w6l);
    cudaGetSymbolAddress((void**)&qh,  g_qh);  cudaGetSymbolAddress((void**)&ql,  g_ql);
    cudaGetSymbolAddress((void**)&h2h, g_h2h); cudaGetSymbolAddress((void**)&h2l, g_h2l);
    cudaGetSymbolAddress((void**)&h1h, g_h1h); cudaGetSymbolAddress((void**)&h1l, g_h1l);

    float* out = (float*)d_out;
    const long long full = 1LL + (long long)B_SZ * G_NUM + (long long)B_SZ * D2;
    float* out_loss = nullptr;
    float* out_x    = out;
    float* out_q    = nullptr;
    if ((long long)out_size == full) {
        out_loss = out;
        out_x    = out + 1;
        out_q    = out + 1 + (long long)B_SZ * G_NUM;
    }

    cudaFuncSetAttribute((const void*)gemm_mma2<0, false>,
                         cudaFuncAttributeMaxDynamicSharedMemorySize, DSMEM);
    cudaFuncSetAttribute((const void*)gemm_mma2<1, true>,
                         cudaFuncAttributeMaxDynamicSharedMemorySize, DSMEM);

    const dim3 blk(256);

    // weight splits (independent of encoder)
    split_pairs<<<(D1 * D2 / 4 + 255) / 256, 256>>>(W4, w4h, w4l, D1 * D2 / 4);
    split_pairs<<<(D0 * D1 / 4 + 255) / 256, 256>>>(W5, w5h, w5l, D0 * D1 / 4);
    split_pairs<<<(G_NUM / 4 * D0 + 255) / 256, 256>>>(W6, w6h, w6l, G_NUM / 4 * D0);

    ee_kernel<<<KEMB / 8, 256>>>(E);
    init_best<<<B_SZ / 256, 256>>>();

    // encoder (bit-exact fp32 chains via packed FFMA2)
    gemm_bias_act<true><<<dim3(D0 / 128, B_SZ / 128), blk>>>(X,  W1, b1, h1, B_SZ, D0, G_NUM);
    gemm_bias_act<true><<<dim3(D1 / 128, B_SZ / 128), blk>>>(h1, W2, b2, h2, B_SZ, D1, D0);
    gemm_bias_act<true><<<dim3(D2 / 128, B_SZ / 128), blk>>>(h2, W3, b3, z,  B_SZ, D2, D1);

    // VQ (bit-exact replication of reference dist formula)
    zz_kernel<<<B_SZ / 256, 256>>>();
    vq_score<<<dim3(KEMB / 128, B_SZ / 128), blk>>>(z, E);
    gather_loss<<<B_SZ, 256>>>(E, out_q);
    if (out_loss) reduce_loss<<<1, 1024>>>(out_loss);

    // decoder: HMMA bf16 3-term split, pre-split operands
    gemm_mma2<1, true ><<<dim3(B_SZ / 128, D1 / 128),    blk, DSMEM>>>(
        qh, ql, w4h, w4l, b4, nullptr, h2h, h2l, D1, D2);
    gemm_mma2<1, true ><<<dim3(B_SZ / 128, D0 / 128),    blk, DSMEM>>>(
        h2h, h2l, w5h, w5l, b5, nullptr, h1h, h1l, D0, D1);
    gemm_mma2<0, false><<<dim3(B_SZ / 128, G_NUM / 128), blk, DSMEM>>>(
        h1h, h1l, w6h, w6l, b6, out_x, nullptr, nullptr, G_NUM, D0);
}

// round 10
// speedup vs baseline: 1.8780x; 1.2152x over previous
#include <cuda_runtime.h>
#include <cuda_bf16.h>
#include <cstdint>

#define B_SZ 4096
#define G_NUM 16384
#define D0 4096
#define D1 2048
#define D2 512
#define KEMB 8192

// -------- scratch (static device memory; no allocations) --------
__device__ float g_h1[(size_t)B_SZ * D0];        // encoder h1 (fp32)
__device__ float g_h2[(size_t)B_SZ * D1];        // encoder h2 (fp32)
__device__ float g_z [(size_t)B_SZ * D2];
__device__ float g_ee[KEMB];
__device__ float g_zz[B_SZ];
__device__ unsigned long long g_best[B_SZ];
__device__ float g_rowsum[B_SZ];

// packed pairs (u32 = 2 consecutive elements)
__device__ uint32_t g_w4h[(size_t)D1 * D2 / 2],    g_w4l[(size_t)D1 * D2 / 2];    // bf16
__device__ uint32_t g_w5h[(size_t)D0 * D1 / 2],    g_w5l[(size_t)D0 * D1 / 2];    // bf16
__device__ uint32_t g_w6h[(size_t)G_NUM * D0 / 2];                                 // fp16
__device__ uint32_t g_qh [(size_t)B_SZ * D2 / 2],  g_ql [(size_t)B_SZ * D2 / 2];  // bf16
__device__ uint32_t g_h2h[(size_t)B_SZ * D1 / 2],  g_h2l[(size_t)B_SZ * D1 / 2];  // bf16
__device__ uint32_t g_h1h[(size_t)B_SZ * D0 / 2];                                  // fp16

// ---------------- XLA/Eigen tanh f32 rational approximation ----------------
__device__ __forceinline__ float xla_tanh(float x)
{
    if (fabsf(x) < 0.0004f) return x;
    float xc = fminf(fmaxf(x, -7.90531110763549805f), 7.90531110763549805f);
    float x2 = __fmul_rn(xc, xc);
    float p = fmaf(x2, -2.76076847742355e-16f, 2.00018790482477e-13f);
    p = fmaf(x2, p, -8.60467152213735e-11f);
    p = fmaf(x2, p,  5.12229709037114e-08f);
    p = fmaf(x2, p,  1.48572235717979e-05f);
    p = fmaf(x2, p,  6.37261928875436e-04f);
    p = fmaf(x2, p,  4.89352455891786e-03f);
    p = __fmul_rn(xc, p);
    float q = fmaf(x2, 1.19825839466702e-06f, 1.18534705686654e-04f);
    q = fmaf(x2, q, 2.26843463243900e-03f);
    q = fmaf(x2, q, 4.89352518554385e-03f);
    return __fdiv_rn(p, q);
}

// ---------------- packed fp32x2 helpers ----------------
__device__ __forceinline__ void ffma2(unsigned long long& d,
                                      unsigned long long a, unsigned long long b)
{
    asm("fma.rn.f32x2 %0, %1, %2, %0;" : "+l"(d) : "l"(a), "l"(b));
}
__device__ __forceinline__ unsigned long long dup2(float a)
{
    unsigned long long r;
    asm("mov.b64 %0, {%1, %1};" : "=l"(r) : "f"(a));
    return r;
}
__device__ __forceinline__ float2 unpack2(unsigned long long v)
{
    float lo, hi;
    asm("mov.b64 {%0, %1}, %2;" : "=f"(lo), "=f"(hi) : "l"(v));
    return make_float2(lo, hi);
}

// ======================= SIMT exact-chain GEMM (encoder) =======================
__device__ __forceinline__ void sts_tile(float (&As)[16][128], float (&Bs)[16][128],
                                         int lr, int lc,
                                         float4 a0, float4 a1, float4 w0, float4 w1)
{
    As[lc + 0][lr] = a0.x; As[lc + 1][lr] = a0.y;
    As[lc + 2][lr] = a0.z; As[lc + 3][lr] = a0.w;
    As[lc + 8][lr] = a1.x; As[lc + 9][lr] = a1.y;
    As[lc +10][lr] = a1.z; As[lc +11][lr] = a1.w;
    Bs[lc + 0][lr] = w0.x; Bs[lc + 1][lr] = w0.y;
    Bs[lc + 2][lr] = w0.z; Bs[lc + 3][lr] = w0.w;
    Bs[lc + 8][lr] = w1.x; Bs[lc + 9][lr] = w1.y;
    Bs[lc +10][lr] = w1.z; Bs[lc +11][lr] = w1.w;
}

// packed-f32x2 inner product tile; each acc lane keeps its own ascending-k
// IEEE-RN FMA chain (bit-identical to scalar fmaf version).
__device__ __forceinline__ void tile_fma16p(const float (&As)[16][128],
                                            const float (&Bs)[16][128],
                                            unsigned long long (&acc)[8][4],
                                            int tx, int ty)
{
#pragma unroll
    for (int kk = 0; kk < 16; kk++) {
        float4 a0 = *(const float4*)&As[kk][ty * 8];
        float4 a1 = *(const float4*)&As[kk][ty * 8 + 4];
        ulonglong2 b01 = *(const ulonglong2*)&Bs[kk][tx * 4];
        ulonglong2 b23 = *(const ulonglong2*)&Bs[kk][64 + tx * 4];
        unsigned long long bb[4] = {b01.x, b01.y, b23.x, b23.y};
        float a[8] = {a0.x, a0.y, a0.z, a0.w, a1.x, a1.y, a1.z, a1.w};
#pragma unroll
        for (int i = 0; i < 8; i++) {
            unsigned long long ai = dup2(a[i]);
#pragma unroll
            for (int p = 0; p < 4; p++) ffma2(acc[i][p], ai, bb[p]);
        }
    }
}

__device__ __forceinline__ int col_of(int tx, int j)
{
    return (j < 4) ? (tx * 4 + j) : (64 + tx * 4 + (j - 4));
}

template<bool TANH>
__global__ __launch_bounds__(256, 2)
void gemm_bias_act(const float* __restrict__ A, const float* __restrict__ W,
                   const float* __restrict__ bias, float* __restrict__ C,
                   int M, int N, int K)
{
    __shared__ float As[2][16][128];
    __shared__ float Bs[2][16][128];
    const int t  = threadIdx.x;
    const int tx = t & 15, ty = t >> 4;
    const int m0 = blockIdx.y * 128, n0 = blockIdx.x * 128;
    const int lr = t >> 1;
    const int lc = (t & 1) * 4;
    const float* Aptr = A + (size_t)(m0 + lr) * K + lc;
    const float* Wptr = W + (size_t)(n0 + lr) * K + lc;

    unsigned long long acc[8][4];
#pragma unroll
    for (int i = 0; i < 8; i++)
#pragma unroll
        for (int p = 0; p < 4; p++) acc[i][p] = 0ull;

    {
        float4 a0 = *(const float4*)(Aptr);
        float4 a1 = *(const float4*)(Aptr + 8);
        float4 w0 = *(const float4*)(Wptr);
        float4 w1 = *(const float4*)(Wptr + 8);
        sts_tile(As[0], Bs[0], lr, lc, a0, a1, w0, w1);
    }
    __syncthreads();

    int cur = 0;
    for (int k0 = 16; k0 < K; k0 += 16) {
        float4 a0 = *(const float4*)(Aptr + k0);
        float4 a1 = *(const float4*)(Aptr + k0 + 8);
        float4 w0 = *(const float4*)(Wptr + k0);
        float4 w1 = *(const float4*)(Wptr + k0 + 8);
        tile_fma16p(As[cur], Bs[cur], acc, tx, ty);
        sts_tile(As[cur ^ 1], Bs[cur ^ 1], lr, lc, a0, a1, w0, w1);
        __syncthreads();
        cur ^= 1;
    }
    tile_fma16p(As[cur], Bs[cur], acc, tx, ty);

#pragma unroll
    for (int i = 0; i < 8; i++) {
        const int m = m0 + ty * 8 + i;
#pragma unroll
        for (int p = 0; p < 4; p++) {
            float2 pr = unpack2(acc[i][p]);
#pragma unroll
            for (int h = 0; h < 2; h++) {
                const int j = 2 * p + h;
                const int n = n0 + col_of(tx, j);
                float v = __fadd_rn(h ? pr.y : pr.x, bias[n]);
                if (TANH) v = xla_tanh(v);
                C[(size_t)m * N + n] = v;
            }
        }
    }
}

// ======================= conversion helpers =======================
// split fp32 pair -> bf16x2 hi + bf16x2 residual (packed u32 each)
__device__ __forceinline__ void split2(float f0, float f1, uint32_t& hi, uint32_t& lo)
{
    asm("cvt.rn.bf16x2.f32 %0, %1, %2;" : "=r"(hi) : "f"(f1), "f"(f0));
    float h0 = __uint_as_float(hi << 16);
    float h1 = __uint_as_float(hi & 0xFFFF0000u);
    float r0 = __fadd_rn(f0, -h0);
    float r1 = __fadd_rn(f1, -h1);
    asm("cvt.rn.bf16x2.f32 %0, %1, %2;" : "=r"(lo) : "f"(r1), "f"(r0));
}

__device__ __forceinline__ uint32_t cvt_h2(float f0, float f1)
{
    uint32_t r;
    asm("cvt.rn.f16x2.f32 %0, %1, %2;" : "=r"(r) : "f"(f1), "f"(f0));
    return r;
}

// elementwise weight split: W fp32 -> packed bf16 hi/lo pair arrays
__global__ void split_pairs(const float* __restrict__ W, uint32_t* __restrict__ Wh,
                            uint32_t* __restrict__ Wl, int n4)
{
    int i = blockIdx.x * 256 + threadIdx.x;
    if (i >= n4) return;
    float4 v = ((const float4*)W)[i];
    uint32_t h0, l0, h1, l1;
    split2(v.x, v.y, h0, l0);
    split2(v.z, v.w, h1, l1);
    ((uint2*)Wh)[i] = make_uint2(h0, h1);
    ((uint2*)Wl)[i] = make_uint2(l0, l1);
}

// elementwise fp16 quantization (no residual): W fp32 -> packed f16 pairs
__global__ void quant_h16(const float* __restrict__ W, uint32_t* __restrict__ Wh, int n4)
{
    int i = blockIdx.x * 256 + threadIdx.x;
    if (i >= n4) return;
    float4 v = ((const float4*)W)[i];
    ((uint2*)Wh)[i] = make_uint2(cvt_h2(v.x, v.y), cvt_h2(v.z, v.w));
}

// ======================= HMMA decoder GEMMs =======================
__device__ __forceinline__ uint32_t smem_u32(const void* p)
{
    uint32_t a;
    asm("{ .reg .u64 t; cvta.to.shared.u64 t, %1; cvt.u32.u64 %0, t; }"
        : "=r"(a) : "l"(p));
    return a;
}

__device__ __forceinline__ void mma_bf16(float* c, const uint32_t* a, const uint32_t* b)
{
    asm volatile(
        "mma.sync.aligned.m16n8k16.row.col.f32.bf16.bf16.f32 "
        "{%0,%1,%2,%3}, {%4,%5,%6,%7}, {%8,%9}, {%0,%1,%2,%3};"
        : "+f"(c[0]), "+f"(c[1]), "+f"(c[2]), "+f"(c[3])
        : "r"(a[0]), "r"(a[1]), "r"(a[2]), "r"(a[3]), "r"(b[0]), "r"(b[1]));
}

__device__ __forceinline__ void mma_f16(float* c, const uint32_t* a, const uint32_t* b)
{
    asm volatile(
        "mma.sync.aligned.m16n8k16.row.col.f32.f16.f16.f32 "
        "{%0,%1,%2,%3}, {%4,%5,%6,%7}, {%8,%9}, {%0,%1,%2,%3};"
        : "+f"(c[0]), "+f"(c[1]), "+f"(c[2]), "+f"(c[3])
        : "r"(a[0]), "r"(a[1]), "r"(a[2]), "r"(a[3]), "r"(b[0]), "r"(b[1]));
}

__device__ __forceinline__ void ldmx4(uint32_t* r, uint32_t a)
{
    asm volatile("ldmatrix.sync.aligned.m8n8.x4.shared.b16 {%0,%1,%2,%3}, [%4];"
                 : "=r"(r[0]), "=r"(r[1]), "=r"(r[2]), "=r"(r[3]) : "r"(a));
}
__device__ __forceinline__ void ldmx2(uint32_t* r, uint32_t a)
{
    asm volatile("ldmatrix.sync.aligned.m8n8.x2.shared.b16 {%0,%1}, [%2];"
                 : "=r"(r[0]), "=r"(r[1]) : "r"(a));
}
__device__ __forceinline__ void sts128(uint32_t a, uint4 v)
{
    asm volatile("st.shared.v4.u32 [%0], {%1,%2,%3,%4};"
                 :: "r"(a), "r"(v.x), "r"(v.y), "r"(v.z), "r"(v.w));
}

// ---- bf16 3-term split GEMM (W4, W5) ----
// smem: 4 tiles (Ah, Al, Bh, Bl), 128 rows x 32 bf16 (64B) padded to 80B stride
#define DSTRIDE 80
#define DTILE  (128 * DSTRIDE)   // 10240
#define DBUF   (4 * DTILE)       // 40960
#define DSMEM  (2 * DBUF)        // 81920

// OUTMODE 1: bf16 split out (Chp/Clp). OUTMODE 2: fp16 packed out (Chp only).
template<int OUTMODE, bool TANH>
__global__ __launch_bounds__(256, 1)
void gemm_mma2(const uint32_t* __restrict__ Ahp, const uint32_t* __restrict__ Alp,
               const uint32_t* __restrict__ Bhp, const uint32_t* __restrict__ Blp,
               const float* __restrict__ bias,
               uint32_t* __restrict__ Chp, uint32_t* __restrict__ Clp,
               int N, int K)
{
    extern __shared__ char sm[];
    const uint32_t sb = smem_u32(sm);
    const int t    = threadIdx.x;
    const int lane = t & 31;
    const int wid  = t >> 5;
    const int wm   = (wid >> 2) * 64;
    const int wn   = (wid & 3) * 32;
    const int m0   = blockIdx.x * 128;
    const int n0   = blockIdx.y * 128;
    const int Kp   = K >> 1;

    const int tile = t >> 6, u = t & 63;
    const uint32_t* src = (tile == 0) ? Ahp : (tile == 1) ? Alp : (tile == 2) ? Bhp : Blp;
    const int grow = ((tile < 2) ? m0 : n0) + 2 * u;
    const uint32_t* g0 = src + (size_t)grow * Kp;
    const uint32_t* g1 = g0 + Kp;
    const uint32_t dstr = (uint32_t)(tile * DTILE + (2 * u) * DSTRIDE);

    float acc[4][4][4];
#pragma unroll
    for (int i = 0; i < 4; i++)
#pragma unroll
        for (int j = 0; j < 4; j++)
#pragma unroll
            for (int r = 0; r < 4; r++) acc[i][j][r] = 0.f;

    const int nslab = K >> 5;
    uint4 pf[8];
#pragma unroll
    for (int c = 0; c < 4; c++) {
        pf[c]     = ((const uint4*)g0)[c];
        pf[4 + c] = ((const uint4*)g1)[c];
    }

    const uint32_t a_lane = (uint32_t)((wm + (lane & 7) + ((lane >> 3) & 1) * 8) * DSTRIDE
                                       + (lane >> 4) * 16);
    const uint32_t b_lane = (uint32_t)((wn + (lane & 7)) * DSTRIDE
                                       + ((lane >> 3) & 1) * 16);

    for (int s = 0; s < nslab; s++) {
        const uint32_t buf = sb + (uint32_t)(s & 1) * DBUF;
        const uint32_t da  = buf + dstr;
#pragma unroll
        for (int c = 0; c < 4; c++) {
            sts128(da + c * 16,           pf[c]);
            sts128(da + DSTRIDE + c * 16, pf[4 + c]);
        }
        if (s + 1 < nslab) {
            const uint4* n0p = (const uint4*)(g0 + (s + 1) * 16);
            const uint4* n1p = (const uint4*)(g1 + (s + 1) * 16);
#pragma unroll
            for (int c = 0; c < 4; c++) { pf[c] = n0p[c]; pf[4 + c] = n1p[c]; }
        }
        __syncthreads();

        const uint32_t Ath = buf;
        const uint32_t Atl = buf + DTILE;
        const uint32_t Bth = buf + 2 * DTILE;
        const uint32_t Btl = buf + 3 * DTILE;
#pragma unroll
        for (int ks = 0; ks < 2; ks++) {
            uint32_t ah[4][4], al[4][4], bh[4][2], bl[4][2];
#pragma unroll
            for (int mt = 0; mt < 4; mt++) {
                const uint32_t off = a_lane + (uint32_t)(mt * 16 * DSTRIDE + ks * 32);
                ldmx4(ah[mt], Ath + off);
                ldmx4(al[mt], Atl + off);
            }
#pragma unroll
            for (int nt = 0; nt < 4; nt++) {
                const uint32_t off = b_lane + (uint32_t)(nt * 8 * DSTRIDE + ks * 32);
                ldmx2(bh[nt], Bth + off);
                ldmx2(bl[nt], Btl + off);
            }
#pragma unroll
            for (int mt = 0; mt < 4; mt++)
#pragma unroll
                for (int nt = 0; nt < 4; nt++)
                    mma_bf16(acc[mt][nt], ah[mt], bh[nt]);     // A1*B1
#pragma unroll
            for (int mt = 0; mt < 4; mt++)
#pragma unroll
                for (int nt = 0; nt < 4; nt++)
                    mma_bf16(acc[mt][nt], ah[mt], bl[nt]);     // A1*B2
#pragma unroll
            for (int mt = 0; mt < 4; mt++)
#pragma unroll
                for (int nt = 0; nt < 4; nt++)
                    mma_bf16(acc[mt][nt], al[mt], bh[nt]);     // A2*B1
        }
    }

#pragma unroll
    for (int mt = 0; mt < 4; mt++) {
        const int mr = m0 + wm + mt * 16 + (lane >> 2);
#pragma unroll
        for (int nt = 0; nt < 4; nt++) {
            const int nc = n0 + wn + nt * 8 + (lane & 3) * 2;
            const float b0 = bias[nc], b1 = bias[nc + 1];
            float v0 = __fadd_rn(acc[mt][nt][0], b0);
            float v1 = __fadd_rn(acc[mt][nt][1], b1);
            float v2 = __fadd_rn(acc[mt][nt][2], b0);
            float v3 = __fadd_rn(acc[mt][nt][3], b1);
            if (TANH) { v0 = xla_tanh(v0); v1 = xla_tanh(v1); v2 = xla_tanh(v2); v3 = xla_tanh(v3); }
            const size_t i0 = (size_t)mr * (N >> 1) + (nc >> 1);
            const size_t i1 = (size_t)(mr + 8) * (N >> 1) + (nc >> 1);
            if (OUTMODE == 1) {
                uint32_t hi, lo;
                split2(v0, v1, hi, lo); Chp[i0] = hi; Clp[i0] = lo;
                split2(v2, v3, hi, lo); Chp[i1] = hi; Clp[i1] = lo;
            } else {
                Chp[i0] = cvt_h2(v0, v1);
                Chp[i1] = cvt_h2(v2, v3);
            }
        }
    }
}

// ---- fp16 single-term GEMM (W6: final, tolerance-bound output) ----
#define HSTRIDE 80
#define HTILE  (128 * HSTRIDE)   // 10240
#define HBUF   (2 * HTILE)       // 20480 (A + B)
#define HSMEM  (2 * HBUF)        // 40960

__global__ __launch_bounds__(256, 1)
void gemm_h16(const uint32_t* __restrict__ Ah, const uint32_t* __restrict__ Bh,
              const float* __restrict__ bias, float* __restrict__ C, int N, int K)
{
    extern __shared__ char sm[];
    const uint32_t sb = smem_u32(sm);
    const int t    = threadIdx.x;
    const int lane = t & 31;
    const int wid  = t >> 5;
    const int wm   = (wid >> 2) * 64;
    const int wn   = (wid & 3) * 32;
    const int m0   = blockIdx.x * 128;
    const int n0   = blockIdx.y * 128;
    const int Kp   = K >> 1;

    const int tile = t >> 7, u = t & 127;
    const uint32_t* g = tile ? (Bh + (size_t)(n0 + u) * Kp)
                             : (Ah + (size_t)(m0 + u) * Kp);
    const uint32_t dstr = (uint32_t)(tile * HTILE + u * HSTRIDE);

    float acc[4][4][4];
#pragma unroll
    for (int i = 0; i < 4; i++)
#pragma unroll
        for (int j = 0; j < 4; j++)
#pragma unroll
            for (int r = 0; r < 4; r++) acc[i][j][r] = 0.f;

    const int nslab = K >> 5;
    uint4 pf[4];
#pragma unroll
    for (int c = 0; c < 4; c++) pf[c] = ((const uint4*)g)[c];

    const uint32_t a_lane = (uint32_t)((wm + (lane & 7) + ((lane >> 3) & 1) * 8) * HSTRIDE
                                       + (lane >> 4) * 16);
    const uint32_t b_lane = (uint32_t)((wn + (lane & 7)) * HSTRIDE
                                       + ((lane >> 3) & 1) * 16);

    for (int s = 0; s < nslab; s++) {
        const uint32_t buf = sb + (uint32_t)(s & 1) * HBUF;
        const uint32_t da  = buf + dstr;
#pragma unroll
        for (int c = 0; c < 4; c++) sts128(da + c * 16, pf[c]);
        if (s + 1 < nslab) {
            const uint4* np = (const uint4*)(g + (s + 1) * 16);
#pragma unroll
            for (int c = 0; c < 4; c++) pf[c] = np[c];
        }
        __syncthreads();

        const uint32_t Ath = buf;
        const uint32_t Bth = buf + HTILE;
#pragma unroll
        for (int ks = 0; ks < 2; ks++) {
            uint32_t ah[4][4], bh[4][2];
#pragma unroll
            for (int mt = 0; mt < 4; mt++)
                ldmx4(ah[mt], Ath + a_lane + (uint32_t)(mt * 16 * HSTRIDE + ks * 32));
#pragma unroll
            for (int nt = 0; nt < 4; nt++)
                ldmx2(bh[nt], Bth + b_lane + (uint32_t)(nt * 8 * HSTRIDE + ks * 32));
#pragma unroll
            for (int mt = 0; mt < 4; mt++)
#pragma unroll
                for (int nt = 0; nt < 4; nt++)
                    mma_f16(acc[mt][nt], ah[mt], bh[nt]);
        }
    }

    // scalar stores: C (x_recon at d_out+1) may be only 4B-aligned
#pragma unroll
    for (int mt = 0; mt < 4; mt++) {
        const int mr = m0 + wm + mt * 16 + (lane >> 2);
#pragma unroll
        for (int nt = 0; nt < 4; nt++) {
            const int nc = n0 + wn + nt * 8 + (lane & 3) * 2;
            float* r0 = &C[(size_t)mr * N + nc];
            float* r1 = &C[(size_t)(mr + 8) * N + nc];
            r0[0] = __fadd_rn(acc[mt][nt][0], bias[nc]);
            r0[1] = __fadd_rn(acc[mt][nt][1], bias[nc + 1]);
            r1[0] = __fadd_rn(acc[mt][nt][2], bias[nc]);
            r1[1] = __fadd_rn(acc[mt][nt][3], bias[nc + 1]);
        }
    }
}

// ======================= VQ / misc kernels =======================
__global__ void ee_kernel(const float* __restrict__ E)
{
    const int row  = blockIdx.x * 8 + (threadIdx.x >> 5);
    const int lane = threadIdx.x & 31;
    const float* e = E + (size_t)row * D2;
    float s = 0.f;
    for (int j = lane; j < D2; j += 32)
        s = __fadd_rn(s, __fmul_rn(e[j], e[j]));
#pragma unroll
    for (int o = 16; o; o >>= 1) s = __fadd_rn(s, __shfl_xor_sync(0xffffffffu, s, o));
    if (lane == 0) g_ee[row] = s;
}

__global__ void zz_kernel()
{
    const int m = blockIdx.x * 256 + threadIdx.x;
    if (m >= B_SZ) return;
    const float* z = g_z + (size_t)m * D2;
    float s = 0.f;
    for (int k = 0; k < D2; k++)
        s = __fadd_rn(s, __fmul_rn(z[k], z[k]));
    g_zz[m] = s;
}

__global__ void init_best()
{
    int i = blockIdx.x * 256 + threadIdx.x;
    if (i < B_SZ) g_best[i] = ~0ull;
}

__device__ __forceinline__ unsigned int orderable_f32(float f)
{
    unsigned int u = __float_as_uint(f);
    return (u & 0x80000000u) ? ~u : (u | 0x80000000u);
}

__global__ __launch_bounds__(256, 2)
void vq_score(const float* __restrict__ Z, const float* __restrict__ E)
{
    __shared__ float As[2][16][128];
    __shared__ float Bs[2][16][128];
    const int t  = threadIdx.x;
    const int tx = t & 15, ty = t >> 4;
    const int m0 = blockIdx.y * 128, n0 = blockIdx.x * 128;
    const int lr = t >> 1;
    const int lc = (t & 1) * 4;
    const float* Aptr = Z + (size_t)(m0 + lr) * D2 + lc;
    const float* Wptr = E + (size_t)(n0 + lr) * D2 + lc;

    unsigned long long acc[8][4];
#pragma unroll
    for (int i = 0; i < 8; i++)
#pragma unroll
        for (int p = 0; p < 4; p++) acc[i][p] = 0ull;

    {
        float4 a0 = *(const float4*)(Aptr);
        float4 a1 = *(const float4*)(Aptr + 8);
        float4 w0 = *(const float4*)(Wptr);
        float4 w1 = *(const float4*)(Wptr + 8);
        sts_tile(As[0], Bs[0], lr, lc, a0, a1, w0, w1);
    }
    __syncthreads();

    int cur = 0;
    for (int k0 = 16; k0 < D2; k0 += 16) {
        float4 a0 = *(const float4*)(Aptr + k0);
        float4 a1 = *(const float4*)(Aptr + k0 + 8);
        float4 w0 = *(const float4*)(Wptr + k0);
        float4 w1 = *(const float4*)(Wptr + k0 + 8);
        tile_fma16p(As[cur], Bs[cur], acc, tx, ty);
        sts_tile(As[cur ^ 1], Bs[cur ^ 1], lr, lc, a0, a1, w0, w1);
        __syncthreads();
        cur ^= 1;
    }
    tile_fma16p(As[cur], Bs[cur], acc, tx, ty);

#pragma unroll
    for (int i = 0; i < 8; i++) {
        const int m = m0 + ty * 8 + i;
        const float zzm = g_zz[m];
        unsigned long long best = ~0ull;
#pragma unroll
        for (int p = 0; p < 4; p++) {
            float2 pr = unpack2(acc[i][p]);
#pragma unroll
            for (int h = 0; h < 2; h++) {
                const int j = 2 * p + h;
                const int n = n0 + col_of(tx, j);
                const float s    = h ? pr.y : pr.x;
                const float zze  = __fadd_rn(zzm, g_ee[n]);
                const float twos = __fmul_rn(2.f, s);
                const float d    = __fadd_rn(zze, -twos);
                unsigned long long key =
                    ((unsigned long long)orderable_f32(d) << 32) | (unsigned int)n;
                best = (key < best) ? key : best;
            }
        }
#pragma unroll
        for (int o = 8; o; o >>= 1) {
            unsigned long long other = __shfl_xor_sync(0xffffffffu, best, o);
            best = (other < best) ? other : best;
        }
        if (tx == 0) atomicMin(&g_best[m], best);
    }
}

// gather q = E[idx]: emit q_st fp32 output + packed bf16 splits + loss partials
__global__ void gather_loss(const float* __restrict__ E, float* __restrict__ out_q)
{
    const int m   = blockIdx.x;
    const int idx = (int)(unsigned int)(g_best[m] & 0xFFFFFFFFull);
    const float* e = E + (size_t)idx * D2;
    const float* z = g_z + (size_t)m * D2;
    const int j = threadIdx.x * 2;
    float q0 = e[j], q1 = e[j + 1];
    float d0 = q0 - z[j], d1 = q1 - z[j + 1];
    float s = fmaf(d1, d1, d0 * d0);
    uint32_t hi, lo;
    split2(q0, q1, hi, lo);
    const size_t pi = ((size_t)m * D2 + j) >> 1;
    g_qh[pi] = hi; g_ql[pi] = lo;
    if (out_q) { out_q[(size_t)m * D2 + j] = q0; out_q[(size_t)m * D2 + j + 1] = q1; }

    __shared__ float red[256];
    red[threadIdx.x] = s;
    __syncthreads();
    for (int o = 128; o; o >>= 1) {
        if (threadIdx.x < o) red[threadIdx.x] += red[threadIdx.x + o];
        __syncthreads();
    }
    if (threadIdx.x == 0) g_rowsum[m] = red[0];
}

__global__ void reduce_loss(float* __restrict__ out_loss)
{
    __shared__ float red[1024];
    float s = 0.f;
    for (int i = threadIdx.x; i < B_SZ; i += 1024) s += g_rowsum[i];
    red[threadIdx.x] = s;
    __syncthreads();
    for (int o = 512; o; o >>= 1) {
        if (threadIdx.x < o) red[threadIdx.x] += red[threadIdx.x + o];
        __syncthreads();
    }
    if (threadIdx.x == 0)
        out_loss[0] = red[0] * (1.25f / (float)((size_t)B_SZ * D2));
}

// ----------------------------------------------------------------
extern "C" void kernel_launch(void* const* d_in, const int* in_sizes, int n_in,
                              void* d_out, int out_size)
{
    const float* X  = (const float*)d_in[0];
    const float* W1 = (const float*)d_in[1];
    const float* b1 = (const float*)d_in[2];
    const float* W2 = (const float*)d_in[3];
    const float* b2 = (const float*)d_in[4];
    const float* W3 = (const float*)d_in[5];
    const float* b3 = (const float*)d_in[6];
    const float* E  = (const float*)d_in[7];
    const float* W4 = (const float*)d_in[8];
    const float* b4 = (const float*)d_in[9];
    const float* W5 = (const float*)d_in[10];
    const float* b5 = (const float*)d_in[11];
    const float* W6 = (const float*)d_in[12];
    const float* b6 = (const float*)d_in[13];

    float *h1, *h2, *z;
    cudaGetSymbolAddress((void**)&h1, g_h1);
    cudaGetSymbolAddress((void**)&h2, g_h2);
    cudaGetSymbolAddress((void**)&z,  g_z);
    uint32_t *w4h, *w4l, *w5h, *w5l, *w6h, *qh, *ql, *h2h, *h2l, *h1h;
    cudaGetSymbolAddress((void**)&w4h, g_w4h); cudaGetSymbolAddress((void**)&w4l, g_w4l);
    cudaGetSymbolAddress((void**)&w5h, g_w5h); cudaGetSymbolAddress((void**)&w5l, g_w5l);
    cudaGetSymbolAddress((void**)&w6h, g_w6h);
    cudaGetSymbolAddress((void**)&qh,  g_qh);  cudaGetSymbolAddress((void**)&ql,  g_ql);
    cudaGetSymbolAddress((void**)&h2h, g_h2h); cudaGetSymbolAddress((void**)&h2l, g_h2l);
    cudaGetSymbolAddress((void**)&h1h, g_h1h);

    float* out = (float*)d_out;
    const long long full = 1LL + (long long)B_SZ * G_NUM + (long long)B_SZ * D2;
    float* out_loss = nullptr;
    float* out_x    = out;
    float* out_q    = nullptr;
    if ((long long)out_size == full) {
        out_loss = out;
        out_x    = out + 1;
        out_q    = out + 1 + (long long)B_SZ * G_NUM;
    }

    cudaFuncSetAttribute((const void*)gemm_mma2<1, true>,
                         cudaFuncAttributeMaxDynamicSharedMemorySize, DSMEM);
    cudaFuncSetAttribute((const void*)gemm_mma2<2, true>,
                         cudaFuncAttributeMaxDynamicSharedMemorySize, DSMEM);
    cudaFuncSetAttribute((const void*)gemm_h16,
                         cudaFuncAttributeMaxDynamicSharedMemorySize, HSMEM);

    const dim3 blk(256);

    // weight prep (independent of encoder)
    split_pairs<<<(D1 * D2 / 4 + 255) / 256, 256>>>(W4, w4h, w4l, D1 * D2 / 4);
    split_pairs<<<(D0 * D1 / 4 + 255) / 256, 256>>>(W5, w5h, w5l, D0 * D1 / 4);
    quant_h16 <<<(G_NUM / 4 * D0 + 255) / 256, 256>>>(W6, w6h, G_NUM / 4 * D0);

    ee_kernel<<<KEMB / 8, 256>>>(E);
    init_best<<<B_SZ / 256, 256>>>();

    // encoder (bit-exact fp32 chains)
    gemm_bias_act<true><<<dim3(D0 / 128, B_SZ / 128), blk>>>(X,  W1, b1, h1, B_SZ, D0, G_NUM);
    gemm_bias_act<true><<<dim3(D1 / 128, B_SZ / 128), blk>>>(h1, W2, b2, h2, B_SZ, D1, D0);
    gemm_bias_act<true><<<dim3(D2 / 128, B_SZ / 128), blk>>>(h2, W3, b3, z,  B_SZ, D2, D1);

    // VQ (bit-exact replication of reference dist formula)
    zz_kernel<<<B_SZ / 256, 256>>>();
    vq_score<<<dim3(KEMB / 128, B_SZ / 128), blk>>>(z, E);
    gather_loss<<<B_SZ, 256>>>(E, out_q);
    if (out_loss) reduce_loss<<<1, 1024>>>(out_loss);

    // decoder: W4/W5 bf16 3-term (high accuracy feeds forward), W6 fp16 1-term
    gemm_mma2<1, true><<<dim3(B_SZ / 128, D1 / 128), blk, DSMEM>>>(
        qh, ql, w4h, w4l, b4, h2h, h2l, D1, D2);
    gemm_mma2<2, true><<<dim3(B_SZ / 128, D0 / 128), blk, DSMEM>>>(
        h2h, h2l, w5h, w5l, b5, h1h, nullptr, D0, D1);
    gemm_h16<<<dim3(B_SZ / 128, G_NUM / 128), blk, HSMEM>>>(
        h1h, w6h, b6, out_x, G_NUM, D0);
}

// round 11
// speedup vs baseline: 1.9269x; 1.0261x over previous
#include <cuda_runtime.h>
#include <cuda_bf16.h>
#include <cstdint>

#define B_SZ 4096
#define G_NUM 16384
#define D0 4096
#define D1 2048
#define D2 512
#define KEMB 8192

// -------- scratch (static device memory; no allocations) --------
__device__ float g_h1[(size_t)B_SZ * D0];        // encoder h1 (fp32)
__device__ float g_h2[(size_t)B_SZ * D1];        // encoder h2 (fp32)
__device__ float g_z [(size_t)B_SZ * D2];
__device__ float g_ee[KEMB];
__device__ float g_zz[B_SZ];
__device__ unsigned long long g_best[B_SZ];
__device__ float g_rowsum[B_SZ];

// packed pairs (u32 = 2 consecutive elements)
__device__ uint32_t g_w4h[(size_t)D1 * D2 / 2],    g_w4l[(size_t)D1 * D2 / 2];    // bf16
__device__ uint32_t g_w5h[(size_t)D0 * D1 / 2];                                    // fp16
__device__ uint32_t g_w6h[(size_t)G_NUM * D0 / 2];                                 // fp16
__device__ uint32_t g_qh [(size_t)B_SZ * D2 / 2],  g_ql [(size_t)B_SZ * D2 / 2];  // bf16
__device__ uint32_t g_h2h[(size_t)B_SZ * D1 / 2];                                  // fp16
__device__ uint32_t g_h1h[(size_t)B_SZ * D0 / 2];                                  // fp16

// ---------------- XLA/Eigen tanh f32 rational approximation ----------------
__device__ __forceinline__ float xla_tanh(float x)
{
    if (fabsf(x) < 0.0004f) return x;
    float xc = fminf(fmaxf(x, -7.90531110763549805f), 7.90531110763549805f);
    float x2 = __fmul_rn(xc, xc);
    float p = fmaf(x2, -2.76076847742355e-16f, 2.00018790482477e-13f);
    p = fmaf(x2, p, -8.60467152213735e-11f);
    p = fmaf(x2, p,  5.12229709037114e-08f);
    p = fmaf(x2, p,  1.48572235717979e-05f);
    p = fmaf(x2, p,  6.37261928875436e-04f);
    p = fmaf(x2, p,  4.89352455891786e-03f);
    p = __fmul_rn(xc, p);
    float q = fmaf(x2, 1.19825839466702e-06f, 1.18534705686654e-04f);
    q = fmaf(x2, q, 2.26843463243900e-03f);
    q = fmaf(x2, q, 4.89352518554385e-03f);
    return __fdiv_rn(p, q);
}

// ---------------- packed fp32x2 helpers ----------------
__device__ __forceinline__ void ffma2(unsigned long long& d,
                                      unsigned long long a, unsigned long long b)
{
    asm("fma.rn.f32x2 %0, %1, %2, %0;" : "+l"(d) : "l"(a), "l"(b));
}
__device__ __forceinline__ unsigned long long dup2(float a)
{
    unsigned long long r;
    asm("mov.b64 %0, {%1, %1};" : "=l"(r) : "f"(a));
    return r;
}
__device__ __forceinline__ float2 unpack2(unsigned long long v)
{
    float lo, hi;
    asm("mov.b64 {%0, %1}, %2;" : "=f"(lo), "=f"(hi) : "l"(v));
    return make_float2(lo, hi);
}

// ======================= SIMT exact-chain GEMM (encoder) =======================
__device__ __forceinline__ void sts_tile(float (&As)[16][128], float (&Bs)[16][128],
                                         int lr, int lc,
                                         float4 a0, float4 a1, float4 w0, float4 w1)
{
    As[lc + 0][lr] = a0.x; As[lc + 1][lr] = a0.y;
    As[lc + 2][lr] = a0.z; As[lc + 3][lr] = a0.w;
    As[lc + 8][lr] = a1.x; As[lc + 9][lr] = a1.y;
    As[lc +10][lr] = a1.z; As[lc +11][lr] = a1.w;
    Bs[lc + 0][lr] = w0.x; Bs[lc + 1][lr] = w0.y;
    Bs[lc + 2][lr] = w0.z; Bs[lc + 3][lr] = w0.w;
    Bs[lc + 8][lr] = w1.x; Bs[lc + 9][lr] = w1.y;
    Bs[lc +10][lr] = w1.z; Bs[lc +11][lr] = w1.w;
}

// packed-f32x2 inner product tile; each acc lane keeps its own ascending-k
// IEEE-RN FMA chain (bit-identical to scalar fmaf version).
__device__ __forceinline__ void tile_fma16p(const float (&As)[16][128],
                                            const float (&Bs)[16][128],
                                            unsigned long long (&acc)[8][4],
                                            int tx, int ty)
{
#pragma unroll
    for (int kk = 0; kk < 16; kk++) {
        float4 a0 = *(const float4*)&As[kk][ty * 8];
        float4 a1 = *(const float4*)&As[kk][ty * 8 + 4];
        ulonglong2 b01 = *(const ulonglong2*)&Bs[kk][tx * 4];
        ulonglong2 b23 = *(const ulonglong2*)&Bs[kk][64 + tx * 4];
        unsigned long long bb[4] = {b01.x, b01.y, b23.x, b23.y};
        float a[8] = {a0.x, a0.y, a0.z, a0.w, a1.x, a1.y, a1.z, a1.w};
#pragma unroll
        for (int i = 0; i < 8; i++) {
            unsigned long long ai = dup2(a[i]);
#pragma unroll
            for (int p = 0; p < 4; p++) ffma2(acc[i][p], ai, bb[p]);
        }
    }
}

__device__ __forceinline__ int col_of(int tx, int j)
{
    return (j < 4) ? (tx * 4 + j) : (64 + tx * 4 + (j - 4));
}

template<bool TANH>
__global__ __launch_bounds__(256, 2)
void gemm_bias_act(const float* __restrict__ A, const float* __restrict__ W,
                   const float* __restrict__ bias, float* __restrict__ C,
                   int M, int N, int K)
{
    __shared__ float As[2][16][128];
    __shared__ float Bs[2][16][128];
    const int t  = threadIdx.x;
    const int tx = t & 15, ty = t >> 4;
    const int m0 = blockIdx.y * 128, n0 = blockIdx.x * 128;
    const int lr = t >> 1;
    const int lc = (t & 1) * 4;
    const float* Aptr = A + (size_t)(m0 + lr) * K + lc;
    const float* Wptr = W + (size_t)(n0 + lr) * K + lc;

    unsigned long long acc[8][4];
#pragma unroll
    for (int i = 0; i < 8; i++)
#pragma unroll
        for (int p = 0; p < 4; p++) acc[i][p] = 0ull;

    {
        float4 a0 = *(const float4*)(Aptr);
        float4 a1 = *(const float4*)(Aptr + 8);
        float4 w0 = *(const float4*)(Wptr);
        float4 w1 = *(const float4*)(Wptr + 8);
        sts_tile(As[0], Bs[0], lr, lc, a0, a1, w0, w1);
    }
    __syncthreads();

    int cur = 0;
    for (int k0 = 16; k0 < K; k0 += 16) {
        float4 a0 = *(const float4*)(Aptr + k0);
        float4 a1 = *(const float4*)(Aptr + k0 + 8);
        float4 w0 = *(const float4*)(Wptr + k0);
        float4 w1 = *(const float4*)(Wptr + k0 + 8);
        tile_fma16p(As[cur], Bs[cur], acc, tx, ty);
        sts_tile(As[cur ^ 1], Bs[cur ^ 1], lr, lc, a0, a1, w0, w1);
        __syncthreads();
        cur ^= 1;
    }
    tile_fma16p(As[cur], Bs[cur], acc, tx, ty);

#pragma unroll
    for (int i = 0; i < 8; i++) {
        const int m = m0 + ty * 8 + i;
#pragma unroll
        for (int p = 0; p < 4; p++) {
            float2 pr = unpack2(acc[i][p]);
#pragma unroll
            for (int h = 0; h < 2; h++) {
                const int j = 2 * p + h;
                const int n = n0 + col_of(tx, j);
                float v = __fadd_rn(h ? pr.y : pr.x, bias[n]);
                if (TANH) v = xla_tanh(v);
                C[(size_t)m * N + n] = v;
            }
        }
    }
}

// ======================= conversion helpers =======================
// split fp32 pair -> bf16x2 hi + bf16x2 residual (packed u32 each)
__device__ __forceinline__ void split2(float f0, float f1, uint32_t& hi, uint32_t& lo)
{
    asm("cvt.rn.bf16x2.f32 %0, %1, %2;" : "=r"(hi) : "f"(f1), "f"(f0));
    float h0 = __uint_as_float(hi << 16);
    float h1 = __uint_as_float(hi & 0xFFFF0000u);
    float r0 = __fadd_rn(f0, -h0);
    float r1 = __fadd_rn(f1, -h1);
    asm("cvt.rn.bf16x2.f32 %0, %1, %2;" : "=r"(lo) : "f"(r1), "f"(r0));
}

__device__ __forceinline__ uint32_t cvt_h2(float f0, float f1)
{
    uint32_t r;
    asm("cvt.rn.f16x2.f32 %0, %1, %2;" : "=r"(r) : "f"(f1), "f"(f0));
    return r;
}

// elementwise weight split: W fp32 -> packed bf16 hi/lo pair arrays
__global__ void split_pairs(const float* __restrict__ W, uint32_t* __restrict__ Wh,
                            uint32_t* __restrict__ Wl, int n4)
{
    int i = blockIdx.x * 256 + threadIdx.x;
    if (i >= n4) return;
    float4 v = ((const float4*)W)[i];
    uint32_t h0, l0, h1, l1;
    split2(v.x, v.y, h0, l0);
    split2(v.z, v.w, h1, l1);
    ((uint2*)Wh)[i] = make_uint2(h0, h1);
    ((uint2*)Wl)[i] = make_uint2(l0, l1);
}

// elementwise fp16 quantization (no residual): W fp32 -> packed f16 pairs
__global__ void quant_h16(const float* __restrict__ W, uint32_t* __restrict__ Wh, int n4)
{
    int i = blockIdx.x * 256 + threadIdx.x;
    if (i >= n4) return;
    float4 v = ((const float4*)W)[i];
    ((uint2*)Wh)[i] = make_uint2(cvt_h2(v.x, v.y), cvt_h2(v.z, v.w));
}

// ======================= HMMA decoder GEMMs =======================
__device__ __forceinline__ uint32_t smem_u32(const void* p)
{
    uint32_t a;
    asm("{ .reg .u64 t; cvta.to.shared.u64 t, %1; cvt.u32.u64 %0, t; }"
        : "=r"(a) : "l"(p));
    return a;
}

__device__ __forceinline__ void mma_bf16(float* c, const uint32_t* a, const uint32_t* b)
{
    asm volatile(
        "mma.sync.aligned.m16n8k16.row.col.f32.bf16.bf16.f32 "
        "{%0,%1,%2,%3}, {%4,%5,%6,%7}, {%8,%9}, {%0,%1,%2,%3};"
        : "+f"(c[0]), "+f"(c[1]), "+f"(c[2]), "+f"(c[3])
        : "r"(a[0]), "r"(a[1]), "r"(a[2]), "r"(a[3]), "r"(b[0]), "r"(b[1]));
}

__device__ __forceinline__ void mma_f16(float* c, const uint32_t* a, const uint32_t* b)
{
    asm volatile(
        "mma.sync.aligned.m16n8k16.row.col.f32.f16.f16.f32 "
        "{%0,%1,%2,%3}, {%4,%5,%6,%7}, {%8,%9}, {%0,%1,%2,%3};"
        : "+f"(c[0]), "+f"(c[1]), "+f"(c[2]), "+f"(c[3])
        : "r"(a[0]), "r"(a[1]), "r"(a[2]), "r"(a[3]), "r"(b[0]), "r"(b[1]));
}

__device__ __forceinline__ void ldmx4(uint32_t* r, uint32_t a)
{
    asm volatile("ldmatrix.sync.aligned.m8n8.x4.shared.b16 {%0,%1,%2,%3}, [%4];"
                 : "=r"(r[0]), "=r"(r[1]), "=r"(r[2]), "=r"(r[3]) : "r"(a));
}
__device__ __forceinline__ void ldmx2(uint32_t* r, uint32_t a)
{
    asm volatile("ldmatrix.sync.aligned.m8n8.x2.shared.b16 {%0,%1}, [%2];"
                 : "=r"(r[0]), "=r"(r[1]) : "r"(a));
}
__device__ __forceinline__ void sts128(uint32_t a, uint4 v)
{
    asm volatile("st.shared.v4.u32 [%0], {%1,%2,%3,%4};"
                 :: "r"(a), "r"(v.x), "r"(v.y), "r"(v.z), "r"(v.w));
}

// ---- bf16 3-term split GEMM (W4) ----
// smem: 4 tiles (Ah, Al, Bh, Bl), 128 rows x 32 bf16 (64B) padded to 80B stride
#define DSTRIDE 80
#define DTILE  (128 * DSTRIDE)   // 10240
#define DBUF   (4 * DTILE)       // 40960
#define DSMEM  (2 * DBUF)        // 81920

// OUTMODE 2: fp16 packed out (Chp only).
template<int OUTMODE, bool TANH>
__global__ __launch_bounds__(256, 1)
void gemm_mma2(const uint32_t* __restrict__ Ahp, const uint32_t* __restrict__ Alp,
               const uint32_t* __restrict__ Bhp, const uint32_t* __restrict__ Blp,
               const float* __restrict__ bias,
               uint32_t* __restrict__ Chp, uint32_t* __restrict__ Clp,
               int N, int K)
{
    extern __shared__ char sm[];
    const uint32_t sb = smem_u32(sm);
    const int t    = threadIdx.x;
    const int lane = t & 31;
    const int wid  = t >> 5;
    const int wm   = (wid >> 2) * 64;
    const int wn   = (wid & 3) * 32;
    const int m0   = blockIdx.x * 128;
    const int n0   = blockIdx.y * 128;
    const int Kp   = K >> 1;

    const int tile = t >> 6, u = t & 63;
    const uint32_t* src = (tile == 0) ? Ahp : (tile == 1) ? Alp : (tile == 2) ? Bhp : Blp;
    const int grow = ((tile < 2) ? m0 : n0) + 2 * u;
    const uint32_t* g0 = src + (size_t)grow * Kp;
    const uint32_t* g1 = g0 + Kp;
    const uint32_t dstr = (uint32_t)(tile * DTILE + (2 * u) * DSTRIDE);

    float acc[4][4][4];
#pragma unroll
    for (int i = 0; i < 4; i++)
#pragma unroll
        for (int j = 0; j < 4; j++)
#pragma unroll
            for (int r = 0; r < 4; r++) acc[i][j][r] = 0.f;

    const int nslab = K >> 5;
    uint4 pf[8];
#pragma unroll
    for (int c = 0; c < 4; c++) {
        pf[c]     = ((const uint4*)g0)[c];
        pf[4 + c] = ((const uint4*)g1)[c];
    }

    const uint32_t a_lane = (uint32_t)((wm + (lane & 7) + ((lane >> 3) & 1) * 8) * DSTRIDE
                                       + (lane >> 4) * 16);
    const uint32_t b_lane = (uint32_t)((wn + (lane & 7)) * DSTRIDE
                                       + ((lane >> 3) & 1) * 16);

    for (int s = 0; s < nslab; s++) {
        const uint32_t buf = sb + (uint32_t)(s & 1) * DBUF;
        const uint32_t da  = buf + dstr;
#pragma unroll
        for (int c = 0; c < 4; c++) {
            sts128(da + c * 16,           pf[c]);
            sts128(da + DSTRIDE + c * 16, pf[4 + c]);
        }
        if (s + 1 < nslab) {
            const uint4* n0p = (const uint4*)(g0 + (s + 1) * 16);
            const uint4* n1p = (const uint4*)(g1 + (s + 1) * 16);
#pragma unroll
            for (int c = 0; c < 4; c++) { pf[c] = n0p[c]; pf[4 + c] = n1p[c]; }
        }
        __syncthreads();

        const uint32_t Ath = buf;
        const uint32_t Atl = buf + DTILE;
        const uint32_t Bth = buf + 2 * DTILE;
        const uint32_t Btl = buf + 3 * DTILE;
#pragma unroll
        for (int ks = 0; ks < 2; ks++) {
            uint32_t ah[4][4], al[4][4], bh[4][2], bl[4][2];
#pragma unroll
            for (int mt = 0; mt < 4; mt++) {
                const uint32_t off = a_lane + (uint32_t)(mt * 16 * DSTRIDE + ks * 32);
                ldmx4(ah[mt], Ath + off);
                ldmx4(al[mt], Atl + off);
            }
#pragma unroll
            for (int nt = 0; nt < 4; nt++) {
                const uint32_t off = b_lane + (uint32_t)(nt * 8 * DSTRIDE + ks * 32);
                ldmx2(bh[nt], Bth + off);
                ldmx2(bl[nt], Btl + off);
            }
#pragma unroll
            for (int mt = 0; mt < 4; mt++)
#pragma unroll
                for (int nt = 0; nt < 4; nt++)
                    mma_bf16(acc[mt][nt], ah[mt], bh[nt]);     // A1*B1
#pragma unroll
            for (int mt = 0; mt < 4; mt++)
#pragma unroll
                for (int nt = 0; nt < 4; nt++)
                    mma_bf16(acc[mt][nt], ah[mt], bl[nt]);     // A1*B2
#pragma unroll
            for (int mt = 0; mt < 4; mt++)
#pragma unroll
                for (int nt = 0; nt < 4; nt++)
                    mma_bf16(acc[mt][nt], al[mt], bh[nt]);     // A2*B1
        }
    }

#pragma unroll
    for (int mt = 0; mt < 4; mt++) {
        const int mr = m0 + wm + mt * 16 + (lane >> 2);
#pragma unroll
        for (int nt = 0; nt < 4; nt++) {
            const int nc = n0 + wn + nt * 8 + (lane & 3) * 2;
            const float b0 = bias[nc], b1 = bias[nc + 1];
            float v0 = __fadd_rn(acc[mt][nt][0], b0);
            float v1 = __fadd_rn(acc[mt][nt][1], b1);
            float v2 = __fadd_rn(acc[mt][nt][2], b0);
            float v3 = __fadd_rn(acc[mt][nt][3], b1);
            if (TANH) { v0 = xla_tanh(v0); v1 = xla_tanh(v1); v2 = xla_tanh(v2); v3 = xla_tanh(v3); }
            const size_t i0 = (size_t)mr * (N >> 1) + (nc >> 1);
            const size_t i1 = (size_t)(mr + 8) * (N >> 1) + (nc >> 1);
            if (OUTMODE == 1) {
                uint32_t hi, lo;
                split2(v0, v1, hi, lo); Chp[i0] = hi; Clp[i0] = lo;
                split2(v2, v3, hi, lo); Chp[i1] = hi; Clp[i1] = lo;
            } else {
                Chp[i0] = cvt_h2(v0, v1);
                Chp[i1] = cvt_h2(v2, v3);
            }
        }
    }
}

// ---- fp16 single-term GEMM (W5, W6) ----
#define HSTRIDE 80
#define HTILE  (128 * HSTRIDE)   // 10240
#define HBUF   (2 * HTILE)       // 20480 (A + B)
#define HSMEM  (2 * HBUF)        // 40960

// OUTMODE 0: fp32 scalar C (x_recon; may be 4B-aligned). OUTMODE 2: fp16 packed Chp.
template<int OUTMODE, bool TANH>
__global__ __launch_bounds__(256, 1)
void gemm_h16(const uint32_t* __restrict__ Ah, const uint32_t* __restrict__ Bh,
              const float* __restrict__ bias, float* __restrict__ C,
              uint32_t* __restrict__ Chp, int N, int K)
{
    extern __shared__ char sm[];
    const uint32_t sb = smem_u32(sm);
    const int t    = threadIdx.x;
    const int lane = t & 31;
    const int wid  = t >> 5;
    const int wm   = (wid >> 2) * 64;
    const int wn   = (wid & 3) * 32;
    const int m0   = blockIdx.x * 128;
    const int n0   = blockIdx.y * 128;
    const int Kp   = K >> 1;

    const int tile = t >> 7, u = t & 127;
    const uint32_t* g = tile ? (Bh + (size_t)(n0 + u) * Kp)
                             : (Ah + (size_t)(m0 + u) * Kp);
    const uint32_t dstr = (uint32_t)(tile * HTILE + u * HSTRIDE);

    float acc[4][4][4];
#pragma unroll
    for (int i = 0; i < 4; i++)
#pragma unroll
        for (int j = 0; j < 4; j++)
#pragma unroll
            for (int r = 0; r < 4; r++) acc[i][j][r] = 0.f;

    const int nslab = K >> 5;
    uint4 pf[4];
#pragma unroll
    for (int c = 0; c < 4; c++) pf[c] = ((const uint4*)g)[c];

    const uint32_t a_lane = (uint32_t)((wm + (lane & 7) + ((lane >> 3) & 1) * 8) * HSTRIDE
                                       + (lane >> 4) * 16);
    const uint32_t b_lane = (uint32_t)((wn + (lane & 7)) * HSTRIDE
                                       + ((lane >> 3) & 1) * 16);

    for (int s = 0; s < nslab; s++) {
        const uint32_t buf = sb + (uint32_t)(s & 1) * HBUF;
        const uint32_t da  = buf + dstr;
#pragma unroll
        for (int c = 0; c < 4; c++) sts128(da + c * 16, pf[c]);
        if (s + 1 < nslab) {
            const uint4* np = (const uint4*)(g + (s + 1) * 16);
#pragma unroll
            for (int c = 0; c < 4; c++) pf[c] = np[c];
        }
        __syncthreads();

        const uint32_t Ath = buf;
        const uint32_t Bth = buf + HTILE;
#pragma unroll
        for (int ks = 0; ks < 2; ks++) {
            uint32_t ah[4][4], bh[4][2];
#pragma unroll
            for (int mt = 0; mt < 4; mt++)
                ldmx4(ah[mt], Ath + a_lane + (uint32_t)(mt * 16 * HSTRIDE + ks * 32));
#pragma unroll
            for (int nt = 0; nt < 4; nt++)
                ldmx2(bh[nt], Bth + b_lane + (uint32_t)(nt * 8 * HSTRIDE + ks * 32));
#pragma unroll
            for (int mt = 0; mt < 4; mt++)
#pragma unroll
                for (int nt = 0; nt < 4; nt++)
                    mma_f16(acc[mt][nt], ah[mt], bh[nt]);
        }
    }

#pragma unroll
    for (int mt = 0; mt < 4; mt++) {
        const int mr = m0 + wm + mt * 16 + (lane >> 2);
#pragma unroll
        for (int nt = 0; nt < 4; nt++) {
            const int nc = n0 + wn + nt * 8 + (lane & 3) * 2;
            float v0 = __fadd_rn(acc[mt][nt][0], bias[nc]);
            float v1 = __fadd_rn(acc[mt][nt][1], bias[nc + 1]);
            float v2 = __fadd_rn(acc[mt][nt][2], bias[nc]);
            float v3 = __fadd_rn(acc[mt][nt][3], bias[nc + 1]);
            if (TANH) { v0 = xla_tanh(v0); v1 = xla_tanh(v1); v2 = xla_tanh(v2); v3 = xla_tanh(v3); }
            if (OUTMODE == 0) {
                float* r0 = &C[(size_t)mr * N + nc];
                float* r1 = &C[(size_t)(mr + 8) * N + nc];
                r0[0] = v0; r0[1] = v1;
                r1[0] = v2; r1[1] = v3;
            } else {
                Chp[(size_t)mr * (N >> 1) + (nc >> 1)]       = cvt_h2(v0, v1);
                Chp[(size_t)(mr + 8) * (N >> 1) + (nc >> 1)] = cvt_h2(v2, v3);
            }
        }
    }
}

// ======================= VQ / misc kernels =======================
__global__ void ee_kernel(const float* __restrict__ E)
{
    const int row  = blockIdx.x * 8 + (threadIdx.x >> 5);
    const int lane = threadIdx.x & 31;
    const float* e = E + (size_t)row * D2;
    float s = 0.f;
    for (int j = lane; j < D2; j += 32)
        s = __fadd_rn(s, __fmul_rn(e[j], e[j]));
#pragma unroll
    for (int o = 16; o; o >>= 1) s = __fadd_rn(s, __shfl_xor_sync(0xffffffffu, s, o));
    if (lane == 0) g_ee[row] = s;
}

__global__ void zz_kernel()
{
    const int m = blockIdx.x * 256 + threadIdx.x;
    if (m >= B_SZ) return;
    const float* z = g_z + (size_t)m * D2;
    float s = 0.f;
    for (int k = 0; k < D2; k++)
        s = __fadd_rn(s, __fmul_rn(z[k], z[k]));
    g_zz[m] = s;
}

__global__ void init_best()
{
    int i = blockIdx.x * 256 + threadIdx.x;
    if (i < B_SZ) g_best[i] = ~0ull;
}

__device__ __forceinline__ unsigned int orderable_f32(float f)
{
    unsigned int u = __float_as_uint(f);
    return (u & 0x80000000u) ? ~u : (u | 0x80000000u);
}

__global__ __launch_bounds__(256, 2)
void vq_score(const float* __restrict__ Z, const float* __restrict__ E)
{
    __shared__ float As[2][16][128];
    __shared__ float Bs[2][16][128];
    const int t  = threadIdx.x;
    const int tx = t & 15, ty = t >> 4;
    const int m0 = blockIdx.y * 128, n0 = blockIdx.x * 128;
    const int lr = t >> 1;
    const int lc = (t & 1) * 4;
    const float* Aptr = Z + (size_t)(m0 + lr) * D2 + lc;
    const float* Wptr = E + (size_t)(n0 + lr) * D2 + lc;

    unsigned long long acc[8][4];
#pragma unroll
    for (int i = 0; i < 8; i++)
#pragma unroll
        for (int p = 0; p < 4; p++) acc[i][p] = 0ull;

    {
        float4 a0 = *(const float4*)(Aptr);
        float4 a1 = *(const float4*)(Aptr + 8);
        float4 w0 = *(const float4*)(Wptr);
        float4 w1 = *(const float4*)(Wptr + 8);
        sts_tile(As[0], Bs[0], lr, lc, a0, a1, w0, w1);
    }
    __syncthreads();

    int cur = 0;
    for (int k0 = 16; k0 < D2; k0 += 16) {
        float4 a0 = *(const float4*)(Aptr + k0);
        float4 a1 = *(const float4*)(Aptr + k0 + 8);
        float4 w0 = *(const float4*)(Wptr + k0);
        float4 w1 = *(const float4*)(Wptr + k0 + 8);
        tile_fma16p(As[cur], Bs[cur], acc, tx, ty);
        sts_tile(As[cur ^ 1], Bs[cur ^ 1], lr, lc, a0, a1, w0, w1);
        __syncthreads();
        cur ^= 1;
    }
    tile_fma16p(As[cur], Bs[cur], acc, tx, ty);

#pragma unroll
    for (int i = 0; i < 8; i++) {
        const int m = m0 + ty * 8 + i;
        const float zzm = g_zz[m];
        unsigned long long best = ~0ull;
#pragma unroll
        for (int p = 0; p < 4; p++) {
            float2 pr = unpack2(acc[i][p]);
#pragma unroll
            for (int h = 0; h < 2; h++) {
                const int j = 2 * p + h;
                const int n = n0 + col_of(tx, j);
                const float s    = h ? pr.y : pr.x;
                const float zze  = __fadd_rn(zzm, g_ee[n]);
                const float twos = __fmul_rn(2.f, s);
                const float d    = __fadd_rn(zze, -twos);
                unsigned long long key =
                    ((unsigned long long)orderable_f32(d) << 32) | (unsigned int)n;
                best = (key < best) ? key : best;
            }
        }
#pragma unroll
        for (int o = 8; o; o >>= 1) {
            unsigned long long other = __shfl_xor_sync(0xffffffffu, best, o);
            best = (other < best) ? other : best;
        }
        if (tx == 0) atomicMin(&g_best[m], best);
    }
}

// gather q = E[idx]: emit q_st fp32 output + packed bf16 splits + loss partials
__global__ void gather_loss(const float* __restrict__ E, float* __restrict__ out_q)
{
    const int m   = blockIdx.x;
    const int idx = (int)(unsigned int)(g_best[m] & 0xFFFFFFFFull);
    const float* e = E + (size_t)idx * D2;
    const float* z = g_z + (size_t)m * D2;
    const int j = threadIdx.x * 2;
    float q0 = e[j], q1 = e[j + 1];
    float d0 = q0 - z[j], d1 = q1 - z[j + 1];
    float s = fmaf(d1, d1, d0 * d0);
    uint32_t hi, lo;
    split2(q0, q1, hi, lo);
    const size_t pi = ((size_t)m * D2 + j) >> 1;
    g_qh[pi] = hi; g_ql[pi] = lo;
    if (out_q) { out_q[(size_t)m * D2 + j] = q0; out_q[(size_t)m * D2 + j + 1] = q1; }

    __shared__ float red[256];
    red[threadIdx.x] = s;
    __syncthreads();
    for (int o = 128; o; o >>= 1) {
        if (threadIdx.x < o) red[threadIdx.x] += red[threadIdx.x + o];
        __syncthreads();
    }
    if (threadIdx.x == 0) g_rowsum[m] = red[0];
}

__global__ void reduce_loss(float* __restrict__ out_loss)
{
    __shared__ float red[1024];
    float s = 0.f;
    for (int i = threadIdx.x; i < B_SZ; i += 1024) s += g_rowsum[i];
    red[threadIdx.x] = s;
    __syncthreads();
    for (int o = 512; o; o >>= 1) {
        if (threadIdx.x < o) red[threadIdx.x] += red[threadIdx.x + o];
        __syncthreads();
    }
    if (threadIdx.x == 0)
        out_loss[0] = red[0] * (1.25f / (float)((size_t)B_SZ * D2));
}

// ----------------------------------------------------------------
extern "C" void kernel_launch(void* const* d_in, const int* in_sizes, int n_in,
                              void* d_out, int out_size)
{
    const float* X  = (const float*)d_in[0];
    const float* W1 = (const float*)d_in[1];
    const float* b1 = (const float*)d_in[2];
    const float* W2 = (const float*)d_in[3];
    const float* b2 = (const float*)d_in[4];
    const float* W3 = (const float*)d_in[5];
    const float* b3 = (const float*)d_in[6];
    const float* E  = (const float*)d_in[7];
    const float* W4 = (const float*)d_in[8];
    const float* b4 = (const float*)d_in[9];
    const float* W5 = (const float*)d_in[10];
    const float* b5 = (const float*)d_in[11];
    const float* W6 = (const float*)d_in[12];
    const float* b6 = (const float*)d_in[13];

    float *h1, *h2, *z;
    cudaGetSymbolAddress((void**)&h1, g_h1);
    cudaGetSymbolAddress((void**)&h2, g_h2);
    cudaGetSymbolAddress((void**)&z,  g_z);
    uint32_t *w4h, *w4l, *w5h, *w6h, *qh, *ql, *h2h, *h1h;
    cudaGetSymbolAddress((void**)&w4h, g_w4h); cudaGetSymbolAddress((void**)&w4l, g_w4l);
    cudaGetSymbolAddress((void**)&w5h, g_w5h);
    cudaGetSymbolAddress((void**)&w6h, g_w6h);
    cudaGetSymbolAddress((void**)&qh,  g_qh);  cudaGetSymbolAddress((void**)&ql,  g_ql);
    cudaGetSymbolAddress((void**)&h2h, g_h2h);
    cudaGetSymbolAddress((void**)&h1h, g_h1h);

    float* out = (float*)d_out;
    const long long full = 1LL + (long long)B_SZ * G_NUM + (long long)B_SZ * D2;
    float* out_loss = nullptr;
    float* out_x    = out;
    float* out_q    = nullptr;
    if ((long long)out_size == full) {
        out_loss = out;
        out_x    = out + 1;
        out_q    = out + 1 + (long long)B_SZ * G_NUM;
    }

    cudaFuncSetAttribute((const void*)gemm_mma2<2, true>,
                         cudaFuncAttributeMaxDynamicSharedMemorySize, DSMEM);
    cudaFuncSetAttribute((const void*)gemm_h16<2, true>,
                         cudaFuncAttributeMaxDynamicSharedMemorySize, HSMEM);
    cudaFuncSetAttribute((const void*)gemm_h16<0, false>,
                         cudaFuncAttributeMaxDynamicSharedMemorySize, HSMEM);

    const dim3 blk(256);

    // weight prep (independent of encoder)
    split_pairs<<<(D1 * D2 / 4 + 255) / 256, 256>>>(W4, w4h, w4l, D1 * D2 / 4);
    quant_h16 <<<(D0 * D1 / 4 + 255) / 256, 256>>>(W5, w5h, D0 * D1 / 4);
    quant_h16 <<<(G_NUM / 4 * D0 + 255) / 256, 256>>>(W6, w6h, G_NUM / 4 * D0);

    ee_kernel<<<KEMB / 8, 256>>>(E);
    init_best<<<B_SZ / 256, 256>>>();

    // encoder (bit-exact fp32 chains)
    gemm_bias_act<true><<<dim3(D0 / 128, B_SZ / 128), blk>>>(X,  W1, b1, h1, B_SZ, D0, G_NUM);
    gemm_bias_act<true><<<dim3(D1 / 128, B_SZ / 128), blk>>>(h1, W2, b2, h2, B_SZ, D1, D0);
    gemm_bias_act<true><<<dim3(D2 / 128, B_SZ / 128), blk>>>(h2, W3, b3, z,  B_SZ, D2, D1);

    // VQ (bit-exact replication of reference dist formula)
    zz_kernel<<<B_SZ / 256, 256>>>();
    vq_score<<<dim3(KEMB / 128, B_SZ / 128), blk>>>(z, E);
    gather_loss<<<B_SZ, 256>>>(E, out_q);
    if (out_loss) reduce_loss<<<1, 1024>>>(out_loss);

    // decoder: W4 bf16 3-term (keeps q->h2 accurate), W5/W6 fp16 1-term
    gemm_mma2<2, true><<<dim3(B_SZ / 128, D1 / 128), blk, DSMEM>>>(
        qh, ql, w4h, w4l, b4, h2h, nullptr, D1, D2);
    gemm_h16<2, true ><<<dim3(B_SZ / 128, D0 / 128),    blk, HSMEM>>>(
        h2h, w5h, b5, nullptr, h1h, D0, D1);
    gemm_h16<0, false><<<dim3(B_SZ / 128, G_NUM / 128), blk, HSMEM>>>(
        h1h, w6h, b6, out_x, nullptr, G_NUM, D0);
}

// round 15
// speedup vs baseline: 2.0843x; 1.0816x over previous
#include <cuda_runtime.h>
#include <cuda_bf16.h>
#include <cstdint>

#define B_SZ 4096
#define G_NUM 16384
#define D0 4096
#define D1 2048
#define D2 512
#define KEMB 8192

// -------- scratch (static device memory; no allocations) --------
__device__ float g_h1[(size_t)B_SZ * D0];        // encoder h1 (fp32)
__device__ float g_h2[(size_t)B_SZ * D1];        // encoder h2 (fp32)
__device__ float g_z [(size_t)B_SZ * D2];
__device__ float g_ee[KEMB];
__device__ float g_zz[B_SZ];
__device__ unsigned long long g_best[B_SZ];
__device__ float g_rowsum[B_SZ];

// packed pairs (u32 = 2 consecutive elements)
__device__ uint32_t g_w4h[(size_t)D1 * D2 / 2],    g_w4l[(size_t)D1 * D2 / 2];    // bf16
__device__ uint32_t g_w5h[(size_t)D0 * D1 / 2];                                    // fp16
__device__ uint32_t g_w6h[(size_t)G_NUM * D0 / 2];                                 // fp16
__device__ uint32_t g_qh [(size_t)B_SZ * D2 / 2],  g_ql [(size_t)B_SZ * D2 / 2];  // bf16
__device__ uint32_t g_h2h[(size_t)B_SZ * D1 / 2];                                  // fp16
__device__ uint32_t g_h1h[(size_t)B_SZ * D0 / 2];                                  // fp16

// ---------------- XLA/Eigen tanh f32 rational approximation ----------------
__device__ __forceinline__ float xla_tanh(float x)
{
    if (fabsf(x) < 0.0004f) return x;
    float xc = fminf(fmaxf(x, -7.90531110763549805f), 7.90531110763549805f);
    float x2 = __fmul_rn(xc, xc);
    float p = fmaf(x2, -2.76076847742355e-16f, 2.00018790482477e-13f);
    p = fmaf(x2, p, -8.60467152213735e-11f);
    p = fmaf(x2, p,  5.12229709037114e-08f);
    p = fmaf(x2, p,  1.48572235717979e-05f);
    p = fmaf(x2, p,  6.37261928875436e-04f);
    p = fmaf(x2, p,  4.89352455891786e-03f);
    p = __fmul_rn(xc, p);
    float q = fmaf(x2, 1.19825839466702e-06f, 1.18534705686654e-04f);
    q = fmaf(x2, q, 2.26843463243900e-03f);
    q = fmaf(x2, q, 4.89352518554385e-03f);
    return __fdiv_rn(p, q);
}

// ---------------- packed fp32x2 helpers ----------------
__device__ __forceinline__ void ffma2(unsigned long long& d,
                                      unsigned long long a, unsigned long long b)
{
    asm("fma.rn.f32x2 %0, %1, %2, %0;" : "+l"(d) : "l"(a), "l"(b));
}
__device__ __forceinline__ unsigned long long dup2(float a)
{
    unsigned long long r;
    asm("mov.b64 %0, {%1, %1};" : "=l"(r) : "f"(a));
    return r;
}
__device__ __forceinline__ float2 unpack2(unsigned long long v)
{
    float lo, hi;
    asm("mov.b64 {%0, %1}, %2;" : "=f"(lo), "=f"(hi) : "l"(v));
    return make_float2(lo, hi);
}

// ======================= SIMT exact-chain GEMM (encoder) =======================
__device__ __forceinline__ void sts_tile(float (&As)[16][128], float (&Bs)[16][128],
                                         int lr, int lc,
                                         float4 a0, float4 a1, float4 w0, float4 w1)
{
    As[lc + 0][lr] = a0.x; As[lc + 1][lr] = a0.y;
    As[lc + 2][lr] = a0.z; As[lc + 3][lr] = a0.w;
    As[lc + 8][lr] = a1.x; As[lc + 9][lr] = a1.y;
    As[lc +10][lr] = a1.z; As[lc +11][lr] = a1.w;
    Bs[lc + 0][lr] = w0.x; Bs[lc + 1][lr] = w0.y;
    Bs[lc + 2][lr] = w0.z; Bs[lc + 3][lr] = w0.w;
    Bs[lc + 8][lr] = w1.x; Bs[lc + 9][lr] = w1.y;
    Bs[lc +10][lr] = w1.z; Bs[lc +11][lr] = w1.w;
}

// packed-f32x2 inner product tile; each acc lane keeps its own ascending-k
// IEEE-RN FMA chain (bit-identical to scalar fmaf version).
__device__ __forceinline__ void tile_fma16p(const float (&As)[16][128],
                                            const float (&Bs)[16][128],
                                            unsigned long long (&acc)[8][4],
                                            int tx, int ty)
{
#pragma unroll
    for (int kk = 0; kk < 16; kk++) {
        float4 a0 = *(const float4*)&As[kk][ty * 8];
        float4 a1 = *(const float4*)&As[kk][ty * 8 + 4];
        ulonglong2 b01 = *(const ulonglong2*)&Bs[kk][tx * 4];
        ulonglong2 b23 = *(const ulonglong2*)&Bs[kk][64 + tx * 4];
        unsigned long long bb[4] = {b01.x, b01.y, b23.x, b23.y};
        float a[8] = {a0.x, a0.y, a0.z, a0.w, a1.x, a1.y, a1.z, a1.w};
#pragma unroll
        for (int i = 0; i < 8; i++) {
            unsigned long long ai = dup2(a[i]);
#pragma unroll
            for (int p = 0; p < 4; p++) ffma2(acc[i][p], ai, bb[p]);
        }
    }
}

__device__ __forceinline__ int col_of(int tx, int j)
{
    return (j < 4) ? (tx * 4 + j) : (64 + tx * 4 + (j - 4));
}

// view a 16-row window of a [32][128] tile
__device__ __forceinline__ float (&sub16(float* base, int buf, int half))[16][128]
{
    return *(float (*)[16][128])(base + (size_t)buf * (32 * 128) + (size_t)half * (16 * 128));
}

// 128x128x32 exact-chain SGEMM, dynamic smem 64KB, 2-phase staged loads.
// FMA chain per output element identical to the Kt=16 version (ascending k).
#define ENC_SMEM (2 * 32 * 128 * 2 * 4)   // 2 bufs * 32x128 * (A+B) * 4B = 65536
template<bool TANH>
__global__ __launch_bounds__(256, 2)
void gemm_bias_act(const float* __restrict__ A, const float* __restrict__ W,
                   const float* __restrict__ bias, float* __restrict__ C,
                   int M, int N, int K)
{
    extern __shared__ float smx[];
    float* Asb = smx;                    // [2][32][128]
    float* Bsb = smx + 2 * 32 * 128;     // [2][32][128]
    const int t  = threadIdx.x;
    const int tx = t & 15, ty = t >> 4;
    const int m0 = blockIdx.y * 128, n0 = blockIdx.x * 128;
    const int lr = t >> 1;
    const int lc = (t & 1) * 4;
    const float* Aptr = A + (size_t)(m0 + lr) * K + lc;
    const float* Wptr = W + (size_t)(n0 + lr) * K + lc;

    unsigned long long acc[8][4];
#pragma unroll
    for (int i = 0; i < 8; i++)
#pragma unroll
        for (int p = 0; p < 4; p++) acc[i][p] = 0ull;

    // prologue: tile 0 (both halves)
    {
        float4 a0 = *(const float4*)(Aptr);
        float4 a1 = *(const float4*)(Aptr + 8);
        float4 w0 = *(const float4*)(Wptr);
        float4 w1 = *(const float4*)(Wptr + 8);
        sts_tile(sub16(Asb, 0, 0), sub16(Bsb, 0, 0), lr, lc, a0, a1, w0, w1);
        a0 = *(const float4*)(Aptr + 16);
        a1 = *(const float4*)(Aptr + 24);
        w0 = *(const float4*)(Wptr + 16);
        w1 = *(const float4*)(Wptr + 24);
        sts_tile(sub16(Asb, 0, 1), sub16(Bsb, 0, 1), lr, lc, a0, a1, w0, w1);
    }
    __syncthreads();

    int cur = 0;
    for (int k0 = 32; k0 < K; k0 += 32) {
        const int nxt = cur ^ 1;
        float4 a0 = *(const float4*)(Aptr + k0);
        float4 a1 = *(const float4*)(Aptr + k0 + 8);
        float4 w0 = *(const float4*)(Wptr + k0);
        float4 w1 = *(const float4*)(Wptr + k0 + 8);
        tile_fma16p(sub16(Asb, cur, 0), sub16(Bsb, cur, 0), acc, tx, ty);
        sts_tile(sub16(Asb, nxt, 0), sub16(Bsb, nxt, 0), lr, lc, a0, a1, w0, w1);
        a0 = *(const float4*)(Aptr + k0 + 16);
        a1 = *(const float4*)(Aptr + k0 + 24);
        w0 = *(const float4*)(Wptr + k0 + 16);
        w1 = *(const float4*)(Wptr + k0 + 24);
        tile_fma16p(sub16(Asb, cur, 1), sub16(Bsb, cur, 1), acc, tx, ty);
        sts_tile(sub16(Asb, nxt, 1), sub16(Bsb, nxt, 1), lr, lc, a0, a1, w0, w1);
        __syncthreads();
        cur = nxt;
    }
    tile_fma16p(sub16(Asb, cur, 0), sub16(Bsb, cur, 0), acc, tx, ty);
    tile_fma16p(sub16(Asb, cur, 1), sub16(Bsb, cur, 1), acc, tx, ty);

#pragma unroll
    for (int i = 0; i < 8; i++) {
        const int m = m0 + ty * 8 + i;
#pragma unroll
        for (int p = 0; p < 4; p++) {
            float2 pr = unpack2(acc[i][p]);
#pragma unroll
            for (int h = 0; h < 2; h++) {
                const int j = 2 * p + h;
                const int n = n0 + col_of(tx, j);
                float v = __fadd_rn(h ? pr.y : pr.x, bias[n]);
                if (TANH) v = xla_tanh(v);
                C[(size_t)m * N + n] = v;
            }
        }
    }
}

// ======================= conversion helpers =======================
// split fp32 pair -> bf16x2 hi + bf16x2 residual (packed u32 each)
__device__ __forceinline__ void split2(float f0, float f1, uint32_t& hi, uint32_t& lo)
{
    asm("cvt.rn.bf16x2.f32 %0, %1, %2;" : "=r"(hi) : "f"(f1), "f"(f0));
    float h0 = __uint_as_float(hi << 16);
    float h1 = __uint_as_float(hi & 0xFFFF0000u);
    float r0 = __fadd_rn(f0, -h0);
    float r1 = __fadd_rn(f1, -h1);
    asm("cvt.rn.bf16x2.f32 %0, %1, %2;" : "=r"(lo) : "f"(r1), "f"(r0));
}

__device__ __forceinline__ uint32_t cvt_h2(float f0, float f1)
{
    uint32_t r;
    asm("cvt.rn.f16x2.f32 %0, %1, %2;" : "=r"(r) : "f"(f1), "f"(f0));
    return r;
}

// elementwise weight split: W fp32 -> packed bf16 hi/lo pair arrays
__global__ void split_pairs(const float* __restrict__ W, uint32_t* __restrict__ Wh,
                            uint32_t* __restrict__ Wl, int n4)
{
    int i = blockIdx.x * 256 + threadIdx.x;
    if (i >= n4) return;
    float4 v = ((const float4*)W)[i];
    uint32_t h0, l0, h1, l1;
    split2(v.x, v.y, h0, l0);
    split2(v.z, v.w, h1, l1);
    ((uint2*)Wh)[i] = make_uint2(h0, h1);
    ((uint2*)Wl)[i] = make_uint2(l0, l1);
}

// elementwise fp16 quantization (no residual): W fp32 -> packed f16 pairs
__global__ void quant_h16(const float* __restrict__ W, uint32_t* __restrict__ Wh, int n4)
{
    int i = blockIdx.x * 256 + threadIdx.x;
    if (i >= n4) return;
    float4 v = ((const float4*)W)[i];
    ((uint2*)Wh)[i] = make_uint2(cvt_h2(v.x, v.y), cvt_h2(v.z, v.w));
}

// ======================= HMMA decoder GEMMs =======================
__device__ __forceinline__ uint32_t smem_u32(const void* p)
{
    uint32_t a;
    asm("{ .reg .u64 t; cvta.to.shared.u64 t, %1; cvt.u32.u64 %0, t; }"
        : "=r"(a) : "l"(p));
    return a;
}

__device__ __forceinline__ void mma_bf16(float* c, const uint32_t* a, const uint32_t* b)
{
    asm volatile(
        "mma.sync.aligned.m16n8k16.row.col.f32.bf16.bf16.f32 "
        "{%0,%1,%2,%3}, {%4,%5,%6,%7}, {%8,%9}, {%0,%1,%2,%3};"
        : "+f"(c[0]), "+f"(c[1]), "+f"(c[2]), "+f"(c[3])
        : "r"(a[0]), "r"(a[1]), "r"(a[2]), "r"(a[3]), "r"(b[0]), "r"(b[1]));
}

__device__ __forceinline__ void mma_f16(float* c, const uint32_t* a, const uint32_t* b)
{
    asm volatile(
        "mma.sync.aligned.m16n8k16.row.col.f32.f16.f16.f32 "
        "{%0,%1,%2,%3}, {%4,%5,%6,%7}, {%8,%9}, {%0,%1,%2,%3};"
        : "+f"(c[0]), "+f"(c[1]), "+f"(c[2]), "+f"(c[3])
        : "r"(a[0]), "r"(a[1]), "r"(a[2]), "r"(a[3]), "r"(b[0]), "r"(b[1]));
}

__device__ __forceinline__ void ldmx4(uint32_t* r, uint32_t a)
{
    asm volatile("ldmatrix.sync.aligned.m8n8.x4.shared.b16 {%0,%1,%2,%3}, [%4];"
                 : "=r"(r[0]), "=r"(r[1]), "=r"(r[2]), "=r"(r[3]) : "r"(a));
}
__device__ __forceinline__ void ldmx2(uint32_t* r, uint32_t a)
{
    asm volatile("ldmatrix.sync.aligned.m8n8.x2.shared.b16 {%0,%1}, [%2];"
                 : "=r"(r[0]), "=r"(r[1]) : "r"(a));
}
__device__ __forceinline__ void sts128(uint32_t a, uint4 v)
{
    asm volatile("st.shared.v4.u32 [%0], {%1,%2,%3,%4};"
                 :: "r"(a), "r"(v.x), "r"(v.y), "r"(v.z), "r"(v.w));
}

// ---- bf16 3-term split GEMM (W4) ----
#define DSTRIDE 80
#define DTILE  (128 * DSTRIDE)   // 10240
#define DBUF   (4 * DTILE)       // 40960
#define DSMEM  (2 * DBUF)        // 81920

// OUTMODE 2: fp16 packed out (Chp only).
template<int OUTMODE, bool TANH>
__global__ __launch_bounds__(256, 1)
void gemm_mma2(const uint32_t* __restrict__ Ahp, const uint32_t* __restrict__ Alp,
               const uint32_t* __restrict__ Bhp, const uint32_t* __restrict__ Blp,
               const float* __restrict__ bias,
               uint32_t* __restrict__ Chp, uint32_t* __restrict__ Clp,
               int N, int K)
{
    extern __shared__ char sm[];
    const uint32_t sb = smem_u32(sm);
    const int t    = threadIdx.x;
    const int lane = t & 31;
    const int wid  = t >> 5;
    const int wm   = (wid >> 2) * 64;
    const int wn   = (wid & 3) * 32;
    const int m0   = blockIdx.x * 128;
    const int n0   = blockIdx.y * 128;
    const int Kp   = K >> 1;

    const int tile = t >> 6, u = t & 63;
    const uint32_t* src = (tile == 0) ? Ahp : (tile == 1) ? Alp : (tile == 2) ? Bhp : Blp;
    const int grow = ((tile < 2) ? m0 : n0) + 2 * u;
    const uint32_t* g0 = src + (size_t)grow * Kp;
    const uint32_t* g1 = g0 + Kp;
    const uint32_t dstr = (uint32_t)(tile * DTILE + (2 * u) * DSTRIDE);

    float acc[4][4][4];
#pragma unroll
    for (int i = 0; i < 4; i++)
#pragma unroll
        for (int j = 0; j < 4; j++)
#pragma unroll
            for (int r = 0; r < 4; r++) acc[i][j][r] = 0.f;

    const int nslab = K >> 5;
    uint4 pf[8];
#pragma unroll
    for (int c = 0; c < 4; c++) {
        pf[c]     = ((const uint4*)g0)[c];
        pf[4 + c] = ((const uint4*)g1)[c];
    }

    const uint32_t a_lane = (uint32_t)((wm + (lane & 7) + ((lane >> 3) & 1) * 8) * DSTRIDE
                                       + (lane >> 4) * 16);
    const uint32_t b_lane = (uint32_t)((wn + (lane & 7)) * DSTRIDE
                                       + ((lane >> 3) & 1) * 16);

    for (int s = 0; s < nslab; s++) {
        const uint32_t buf = sb + (uint32_t)(s & 1) * DBUF;
        const uint32_t da  = buf + dstr;
#pragma unroll
        for (int c = 0; c < 4; c++) {
            sts128(da + c * 16,           pf[c]);
            sts128(da + DSTRIDE + c * 16, pf[4 + c]);
        }
        if (s + 1 < nslab) {
            const uint4* n0p = (const uint4*)(g0 + (s + 1) * 16);
            const uint4* n1p = (const uint4*)(g1 + (s + 1) * 16);
#pragma unroll
            for (int c = 0; c < 4; c++) { pf[c] = n0p[c]; pf[4 + c] = n1p[c]; }
        }
        __syncthreads();

        const uint32_t Ath = buf;
        const uint32_t Atl = buf + DTILE;
        const uint32_t Bth = buf + 2 * DTILE;
        const uint32_t Btl = buf + 3 * DTILE;
#pragma unroll
        for (int ks = 0; ks < 2; ks++) {
            uint32_t ah[4][4], al[4][4], bh[4][2], bl[4][2];
#pragma unroll
            for (int mt = 0; mt < 4; mt++) {
                const uint32_t off = a_lane + (uint32_t)(mt * 16 * DSTRIDE + ks * 32);
                ldmx4(ah[mt], Ath + off);
                ldmx4(al[mt], Atl + off);
            }
#pragma unroll
            for (int nt = 0; nt < 4; nt++) {
                const uint32_t off = b_lane + (uint32_t)(nt * 8 * DSTRIDE + ks * 32);
                ldmx2(bh[nt], Bth + off);
                ldmx2(bl[nt], Btl + off);
            }
#pragma unroll
            for (int mt = 0; mt < 4; mt++)
#pragma unroll
                for (int nt = 0; nt < 4; nt++)
                    mma_bf16(acc[mt][nt], ah[mt], bh[nt]);     // A1*B1
#pragma unroll
            for (int mt = 0; mt < 4; mt++)
#pragma unroll
                for (int nt = 0; nt < 4; nt++)
                    mma_bf16(acc[mt][nt], ah[mt], bl[nt]);     // A1*B2
#pragma unroll
            for (int mt = 0; mt < 4; mt++)
#pragma unroll
                for (int nt = 0; nt < 4; nt++)
                    mma_bf16(acc[mt][nt], al[mt], bh[nt]);     // A2*B1
        }
    }

#pragma unroll
    for (int mt = 0; mt < 4; mt++) {
        const int mr = m0 + wm + mt * 16 + (lane >> 2);
#pragma unroll
        for (int nt = 0; nt < 4; nt++) {
            const int nc = n0 + wn + nt * 8 + (lane & 3) * 2;
            const float b0 = bias[nc], b1 = bias[nc + 1];
            float v0 = __fadd_rn(acc[mt][nt][0], b0);
            float v1 = __fadd_rn(acc[mt][nt][1], b1);
            float v2 = __fadd_rn(acc[mt][nt][2], b0);
            float v3 = __fadd_rn(acc[mt][nt][3], b1);
            if (TANH) { v0 = xla_tanh(v0); v1 = xla_tanh(v1); v2 = xla_tanh(v2); v3 = xla_tanh(v3); }
            const size_t i0 = (size_t)mr * (N >> 1) + (nc >> 1);
            const size_t i1 = (size_t)(mr + 8) * (N >> 1) + (nc >> 1);
            if (OUTMODE == 1) {
                uint32_t hi, lo;
                split2(v0, v1, hi, lo); Chp[i0] = hi; Clp[i0] = lo;
                split2(v2, v3, hi, lo); Chp[i1] = hi; Clp[i1] = lo;
            } else {
                Chp[i0] = cvt_h2(v0, v1);
                Chp[i1] = cvt_h2(v2, v3);
            }
        }
    }
}

// ---- fp16 single-term GEMM (W5, W6) ----
#define HSTRIDE 80
#define HTILE  (128 * HSTRIDE)   // 10240
#define HBUF   (2 * HTILE)       // 20480 (A + B)
#define HSMEM  (2 * HBUF)        // 40960

// OUTMODE 0: fp32 scalar C (x_recon; may be 4B-aligned). OUTMODE 2: fp16 packed Chp.
template<int OUTMODE, bool TANH>
__global__ __launch_bounds__(256, 1)
void gemm_h16(const uint32_t* __restrict__ Ah, const uint32_t* __restrict__ Bh,
              const float* __restrict__ bias, float* __restrict__ C,
              uint32_t* __restrict__ Chp, int N, int K)
{
    extern __shared__ char sm[];
    const uint32_t sb = smem_u32(sm);
    const int t    = threadIdx.x;
    const int lane = t & 31;
    const int wid  = t >> 5;
    const int wm   = (wid >> 2) * 64;
    const int wn   = (wid & 3) * 32;
    const int m0   = blockIdx.x * 128;
    const int n0   = blockIdx.y * 128;
    const int Kp   = K >> 1;

    const int tile = t >> 7, u = t & 127;
    const uint32_t* g = tile ? (Bh + (size_t)(n0 + u) * Kp)
                             : (Ah + (size_t)(m0 + u) * Kp);
    const uint32_t dstr = (uint32_t)(tile * HTILE + u * HSTRIDE);

    float acc[4][4][4];
#pragma unroll
    for (int i = 0; i < 4; i++)
#pragma unroll
        for (int j = 0; j < 4; j++)
#pragma unroll
            for (int r = 0; r < 4; r++) acc[i][j][r] = 0.f;

    const int nslab = K >> 5;
    uint4 pf[4];
#pragma unroll
    for (int c = 0; c < 4; c++) pf[c] = ((const uint4*)g)[c];

    const uint32_t a_lane = (uint32_t)((wm + (lane & 7) + ((lane >> 3) & 1) * 8) * HSTRIDE
                                       + (lane >> 4) * 16);
    const uint32_t b_lane = (uint32_t)((wn + (lane & 7)) * HSTRIDE
                                       + ((lane >> 3) & 1) * 16);

    for (int s = 0; s < nslab; s++) {
        const uint32_t buf = sb + (uint32_t)(s & 1) * HBUF;
        const uint32_t da  = buf + dstr;
#pragma unroll
        for (int c = 0; c < 4; c++) sts128(da + c * 16, pf[c]);
        if (s + 1 < nslab) {
            const uint4* np = (const uint4*)(g + (s + 1) * 16);
#pragma unroll
            for (int c = 0; c < 4; c++) pf[c] = np[c];
        }
        __syncthreads();

        const uint32_t Ath = buf;
        const uint32_t Bth = buf + HTILE;
#pragma unroll
        for (int ks = 0; ks < 2; ks++) {
            uint32_t ah[4][4], bh[4][2];
#pragma unroll
            for (int mt = 0; mt < 4; mt++)
                ldmx4(ah[mt], Ath + a_lane + (uint32_t)(mt * 16 * HSTRIDE + ks * 32));
#pragma unroll
            for (int nt = 0; nt < 4; nt++)
                ldmx2(bh[nt], Bth + b_lane + (uint32_t)(nt * 8 * HSTRIDE + ks * 32));
#pragma unroll
            for (int mt = 0; mt < 4; mt++)
#pragma unroll
                for (int nt = 0; nt < 4; nt++)
                    mma_f16(acc[mt][nt], ah[mt], bh[nt]);
        }
    }

#pragma unroll
    for (int mt = 0; mt < 4; mt++) {
        const int mr = m0 + wm + mt * 16 + (lane >> 2);
#pragma unroll
        for (int nt = 0; nt < 4; nt++) {
            const int nc = n0 + wn + nt * 8 + (lane & 3) * 2;
            float v0 = __fadd_rn(acc[mt][nt][0], bias[nc]);
            float v1 = __fadd_rn(acc[mt][nt][1], bias[nc + 1]);
            float v2 = __fadd_rn(acc[mt][nt][2], bias[nc]);
            float v3 = __fadd_rn(acc[mt][nt][3], bias[nc + 1]);
            if (TANH) { v0 = xla_tanh(v0); v1 = xla_tanh(v1); v2 = xla_tanh(v2); v3 = xla_tanh(v3); }
            if (OUTMODE == 0) {
                float* r0 = &C[(size_t)mr * N + nc];
                float* r1 = &C[(size_t)(mr + 8) * N + nc];
                r0[0] = v0; r0[1] = v1;
                r1[0] = v2; r1[1] = v3;
            } else {
                Chp[(size_t)mr * (N >> 1) + (nc >> 1)]       = cvt_h2(v0, v1);
                Chp[(size_t)(mr + 8) * (N >> 1) + (nc >> 1)] = cvt_h2(v2, v3);
            }
        }
    }
}

// ======================= VQ / misc kernels (bit-exact path, unchanged) =======================
__global__ void ee_kernel(const float* __restrict__ E)
{
    const int row  = blockIdx.x * 8 + (threadIdx.x >> 5);
    const int lane = threadIdx.x & 31;
    const float* e = E + (size_t)row * D2;
    float s = 0.f;
    for (int j = lane; j < D2; j += 32)
        s = __fadd_rn(s, __fmul_rn(e[j], e[j]));
#pragma unroll
    for (int o = 16; o; o >>= 1) s = __fadd_rn(s, __shfl_xor_sync(0xffffffffu, s, o));
    if (lane == 0) g_ee[row] = s;
}

__global__ void zz_kernel()
{
    const int m = blockIdx.x * 256 + threadIdx.x;
    if (m >= B_SZ) return;
    const float* z = g_z + (size_t)m * D2;
    float s = 0.f;
    for (int k = 0; k < D2; k++)
        s = __fadd_rn(s, __fmul_rn(z[k], z[k]));
    g_zz[m] = s;
}

__global__ void init_best()
{
    int i = blockIdx.x * 256 + threadIdx.x;
    if (i < B_SZ) g_best[i] = ~0ull;
}

__device__ __forceinline__ unsigned int orderable_f32(float f)
{
    unsigned int u = __float_as_uint(f);
    return (u & 0x80000000u) ? ~u : (u | 0x80000000u);
}

__global__ __launch_bounds__(256, 2)
void vq_score(const float* __restrict__ Z, const float* __restrict__ E)
{
    __shared__ float As[2][16][128];
    __shared__ float Bs[2][16][128];
    const int t  = threadIdx.x;
    const int tx = t & 15, ty = t >> 4;
    const int m0 = blockIdx.y * 128, n0 = blockIdx.x * 128;
    const int lr = t >> 1;
    const int lc = (t & 1) * 4;
    const float* Aptr = Z + (size_t)(m0 + lr) * D2 + lc;
    const float* Wptr = E + (size_t)(n0 + lr) * D2 + lc;

    unsigned long long acc[8][4];
#pragma unroll
    for (int i = 0; i < 8; i++)
#pragma unroll
        for (int p = 0; p < 4; p++) acc[i][p] = 0ull;

    {
        float4 a0 = *(const float4*)(Aptr);
        float4 a1 = *(const float4*)(Aptr + 8);
        float4 w0 = *(const float4*)(Wptr);
        float4 w1 = *(const float4*)(Wptr + 8);
        sts_tile(As[0], Bs[0], lr, lc, a0, a1, w0, w1);
    }
    __syncthreads();

    int cur = 0;
    for (int k0 = 16; k0 < D2; k0 += 16) {
        float4 a0 = *(const float4*)(Aptr + k0);
        float4 a1 = *(const float4*)(Aptr + k0 + 8);
        float4 w0 = *(const float4*)(Wptr + k0);
        float4 w1 = *(const float4*)(Wptr + k0 + 8);
        tile_fma16p(As[cur], Bs[cur], acc, tx, ty);
        sts_tile(As[cur ^ 1], Bs[cur ^ 1], lr, lc, a0, a1, w0, w1);
        __syncthreads();
        cur ^= 1;
    }
    tile_fma16p(As[cur], Bs[cur], acc, tx, ty);

#pragma unroll
    for (int i = 0; i < 8; i++) {
        const int m = m0 + ty * 8 + i;
        const float zzm = g_zz[m];
        unsigned long long best = ~0ull;
#pragma unroll
        for (int p = 0; p < 4; p++) {
            float2 pr = unpack2(acc[i][p]);
#pragma unroll
            for (int h = 0; h < 2; h++) {
                const int j = 2 * p + h;
                const int n = n0 + col_of(tx, j);
                const float s    = h ? pr.y : pr.x;
                const float zze  = __fadd_rn(zzm, g_ee[n]);
                const float twos = __fmul_rn(2.f, s);
                const float d    = __fadd_rn(zze, -twos);
                unsigned long long key =
                    ((unsigned long long)orderable_f32(d) << 32) | (unsigned int)n;
                best = (key < best) ? key : best;
            }
        }
#pragma unroll
        for (int o = 8; o; o >>= 1) {
            unsigned long long other = __shfl_xor_sync(0xffffffffu, best, o);
            best = (other < best) ? other : best;
        }
        if (tx == 0) atomicMin(&g_best[m], best);
    }
}

// gather q = E[idx]: emit q_st fp32 output + packed bf16 splits + loss partials
__global__ void gather_loss(const float* __restrict__ E, float* __restrict__ out_q)
{
    const int m   = blockIdx.x;
    const int idx = (int)(unsigned int)(g_best[m] & 0xFFFFFFFFull);
    const float* e = E + (size_t)idx * D2;
    const float* z = g_z + (size_t)m * D2;
    const int j = threadIdx.x * 2;
    float q0 = e[j], q1 = e[j + 1];
    float d0 = q0 - z[j], d1 = q1 - z[j + 1];
    float s = fmaf(d1, d1, d0 * d0);
    uint32_t hi, lo;
    split2(q0, q1, hi, lo);
    const size_t pi = ((size_t)m * D2 + j) >> 1;
    g_qh[pi] = hi; g_ql[pi] = lo;
    if (out_q) { out_q[(size_t)m * D2 + j] = q0; out_q[(size_t)m * D2 + j + 1] = q1; }

    __shared__ float red[256];
    red[threadIdx.x] = s;
    __syncthreads();
    for (int o = 128; o; o >>= 1) {
        if (threadIdx.x < o) red[threadIdx.x] += red[threadIdx.x + o];
        __syncthreads();
    }
    if (threadIdx.x == 0) g_rowsum[m] = red[0];
}

__global__ void reduce_loss(float* __restrict__ out_loss)
{
    __shared__ float red[1024];
    float s = 0.f;
    for (int i = threadIdx.x; i < B_SZ; i += 1024) s += g_rowsum[i];
    red[threadIdx.x] = s;
    __syncthreads();
    for (int o = 512; o; o >>= 1) {
        if (threadIdx.x < o) red[threadIdx.x] += red[threadIdx.x + o];
        __syncthreads();
    }
    if (threadIdx.x == 0)
        out_loss[0] = red[0] * (1.25f / (float)((size_t)B_SZ * D2));
}

// ----------------------------------------------------------------
extern "C" void kernel_launch(void* const* d_in, const int* in_sizes, int n_in,
                              void* d_out, int out_size)
{
    const float* X  = (const float*)d_in[0];
    const float* W1 = (const float*)d_in[1];
    const float* b1 = (const float*)d_in[2];
    const float* W2 = (const float*)d_in[3];
    const float* b2 = (const float*)d_in[4];
    const float* W3 = (const float*)d_in[5];
    const float* b3 = (const float*)d_in[6];
    const float* E  = (const float*)d_in[7];
    const float* W4 = (const float*)d_in[8];
    const float* b4 = (const float*)d_in[9];
    const float* W5 = (const float*)d_in[10];
    const float* b5 = (const float*)d_in[11];
    const float* W6 = (const float*)d_in[12];
    const float* b6 = (const float*)d_in[13];

    float *h1, *h2, *z;
    cudaGetSymbolAddress((void**)&h1, g_h1);
    cudaGetSymbolAddress((void**)&h2, g_h2);
    cudaGetSymbolAddress((void**)&z,  g_z);
    uint32_t *w4h, *w4l, *w5h, *w6h, *qh, *ql, *h2h, *h1h;
    cudaGetSymbolAddress((void**)&w4h, g_w4h); cudaGetSymbolAddress((void**)&w4l, g_w4l);
    cudaGetSymbolAddress((void**)&w5h, g_w5h);
    cudaGetSymbolAddress((void**)&w6h, g_w6h);
    cudaGetSymbolAddress((void**)&qh,  g_qh);  cudaGetSymbolAddress((void**)&ql,  g_ql);
    cudaGetSymbolAddress((void**)&h2h, g_h2h);
    cudaGetSymbolAddress((void**)&h1h, g_h1h);

    float* out = (float*)d_out;
    const long long full = 1LL + (long long)B_SZ * G_NUM + (long long)B_SZ * D2;
    float* out_loss = nullptr;
    float* out_x    = out;
    float* out_q    = nullptr;
    if ((long long)out_size == full) {
        out_loss = out;
        out_x    = out + 1;
        out_q    = out + 1 + (long long)B_SZ * G_NUM;
    }

    cudaFuncSetAttribute((const void*)gemm_bias_act<true>,
                         cudaFuncAttributeMaxDynamicSharedMemorySize, ENC_SMEM);
    cudaFuncSetAttribute((const void*)gemm_mma2<2, true>,
                         cudaFuncAttributeMaxDynamicSharedMemorySize, DSMEM);
    cudaFuncSetAttribute((const void*)gemm_h16<2, true>,
                         cudaFuncAttributeMaxDynamicSharedMemorySize, HSMEM);
    cudaFuncSetAttribute((const void*)gemm_h16<0, false>,
                         cudaFuncAttributeMaxDynamicSharedMemorySize, HSMEM);

    const dim3 blk(256);

    // weight prep (independent of encoder)
    split_pairs<<<(D1 * D2 / 4 + 255) / 256, 256>>>(W4, w4h, w4l, D1 * D2 / 4);
    quant_h16 <<<(D0 * D1 / 4 + 255) / 256, 256>>>(W5, w5h, D0 * D1 / 4);
    quant_h16 <<<(G_NUM / 4 * D0 + 255) / 256, 256>>>(W6, w6h, G_NUM / 4 * D0);

    ee_kernel<<<KEMB / 8, 256>>>(E);
    init_best<<<B_SZ / 256, 256>>>();

    // encoder (bit-exact fp32 chains; Kt=32 staged double-buffer)
    gemm_bias_act<true><<<dim3(D0 / 128, B_SZ / 128), blk, ENC_SMEM>>>(X,  W1, b1, h1, B_SZ, D0, G_NUM);
    gemm_bias_act<true><<<dim3(D1 / 128, B_SZ / 128), blk, ENC_SMEM>>>(h1, W2, b2, h2, B_SZ, D1, D0);
    gemm_bias_act<true><<<dim3(D2 / 128, B_SZ / 128), blk, ENC_SMEM>>>(h2, W3, b3, z,  B_SZ, D2, D1);

    // VQ (bit-exact replication of reference dist formula)
    zz_kernel<<<B_SZ / 256, 256>>>();
    vq_score<<<dim3(KEMB / 128, B_SZ / 128), blk>>>(z, E);
    gather_loss<<<B_SZ, 256>>>(E, out_q);
    if (out_loss) reduce_loss<<<1, 1024>>>(out_loss);

    // decoder: W4 bf16 3-term (keeps q->h2 accurate), W5/W6 fp16 1-term
    gemm_mma2<2, true><<<dim3(B_SZ / 128, D1 / 128), blk, DSMEM>>>(
        qh, ql, w4h, w4l, b4, h2h, nullptr, D1, D2);
    gemm_h16<2, true ><<<dim3(B_SZ / 128, D0 / 128),    blk, HSMEM>>>(
        h2h, w5h, b5, nullptr, h1h, D0, D1);
    gemm_h16<0, false><<<dim3(B_SZ / 128, G_NUM / 128), blk, HSMEM>>>(
        h1h, w6h, b6, out_x, nullptr, G_NUM, D0);
}

// round 16
// speedup vs baseline: 2.1360x; 1.0248x over previous
#include <cuda_runtime.h>
#include <cuda_bf16.h>
#include <cstdint>

#define B_SZ 4096
#define G_NUM 16384
#define D0 4096
#define D1 2048
#define D2 512
#define KEMB 8192

// -------- scratch (static device memory; no allocations) --------
__device__ float g_h1[(size_t)B_SZ * D0];        // encoder h1 (fp32)
__device__ float g_h2[(size_t)B_SZ * D1];        // encoder h2 (fp32)
__device__ float g_z [(size_t)B_SZ * D2];
__device__ float g_ee[KEMB];
__device__ float g_zz[B_SZ];
__device__ unsigned long long g_best[B_SZ];
__device__ float g_rowsum[B_SZ];

// packed fp16 pairs (u32 = 2 consecutive elements)
__device__ uint32_t g_w4h[(size_t)D1 * D2 / 2];
__device__ uint32_t g_w5h[(size_t)D0 * D1 / 2];
__device__ uint32_t g_w6h[(size_t)G_NUM * D0 / 2];
__device__ uint32_t g_qh [(size_t)B_SZ * D2 / 2];
__device__ uint32_t g_h2h[(size_t)B_SZ * D1 / 2];
__device__ uint32_t g_h1h[(size_t)B_SZ * D0 / 2];

// ---------------- XLA/Eigen tanh f32 rational approximation ----------------
__device__ __forceinline__ float xla_tanh(float x)
{
    if (fabsf(x) < 0.0004f) return x;
    float xc = fminf(fmaxf(x, -7.90531110763549805f), 7.90531110763549805f);
    float x2 = __fmul_rn(xc, xc);
    float p = fmaf(x2, -2.76076847742355e-16f, 2.00018790482477e-13f);
    p = fmaf(x2, p, -8.60467152213735e-11f);
    p = fmaf(x2, p,  5.12229709037114e-08f);
    p = fmaf(x2, p,  1.48572235717979e-05f);
    p = fmaf(x2, p,  6.37261928875436e-04f);
    p = fmaf(x2, p,  4.89352455891786e-03f);
    p = __fmul_rn(xc, p);
    float q = fmaf(x2, 1.19825839466702e-06f, 1.18534705686654e-04f);
    q = fmaf(x2, q, 2.26843463243900e-03f);
    q = fmaf(x2, q, 4.89352518554385e-03f);
    return __fdiv_rn(p, q);
}

// ---------------- packed fp32x2 helpers ----------------
__device__ __forceinline__ void ffma2(unsigned long long& d,
                                      unsigned long long a, unsigned long long b)
{
    asm("fma.rn.f32x2 %0, %1, %2, %0;" : "+l"(d) : "l"(a), "l"(b));
}
__device__ __forceinline__ unsigned long long dup2(float a)
{
    unsigned long long r;
    asm("mov.b64 %0, {%1, %1};" : "=l"(r) : "f"(a));
    return r;
}
__device__ __forceinline__ float2 unpack2(unsigned long long v)
{
    float lo, hi;
    asm("mov.b64 {%0, %1}, %2;" : "=f"(lo), "=f"(hi) : "l"(v));
    return make_float2(lo, hi);
}

// ======================= SIMT exact-chain GEMM (encoder) =======================
__device__ __forceinline__ void sts_tile(float (&As)[16][128], float (&Bs)[16][128],
                                         int lr, int lc,
                                         float4 a0, float4 a1, float4 w0, float4 w1)
{
    As[lc + 0][lr] = a0.x; As[lc + 1][lr] = a0.y;
    As[lc + 2][lr] = a0.z; As[lc + 3][lr] = a0.w;
    As[lc + 8][lr] = a1.x; As[lc + 9][lr] = a1.y;
    As[lc +10][lr] = a1.z; As[lc +11][lr] = a1.w;
    Bs[lc + 0][lr] = w0.x; Bs[lc + 1][lr] = w0.y;
    Bs[lc + 2][lr] = w0.z; Bs[lc + 3][lr] = w0.w;
    Bs[lc + 8][lr] = w1.x; Bs[lc + 9][lr] = w1.y;
    Bs[lc +10][lr] = w1.z; Bs[lc +11][lr] = w1.w;
}

// packed-f32x2 inner product tile; each acc lane keeps its own ascending-k
// IEEE-RN FMA chain (bit-identical to scalar fmaf version).
__device__ __forceinline__ void tile_fma16p(const float (&As)[16][128],
                                            const float (&Bs)[16][128],
                                            unsigned long long (&acc)[8][4],
                                            int tx, int ty)
{
#pragma unroll
    for (int kk = 0; kk < 16; kk++) {
        float4 a0 = *(const float4*)&As[kk][ty * 8];
        float4 a1 = *(const float4*)&As[kk][ty * 8 + 4];
        ulonglong2 b01 = *(const ulonglong2*)&Bs[kk][tx * 4];
        ulonglong2 b23 = *(const ulonglong2*)&Bs[kk][64 + tx * 4];
        unsigned long long bb[4] = {b01.x, b01.y, b23.x, b23.y};
        float a[8] = {a0.x, a0.y, a0.z, a0.w, a1.x, a1.y, a1.z, a1.w};
#pragma unroll
        for (int i = 0; i < 8; i++) {
            unsigned long long ai = dup2(a[i]);
#pragma unroll
            for (int p = 0; p < 4; p++) ffma2(acc[i][p], ai, bb[p]);
        }
    }
}

__device__ __forceinline__ int col_of(int tx, int j)
{
    return (j < 4) ? (tx * 4 + j) : (64 + tx * 4 + (j - 4));
}

// view a 16-row window of a [32][128] tile
__device__ __forceinline__ float (&sub16(float* base, int buf, int half))[16][128]
{
    return *(float (*)[16][128])(base + (size_t)buf * (32 * 128) + (size_t)half * (16 * 128));
}

// 128x128x32 exact-chain SGEMM, dynamic smem 64KB, 2-phase staged loads.
#define ENC_SMEM (2 * 32 * 128 * 2 * 4)   // 65536
template<bool TANH>
__global__ __launch_bounds__(256, 2)
void gemm_bias_act(const float* __restrict__ A, const float* __restrict__ W,
                   const float* __restrict__ bias, float* __restrict__ C,
                   int M, int N, int K)
{
    extern __shared__ float smx[];
    float* Asb = smx;                    // [2][32][128]
    float* Bsb = smx + 2 * 32 * 128;     // [2][32][128]
    const int t  = threadIdx.x;
    const int tx = t & 15, ty = t >> 4;
    const int m0 = blockIdx.y * 128, n0 = blockIdx.x * 128;
    const int lr = t >> 1;
    const int lc = (t & 1) * 4;
    const float* Aptr = A + (size_t)(m0 + lr) * K + lc;
    const float* Wptr = W + (size_t)(n0 + lr) * K + lc;

    unsigned long long acc[8][4];
#pragma unroll
    for (int i = 0; i < 8; i++)
#pragma unroll
        for (int p = 0; p < 4; p++) acc[i][p] = 0ull;

    {
        float4 a0 = *(const float4*)(Aptr);
        float4 a1 = *(const float4*)(Aptr + 8);
        float4 w0 = *(const float4*)(Wptr);
        float4 w1 = *(const float4*)(Wptr + 8);
        sts_tile(sub16(Asb, 0, 0), sub16(Bsb, 0, 0), lr, lc, a0, a1, w0, w1);
        a0 = *(const float4*)(Aptr + 16);
        a1 = *(const float4*)(Aptr + 24);
        w0 = *(const float4*)(Wptr + 16);
        w1 = *(const float4*)(Wptr + 24);
        sts_tile(sub16(Asb, 0, 1), sub16(Bsb, 0, 1), lr, lc, a0, a1, w0, w1);
    }
    __syncthreads();

    int cur = 0;
    for (int k0 = 32; k0 < K; k0 += 32) {
        const int nxt = cur ^ 1;
        float4 a0 = *(const float4*)(Aptr + k0);
        float4 a1 = *(const float4*)(Aptr + k0 + 8);
        float4 w0 = *(const float4*)(Wptr + k0);
        float4 w1 = *(const float4*)(Wptr + k0 + 8);
        tile_fma16p(sub16(Asb, cur, 0), sub16(Bsb, cur, 0), acc, tx, ty);
        sts_tile(sub16(Asb, nxt, 0), sub16(Bsb, nxt, 0), lr, lc, a0, a1, w0, w1);
        a0 = *(const float4*)(Aptr + k0 + 16);
        a1 = *(const float4*)(Aptr + k0 + 24);
        w0 = *(const float4*)(Wptr + k0 + 16);
        w1 = *(const float4*)(Wptr + k0 + 24);
        tile_fma16p(sub16(Asb, cur, 1), sub16(Bsb, cur, 1), acc, tx, ty);
        sts_tile(sub16(Asb, nxt, 1), sub16(Bsb, nxt, 1), lr, lc, a0, a1, w0, w1);
        __syncthreads();
        cur = nxt;
    }
    tile_fma16p(sub16(Asb, cur, 0), sub16(Bsb, cur, 0), acc, tx, ty);
    tile_fma16p(sub16(Asb, cur, 1), sub16(Bsb, cur, 1), acc, tx, ty);

#pragma unroll
    for (int i = 0; i < 8; i++) {
        const int m = m0 + ty * 8 + i;
#pragma unroll
        for (int p = 0; p < 4; p++) {
            float2 pr = unpack2(acc[i][p]);
#pragma unroll
            for (int h = 0; h < 2; h++) {
                const int j = 2 * p + h;
                const int n = n0 + col_of(tx, j);
                float v = __fadd_rn(h ? pr.y : pr.x, bias[n]);
                if (TANH) v = xla_tanh(v);
                C[(size_t)m * N + n] = v;
            }
        }
    }
}

// ======================= conversion helpers =======================
__device__ __forceinline__ uint32_t cvt_h2(float f0, float f1)
{
    uint32_t r;
    asm("cvt.rn.f16x2.f32 %0, %1, %2;" : "=r"(r) : "f"(f1), "f"(f0));
    return r;
}

// elementwise fp16 quantization: W fp32 -> packed f16 pairs
__global__ void quant_h16(const float* __restrict__ W, uint32_t* __restrict__ Wh, int n4)
{
    int i = blockIdx.x * 256 + threadIdx.x;
    if (i >= n4) return;
    float4 v = ((const float4*)W)[i];
    ((uint2*)Wh)[i] = make_uint2(cvt_h2(v.x, v.y), cvt_h2(v.z, v.w));
}

// ======================= HMMA decoder GEMM (fp16 1-term) =======================
__device__ __forceinline__ uint32_t smem_u32(const void* p)
{
    uint32_t a;
    asm("{ .reg .u64 t; cvta.to.shared.u64 t, %1; cvt.u32.u64 %0, t; }"
        : "=r"(a) : "l"(p));
    return a;
}

__device__ __forceinline__ void mma_f16(float* c, const uint32_t* a, const uint32_t* b)
{
    asm volatile(
        "mma.sync.aligned.m16n8k16.row.col.f32.f16.f16.f32 "
        "{%0,%1,%2,%3}, {%4,%5,%6,%7}, {%8,%9}, {%0,%1,%2,%3};"
        : "+f"(c[0]), "+f"(c[1]), "+f"(c[2]), "+f"(c[3])
        : "r"(a[0]), "r"(a[1]), "r"(a[2]), "r"(a[3]), "r"(b[0]), "r"(b[1]));
}

__device__ __forceinline__ void ldmx4(uint32_t* r, uint32_t a)
{
    asm volatile("ldmatrix.sync.aligned.m8n8.x4.shared.b16 {%0,%1,%2,%3}, [%4];"
                 : "=r"(r[0]), "=r"(r[1]), "=r"(r[2]), "=r"(r[3]) : "r"(a));
}
__device__ __forceinline__ void ldmx2(uint32_t* r, uint32_t a)
{
    asm volatile("ldmatrix.sync.aligned.m8n8.x2.shared.b16 {%0,%1}, [%2];"
                 : "=r"(r[0]), "=r"(r[1]) : "r"(a));
}
__device__ __forceinline__ void sts128(uint32_t a, uint4 v)
{
    asm volatile("st.shared.v4.u32 [%0], {%1,%2,%3,%4};"
                 :: "r"(a), "r"(v.x), "r"(v.y), "r"(v.z), "r"(v.w));
}

#define HSTRIDE 80
#define HTILE  (128 * HSTRIDE)   // 10240
#define HBUF   (2 * HTILE)       // 20480 (A + B)
#define HSMEM  (2 * HBUF)        // 40960

// C = act(A @ W^T + bias); packed fp16 inputs, fp32 TMEM-free HMMA accum.
// OUTMODE 0: fp32 scalar C (x_recon; may be 4B-aligned). OUTMODE 2: fp16 packed Chp.
template<int OUTMODE, bool TANH>
__global__ __launch_bounds__(256, 2)
void gemm_h16(const uint32_t* __restrict__ Ah, const uint32_t* __restrict__ Bh,
              const float* __restrict__ bias, float* __restrict__ C,
              uint32_t* __restrict__ Chp, int N, int K)
{
    extern __shared__ char sm[];
    const uint32_t sb = smem_u32(sm);
    const int t    = threadIdx.x;
    const int lane = t & 31;
    const int wid  = t >> 5;
    const int wm   = (wid >> 2) * 64;
    const int wn   = (wid & 3) * 32;
    const int m0   = blockIdx.x * 128;
    const int n0   = blockIdx.y * 128;
    const int Kp   = K >> 1;

    const int tile = t >> 7, u = t & 127;
    const uint32_t* g = tile ? (Bh + (size_t)(n0 + u) * Kp)
                             : (Ah + (size_t)(m0 + u) * Kp);
    const uint32_t dstr = (uint32_t)(tile * HTILE + u * HSTRIDE);

    float acc[4][4][4];
#pragma unroll
    for (int i = 0; i < 4; i++)
#pragma unroll
        for (int j = 0; j < 4; j++)
#pragma unroll
            for (int r = 0; r < 4; r++) acc[i][j][r] = 0.f;

    const int nslab = K >> 5;
    uint4 pf[4];
#pragma unroll
    for (int c = 0; c < 4; c++) pf[c] = ((const uint4*)g)[c];

    const uint32_t a_lane = (uint32_t)((wm + (lane & 7) + ((lane >> 3) & 1) * 8) * HSTRIDE
                                       + (lane >> 4) * 16);
    const uint32_t b_lane = (uint32_t)((wn + (lane & 7)) * HSTRIDE
                                       + ((lane >> 3) & 1) * 16);

    for (int s = 0; s < nslab; s++) {
        const uint32_t buf = sb + (uint32_t)(s & 1) * HBUF;
        const uint32_t da  = buf + dstr;
#pragma unroll
        for (int c = 0; c < 4; c++) sts128(da + c * 16, pf[c]);
        if (s + 1 < nslab) {
            const uint4* np = (const uint4*)(g + (s + 1) * 16);
#pragma unroll
            for (int c = 0; c < 4; c++) pf[c] = np[c];
        }
        __syncthreads();

        const uint32_t Ath = buf;
        const uint32_t Bth = buf + HTILE;
#pragma unroll
        for (int ks = 0; ks < 2; ks++) {
            uint32_t ah[4][4], bh[4][2];
#pragma unroll
            for (int mt = 0; mt < 4; mt++)
                ldmx4(ah[mt], Ath + a_lane + (uint32_t)(mt * 16 * HSTRIDE + ks * 32));
#pragma unroll
            for (int nt = 0; nt < 4; nt++)
                ldmx2(bh[nt], Bth + b_lane + (uint32_t)(nt * 8 * HSTRIDE + ks * 32));
#pragma unroll
            for (int mt = 0; mt < 4; mt++)
#pragma unroll
                for (int nt = 0; nt < 4; nt++)
                    mma_f16(acc[mt][nt], ah[mt], bh[nt]);
        }
    }

#pragma unroll
    for (int mt = 0; mt < 4; mt++) {
        const int mr = m0 + wm + mt * 16 + (lane >> 2);
#pragma unroll
        for (int nt = 0; nt < 4; nt++) {
            const int nc = n0 + wn + nt * 8 + (lane & 3) * 2;
            float v0 = __fadd_rn(acc[mt][nt][0], bias[nc]);
            float v1 = __fadd_rn(acc[mt][nt][1], bias[nc + 1]);
            float v2 = __fadd_rn(acc[mt][nt][2], bias[nc]);
            float v3 = __fadd_rn(acc[mt][nt][3], bias[nc + 1]);
            if (TANH) { v0 = xla_tanh(v0); v1 = xla_tanh(v1); v2 = xla_tanh(v2); v3 = xla_tanh(v3); }
            if (OUTMODE == 0) {
                float* r0 = &C[(size_t)mr * N + nc];
                float* r1 = &C[(size_t)(mr + 8) * N + nc];
                r0[0] = v0; r0[1] = v1;
                r1[0] = v2; r1[1] = v3;
            } else {
                Chp[(size_t)mr * (N >> 1) + (nc >> 1)]       = cvt_h2(v0, v1);
                Chp[(size_t)(mr + 8) * (N >> 1) + (nc >> 1)] = cvt_h2(v2, v3);
            }
        }
    }
}

// ======================= VQ / misc kernels (bit-exact path, unchanged) =======================
__global__ void ee_kernel(const float* __restrict__ E)
{
    const int row  = blockIdx.x * 8 + (threadIdx.x >> 5);
    const int lane = threadIdx.x & 31;
    const float* e = E + (size_t)row * D2;
    float s = 0.f;
    for (int j = lane; j < D2; j += 32)
        s = __fadd_rn(s, __fmul_rn(e[j], e[j]));
#pragma unroll
    for (int o = 16; o; o >>= 1) s = __fadd_rn(s, __shfl_xor_sync(0xffffffffu, s, o));
    if (lane == 0) g_ee[row] = s;
}

__global__ void zz_kernel()
{
    const int m = blockIdx.x * 256 + threadIdx.x;
    if (m >= B_SZ) return;
    const float* z = g_z + (size_t)m * D2;
    float s = 0.f;
    for (int k = 0; k < D2; k++)
        s = __fadd_rn(s, __fmul_rn(z[k], z[k]));
    g_zz[m] = s;
}

__global__ void init_best()
{
    int i = blockIdx.x * 256 + threadIdx.x;
    if (i < B_SZ) g_best[i] = ~0ull;
}

__device__ __forceinline__ unsigned int orderable_f32(float f)
{
    unsigned int u = __float_as_uint(f);
    return (u & 0x80000000u) ? ~u : (u | 0x80000000u);
}

__global__ __launch_bounds__(256, 2)
void vq_score(const float* __restrict__ Z, const float* __restrict__ E)
{
    __shared__ float As[2][16][128];
    __shared__ float Bs[2][16][128];
    const int t  = threadIdx.x;
    const int tx = t & 15, ty = t >> 4;
    const int m0 = blockIdx.y * 128, n0 = blockIdx.x * 128;
    const int lr = t >> 1;
    const int lc = (t & 1) * 4;
    const float* Aptr = Z + (size_t)(m0 + lr) * D2 + lc;
    const float* Wptr = E + (size_t)(n0 + lr) * D2 + lc;

    unsigned long long acc[8][4];
#pragma unroll
    for (int i = 0; i < 8; i++)
#pragma unroll
        for (int p = 0; p < 4; p++) acc[i][p] = 0ull;

    {
        float4 a0 = *(const float4*)(Aptr);
        float4 a1 = *(const float4*)(Aptr + 8);
        float4 w0 = *(const float4*)(Wptr);
        float4 w1 = *(const float4*)(Wptr + 8);
        sts_tile(As[0], Bs[0], lr, lc, a0, a1, w0, w1);
    }
    __syncthreads();

    int cur = 0;
    for (int k0 = 16; k0 < D2; k0 += 16) {
        float4 a0 = *(const float4*)(Aptr + k0);
        float4 a1 = *(const float4*)(Aptr + k0 + 8);
        float4 w0 = *(const float4*)(Wptr + k0);
        float4 w1 = *(const float4*)(Wptr + k0 + 8);
        tile_fma16p(As[cur], Bs[cur], acc, tx, ty);
        sts_tile(As[cur ^ 1], Bs[cur ^ 1], lr, lc, a0, a1, w0, w1);
        __syncthreads();
        cur ^= 1;
    }
    tile_fma16p(As[cur], Bs[cur], acc, tx, ty);

#pragma unroll
    for (int i = 0; i < 8; i++) {
        const int m = m0 + ty * 8 + i;
        const float zzm = g_zz[m];
        unsigned long long best = ~0ull;
#pragma unroll
        for (int p = 0; p < 4; p++) {
            float2 pr = unpack2(acc[i][p]);
#pragma unroll
            for (int h = 0; h < 2; h++) {
                const int j = 2 * p + h;
                const int n = n0 + col_of(tx, j);
                const float s    = h ? pr.y : pr.x;
                const float zze  = __fadd_rn(zzm, g_ee[n]);
                const float twos = __fmul_rn(2.f, s);
                const float d    = __fadd_rn(zze, -twos);
                unsigned long long key =
                    ((unsigned long long)orderable_f32(d) << 32) | (unsigned int)n;
                best = (key < best) ? key : best;
            }
        }
#pragma unroll
        for (int o = 8; o; o >>= 1) {
            unsigned long long other = __shfl_xor_sync(0xffffffffu, best, o);
            best = (other < best) ? other : best;
        }
        if (tx == 0) atomicMin(&g_best[m], best);
    }
}

// gather q = E[idx]: emit q_st fp32 output + packed fp16 q + loss partials
__global__ void gather_loss(const float* __restrict__ E, float* __restrict__ out_q)
{
    const int m   = blockIdx.x;
    const int idx = (int)(unsigned int)(g_best[m] & 0xFFFFFFFFull);
    const float* e = E + (size_t)idx * D2;
    const float* z = g_z + (size_t)m * D2;
    const int j = threadIdx.x * 2;
    float q0 = e[j], q1 = e[j + 1];
    float d0 = q0 - z[j], d1 = q1 - z[j + 1];
    float s = fmaf(d1, d1, d0 * d0);
    g_qh[((size_t)m * D2 + j) >> 1] = cvt_h2(q0, q1);
    if (out_q) { out_q[(size_t)m * D2 + j] = q0; out_q[(size_t)m * D2 + j + 1] = q1; }

    __shared__ float red[256];
    red[threadIdx.x] = s;
    __syncthreads();
    for (int o = 128; o; o >>= 1) {
        if (threadIdx.x < o) red[threadIdx.x] += red[threadIdx.x + o];
        __syncthreads();
    }
    if (threadIdx.x == 0) g_rowsum[m] = red[0];
}

__global__ void reduce_loss(float* __restrict__ out_loss)
{
    __shared__ float red[1024];
    float s = 0.f;
    for (int i = threadIdx.x; i < B_SZ; i += 1024) s += g_rowsum[i];
    red[threadIdx.x] = s;
    __syncthreads();
    for (int o = 512; o; o >>= 1) {
        if (threadIdx.x < o) red[threadIdx.x] += red[threadIdx.x + o];
        __syncthreads();
    }
    if (threadIdx.x == 0)
        out_loss[0] = red[0] * (1.25f / (float)((size_t)B_SZ * D2));
}

// ----------------------------------------------------------------
extern "C" void kernel_launch(void* const* d_in, const int* in_sizes, int n_in,
                              void* d_out, int out_size)
{
    const float* X  = (const float*)d_in[0];
    const float* W1 = (const float*)d_in[1];
    const float* b1 = (const float*)d_in[2];
    const float* W2 = (const float*)d_in[3];
    const float* b2 = (const float*)d_in[4];
    const float* W3 = (const float*)d_in[5];
    const float* b3 = (const float*)d_in[6];
    const float* E  = (const float*)d_in[7];
    const float* W4 = (const float*)d_in[8];
    const float* b4 = (const float*)d_in[9];
    const float* W5 = (const float*)d_in[10];
    const float* b5 = (const float*)d_in[11];
    const float* W6 = (const float*)d_in[12];
    const float* b6 = (const float*)d_in[13];

    float *h1, *h2, *z;
    cudaGetSymbolAddress((void**)&h1, g_h1);
    cudaGetSymbolAddress((void**)&h2, g_h2);
    cudaGetSymbolAddress((void**)&z,  g_z);
    uint32_t *w4h, *w5h, *w6h, *qh, *h2h, *h1h;
    cudaGetSymbolAddress((void**)&w4h, g_w4h);
    cudaGetSymbolAddress((void**)&w5h, g_w5h);
    cudaGetSymbolAddress((void**)&w6h, g_w6h);
    cudaGetSymbolAddress((void**)&qh,  g_qh);
    cudaGetSymbolAddress((void**)&h2h, g_h2h);
    cudaGetSymbolAddress((void**)&h1h, g_h1h);

    float* out = (float*)d_out;
    const long long full = 1LL + (long long)B_SZ * G_NUM + (long long)B_SZ * D2;
    float* out_loss = nullptr;
    float* out_x    = out;
    float* out_q    = nullptr;
    if ((long long)out_size == full) {
        out_loss = out;
        out_x    = out + 1;
        out_q    = out + 1 + (long long)B_SZ * G_NUM;
    }

    cudaFuncSetAttribute((const void*)gemm_bias_act<true>,
                         cudaFuncAttributeMaxDynamicSharedMemorySize, ENC_SMEM);
    cudaFuncSetAttribute((const void*)gemm_h16<2, true>,
                         cudaFuncAttributeMaxDynamicSharedMemorySize, HSMEM);
    cudaFuncSetAttribute((const void*)gemm_h16<0, false>,
                         cudaFuncAttributeMaxDynamicSharedMemorySize, HSMEM);

    const dim3 blk(256);

    // weight prep (independent of encoder)
    quant_h16<<<(D1 * D2 / 4 + 255) / 256, 256>>>(W4, w4h, D1 * D2 / 4);
    quant_h16<<<(D0 * D1 / 4 + 255) / 256, 256>>>(W5, w5h, D0 * D1 / 4);
    quant_h16<<<(G_NUM / 4 * D0 + 255) / 256, 256>>>(W6, w6h, G_NUM / 4 * D0);

    ee_kernel<<<KEMB / 8, 256>>>(E);
    init_best<<<B_SZ / 256, 256>>>();

    // encoder (bit-exact fp32 chains; Kt=32 staged double-buffer)
    gemm_bias_act<true><<<dim3(D0 / 128, B_SZ / 128), blk, ENC_SMEM>>>(X,  W1, b1, h1, B_SZ, D0, G_NUM);
    gemm_bias_act<true><<<dim3(D1 / 128, B_SZ / 128), blk, ENC_SMEM>>>(h1, W2, b2, h2, B_SZ, D1, D0);
    gemm_bias_act<true><<<dim3(D2 / 128, B_SZ / 128), blk, ENC_SMEM>>>(h2, W3, b3, z,  B_SZ, D2, D1);

    // VQ (bit-exact replication of reference dist formula)
    zz_kernel<<<B_SZ / 256, 256>>>();
    vq_score<<<dim3(KEMB / 128, B_SZ / 128), blk>>>(z, E);
    gather_loss<<<B_SZ, 256>>>(E, out_q);
    if (out_loss) reduce_loss<<<1, 1024>>>(out_loss);

    // decoder: all fp16 1-term HMMA (q contribution to h2 is negligible vs b4;
    // W5/W6 errors measured/modelled well under 1e-3)
    gemm_h16<2, true ><<<dim3(B_SZ / 128, D1 / 128),    blk, HSMEM>>>(
        qh, w4h, b4, nullptr, h2h, D1, D2);
    gemm_h16<2, true ><<<dim3(B_SZ / 128, D0 / 128),    blk, HSMEM>>>(
        h2h, w5h, b5, nullptr, h1h, D0, D1);
    gemm_h16<0, false><<<dim3(B_SZ / 128, G_NUM / 128), blk, HSMEM>>>(
        h1h, w6h, b6, out_x, nullptr, G_NUM, D0);
}